// round 3
// baseline (speedup 1.0000x reference)
#include <cuda_runtime.h>
#include <math.h>

#define NTOK 200
#define CD   256
#define TD   128
#define NHH  8
#define DKK  32
#define DFFD 1024
#define ITER 4
#define NCT  (NTOK*CD*TD)
#define NC   (NTOK*CD)

#define OFF_EMBS   0
#define OFF_NODES  (1*NCT)
#define OFF_XLN    (2*NCT)
#define OFF_Q      (3*NCT)
#define OFF_K      (4*NCT)
#define OFF_V      (5*NCT)
#define OFF_KE     (6*NCT)
#define OFF_VE     (7*NCT)
#define OFF_S      (8*NCT)
#define OFF_RET    (9*NCT)
#define OFF_O      (10*NCT)
#define OFF_KTR    (11*NCT)
#define OFF_VTR    (12*NCT)
#define OFF_H      (13*NCT)            /* N*DFF*T = 4*NCT */
#define OFF_RELAY  (17*NCT)
#define OFF_KR     (OFF_RELAY+NC)
#define OFF_VR     (OFF_KR+NC)
#define OFF_QTR    (OFF_VR+NC)
#define OFF_KTRR   (OFF_QTR+NC)
#define OFF_VTRR   (OFF_KTRR+NC)
#define OFF_Z      (OFF_VTRR+NC)
#define OFF_RETT   (OFF_Z+NC)
#define OFF_OTR    (OFF_RETT+NC)
#define OFF_HTR    (OFF_OTR+NC)
#define OFF_MEAN   (OFF_HTR+NTOK*DFFD)
#define OFF_INV    (OFF_MEAN+256)
#define BUF_TOTAL  (OFF_INV+256)

__device__ __align__(16) float g_buf[BUF_TOTAL];

// ---------------------------------------------------------------------------
// prep: embs[n,c,t] = data[b,c,v,t] (n=b*25+v), relay[n,c] = mean_t embs
// grid (NTOK, 32), block (32,8)
// ---------------------------------------------------------------------------
__global__ void prep_kernel(const float* __restrict__ data,
                            float* __restrict__ embs, float* __restrict__ relay)
{
    int n = blockIdx.x;
    int b = n / 25, v = n % 25;
    int c = blockIdx.y * 8 + threadIdx.y;
    int tx = threadIdx.x;
    const float* src = data + (((size_t)b * CD + c) * 25 + v) * TD;
    float* dst = embs + ((size_t)n * CD + c) * TD;
    float s = 0.f;
#pragma unroll
    for (int j = 0; j < 4; j++) {
        int t = tx + 32 * j;
        float x = src[t];
        dst[t] = x;
        s += x;
    }
#pragma unroll
    for (int o = 16; o > 0; o >>= 1) s += __shfl_xor_sync(0xffffffffu, s, o);
    if (tx == 0) relay[n * CD + c] = s * (1.0f / 128.0f);
}

// ---------------------------------------------------------------------------
// LayerNorm over channel dim. grid (NTOK, 4), block (32,8)
// ---------------------------------------------------------------------------
__global__ void ln_kernel(const float* __restrict__ X, const float* __restrict__ g,
                          const float* __restrict__ b, float* __restrict__ Y)
{
    int n = blockIdx.x;
    int t = blockIdx.y * 32 + threadIdx.x;
    int tx = threadIdx.x, ty = threadIdx.y;
    float x[32];
    float s1 = 0.f, s2 = 0.f;
#pragma unroll
    for (int j = 0; j < 32; j++) {
        int c = ty + j * 8;
        x[j] = X[((size_t)n * CD + c) * TD + t];
        s1 += x[j];
        s2 += x[j] * x[j];
    }
    __shared__ float sm1[8][32], sm2[8][32], smean[32], sinv[32];
    sm1[ty][tx] = s1; sm2[ty][tx] = s2;
    __syncthreads();
    if (ty == 0) {
        float a = 0.f, bb = 0.f;
#pragma unroll
        for (int qy = 0; qy < 8; qy++) { a += sm1[qy][tx]; bb += sm2[qy][tx]; }
        float m = a * (1.0f / 256.0f);
        float var = bb * (1.0f / 256.0f) - m * m;
        smean[tx] = m;
        sinv[tx] = rsqrtf(var + 1e-6f);
    }
    __syncthreads();
    float m = smean[tx], inv = sinv[tx];
#pragma unroll
    for (int j = 0; j < 32; j++) {
        int c = ty + j * 8;
        Y[((size_t)n * CD + c) * TD + t] = (x[j] - m) * inv * g[c] + b[c];
    }
}

// ---------------------------------------------------------------------------
// Main GEMM: Y[n,o,t] = sum_c W[o,c]*X[n,c,t] + bias[o]  (T fixed = 128)
// EPI: 0 = bias only, 1 = relu, 2 = +Res
// grid (O/64, NTOK), block 256
// ---------------------------------------------------------------------------
template <int EPI>
__global__ __launch_bounds__(256)
void gemm_nct(const float* __restrict__ W, const float* __restrict__ bias,
              const float* __restrict__ X, float* __restrict__ Y,
              const float* __restrict__ Res, int O, int Cin)
{
    int n = blockIdx.y;
    int o0 = blockIdx.x * 64;
    const float* Xn = X + (size_t)n * Cin * TD;
    int tid = threadIdx.x;
    int tx = tid & 15, ty = tid >> 4;

    __shared__ float Ws[16][64];
    __shared__ __align__(16) float Xs[16][128];

    float acc[4][8];
#pragma unroll
    for (int i = 0; i < 4; i++)
#pragma unroll
        for (int j = 0; j < 8; j++) acc[i][j] = 0.f;

    for (int k0 = 0; k0 < Cin; k0 += 16) {
        // W tile 64x16 (transposed into smem)
        {
            int o = tid >> 2, kq = tid & 3;
            float4 w4 = *(const float4*)(W + (size_t)(o0 + o) * Cin + k0 + kq * 4);
            Ws[kq * 4 + 0][o] = w4.x;
            Ws[kq * 4 + 1][o] = w4.y;
            Ws[kq * 4 + 2][o] = w4.z;
            Ws[kq * 4 + 3][o] = w4.w;
        }
        // X tile 16x128
#pragma unroll
        for (int r = 0; r < 2; r++) {
            int idx = tid + r * 256;
            int kk = idx >> 5, c4 = idx & 31;
            float4 x4 = *(const float4*)(Xn + (size_t)(k0 + kk) * TD + c4 * 4);
            *(float4*)(&Xs[kk][c4 * 4]) = x4;
        }
        __syncthreads();
#pragma unroll
        for (int kk = 0; kk < 16; kk++) {
            float a[4], bv[8];
#pragma unroll
            for (int i = 0; i < 4; i++) a[i] = Ws[kk][ty * 4 + i];
#pragma unroll
            for (int j = 0; j < 8; j++) bv[j] = Xs[kk][tx + 16 * j];
#pragma unroll
            for (int i = 0; i < 4; i++)
#pragma unroll
                for (int j = 0; j < 8; j++) acc[i][j] += a[i] * bv[j];
        }
        __syncthreads();
    }

#pragma unroll
    for (int i = 0; i < 4; i++) {
        int o = o0 + ty * 4 + i;
        float bs = bias[o];
        float* yrow = Y + ((size_t)n * O + o) * TD;
        const float* rrow = (EPI == 2) ? (Res + ((size_t)n * O + o) * TD) : nullptr;
#pragma unroll
        for (int j = 0; j < 8; j++) {
            int t = tx + 16 * j;
            float val = acc[i][j] + bs;
            if (EPI == 1) val = fmaxf(val, 0.f);
            if (EPI == 2) val += rrow[t];
            yrow[t] = val;
        }
    }
}

// ---------------------------------------------------------------------------
// Small GEMM over [N, Cin] tokens: Y[n,o] = sum_c W[o,c]*X[n,c] + bias[o]
// grid (O/64, ceil(N/32)), block 256
// ---------------------------------------------------------------------------
template <int EPI>
__global__ __launch_bounds__(256)
void gemm_nc(const float* __restrict__ W, const float* __restrict__ bias,
             const float* __restrict__ X, float* __restrict__ Y,
             const float* __restrict__ Res, int O, int Cin)
{
    int o0 = blockIdx.x * 64;
    int n0 = blockIdx.y * 32;
    int tid = threadIdx.x;
    int tx = tid & 31, ty = tid >> 5;

    __shared__ float Ws[32][64];
    __shared__ float Xs[32][33];

    float acc[8];
#pragma unroll
    for (int i = 0; i < 8; i++) acc[i] = 0.f;

    for (int k0 = 0; k0 < Cin; k0 += 32) {
#pragma unroll
        for (int r = 0; r < 2; r++) {
            int idx = tid + 256 * r;
            int o = idx >> 3, kq = idx & 7;
            float4 w4 = *(const float4*)(W + (size_t)(o0 + o) * Cin + k0 + kq * 4);
            Ws[kq * 4 + 0][o] = w4.x;
            Ws[kq * 4 + 1][o] = w4.y;
            Ws[kq * 4 + 2][o] = w4.z;
            Ws[kq * 4 + 3][o] = w4.w;
        }
        {
            int nn = tid >> 3, kq = tid & 7;
            int n = n0 + nn;
            float4 x4 = make_float4(0.f, 0.f, 0.f, 0.f);
            if (n < NTOK) x4 = *(const float4*)(X + (size_t)n * Cin + k0 + kq * 4);
            Xs[kq * 4 + 0][nn] = x4.x;
            Xs[kq * 4 + 1][nn] = x4.y;
            Xs[kq * 4 + 2][nn] = x4.z;
            Xs[kq * 4 + 3][nn] = x4.w;
        }
        __syncthreads();
#pragma unroll
        for (int kk = 0; kk < 32; kk++) {
            float bv = Xs[kk][tx];
#pragma unroll
            for (int i = 0; i < 8; i++) acc[i] += Ws[kk][ty * 8 + i] * bv;
        }
        __syncthreads();
    }

    int n = n0 + tx;
    if (n < NTOK) {
#pragma unroll
        for (int i = 0; i < 8; i++) {
            int o = o0 + ty * 8 + i;
            float val = acc[i] + bias[o];
            if (EPI == 1) val = fmaxf(val, 0.f);
            if (EPI == 2) val += Res[(size_t)n * O + o];
            Y[(size_t)n * O + o] = val;
        }
    }
}

// ---------------------------------------------------------------------------
// tju attention (window-3 + emb token + relay token), fused residual add.
// grid NTOK*NHH, block 128 (one thread per t)
// ---------------------------------------------------------------------------
__global__ void attn_tju(const float* __restrict__ q, const float* __restrict__ k,
                         const float* __restrict__ v, const float* __restrict__ ke,
                         const float* __restrict__ ve, const float* __restrict__ kr,
                         const float* __restrict__ vr, const float* __restrict__ xln,
                         float* __restrict__ sout)
{
    int nh = blockIdx.x;
    int n = nh >> 3, h = nh & 7;
    int t = threadIdx.x;
    int rbase = n * CD + h * DKK;
    size_t base = (size_t)rbase * TD;

    float l0 = 0.f, l1 = 0.f, l2 = 0.f, l3 = 0.f, l4 = 0.f;
#pragma unroll 8
    for (int d = 0; d < DKK; d++) {
        size_t off = base + (size_t)d * TD + t;
        float qd = q[off];
        float kc = k[off];
        float km = (t > 0) ? k[off - 1] : 0.f;
        float kp = (t < TD - 1) ? k[off + 1] : 0.f;
        l0 += qd * km;
        l1 += qd * kc;
        l2 += qd * kp;
        l3 += qd * ke[off];
        l4 += qd * kr[rbase + d];
    }
    const float sc = 0.17677669529663687f; // 1/sqrt(32)
    l0 *= sc; l1 *= sc; l2 *= sc; l3 *= sc; l4 *= sc;
    float m = fmaxf(fmaxf(fmaxf(l0, l1), fmaxf(l2, l3)), l4);
    float e0 = expf(l0 - m), e1 = expf(l1 - m), e2 = expf(l2 - m);
    float e3 = expf(l3 - m), e4 = expf(l4 - m);
    float rs = 1.f / (e0 + e1 + e2 + e3 + e4);
    float a0 = e0 * rs, a1 = e1 * rs, a2 = e2 * rs, a3 = e3 * rs, a4 = e4 * rs;

#pragma unroll 8
    for (int d = 0; d < DKK; d++) {
        size_t off = base + (size_t)d * TD + t;
        float vc = v[off];
        float vm = (t > 0) ? v[off - 1] : 0.f;
        float vp = (t < TD - 1) ? v[off + 1] : 0.f;
        float att = a0 * vm + a1 * vc + a2 * vp + a3 * ve[off] + a4 * vr[rbase + d];
        sout[off] = xln[off] + att;
    }
}

// ---------------------------------------------------------------------------
// tru attention (relay over 129 tokens). block 256 = 8 warps, grid 200.
// ---------------------------------------------------------------------------
__global__ void attn_tru(const float* __restrict__ qtr, const float* __restrict__ ktr,
                         const float* __restrict__ vtr, const float* __restrict__ ktrr,
                         const float* __restrict__ vtrr, const float* __restrict__ relay,
                         float* __restrict__ z)
{
    __shared__ float sq[8][DKK];
    __shared__ float slog[8][132];
    int wid = threadIdx.x >> 5, lane = threadIdx.x & 31;
    int nh = blockIdx.x * 8 + wid;
    int n = nh >> 3, h = nh & 7;
    int rbase = n * CD + h * DKK;
    size_t base = (size_t)rbase * TD;
    const float sc = 0.17677669529663687f;

    sq[wid][lane] = qtr[rbase + lane];
    __syncwarp();

    float lg[5];
#pragma unroll
    for (int j = 0; j < 5; j++) {
        int l = lane + 32 * j;
        float acc = -1e30f;
        if (l < 129) {
            acc = 0.f;
            if (l == 0) {
#pragma unroll 8
                for (int d = 0; d < DKK; d++) acc += sq[wid][d] * ktrr[rbase + d];
            } else {
                int t = l - 1;
#pragma unroll 8
                for (int d = 0; d < DKK; d++) acc += sq[wid][d] * ktr[base + (size_t)d * TD + t];
            }
            acc *= sc;
        }
        lg[j] = acc;
    }
    float m = -1e30f;
#pragma unroll
    for (int j = 0; j < 5; j++) m = fmaxf(m, lg[j]);
#pragma unroll
    for (int o = 16; o > 0; o >>= 1) m = fmaxf(m, __shfl_xor_sync(0xffffffffu, m, o));
    float es = 0.f;
#pragma unroll
    for (int j = 0; j < 5; j++) {
        int l = lane + 32 * j;
        if (l < 129) {
            float e = expf(lg[j] - m);
            slog[wid][l] = e;
            es += e;
        }
    }
#pragma unroll
    for (int o = 16; o > 0; o >>= 1) es += __shfl_xor_sync(0xffffffffu, es, o);
    __syncwarp();
    float rinv = 1.f / es;

    int d = lane;
    float att = slog[wid][0] * vtrr[rbase + d];
    const float* vp = vtr + base + (size_t)d * TD;
#pragma unroll 16
    for (int t = 0; t < TD; t++) att += slog[wid][1 + t] * vp[t];
    att *= rinv;
    z[rbase + d] = relay[rbase + d] + att;
}

// ---------------------------------------------------------------------------
// BN stats over (n,t) per channel. grid 256, block 256.
// ---------------------------------------------------------------------------
__global__ void bn_stats_nct(const float* __restrict__ X, float* __restrict__ mean,
                             float* __restrict__ inv, float eps)
{
    int c = blockIdx.x, tid = threadIdx.x;
    float s1 = 0.f, s2 = 0.f;
    for (int i = tid; i < NTOK * TD; i += 256) {
        int n = i >> 7, t = i & 127;
        float x = X[((size_t)n * CD + c) * TD + t];
        s1 += x;
        s2 += x * x;
    }
    __shared__ double d1[256], d2[256];
    d1[tid] = s1; d2[tid] = s2;
    __syncthreads();
    for (int s = 128; s > 0; s >>= 1) {
        if (tid < s) { d1[tid] += d1[tid + s]; d2[tid] += d2[tid + s]; }
        __syncthreads();
    }
    if (tid == 0) {
        double mm = d1[0] / (NTOK * TD);
        double var = d2[0] / (NTOK * TD) - mm * mm;
        mean[c] = (float)mm;
        inv[c] = rsqrtf((float)var + eps);
    }
}

// BN stats over n per channel ([N,C] input). grid 256, block 256.
__global__ void bn_stats_nc(const float* __restrict__ X, float* __restrict__ mean,
                            float* __restrict__ inv, float eps)
{
    int c = blockIdx.x, tid = threadIdx.x;
    float s1 = 0.f, s2 = 0.f;
    for (int n = tid; n < NTOK; n += 256) {
        float x = X[(size_t)n * CD + c];
        s1 += x;
        s2 += x * x;
    }
    __shared__ double d1[256], d2[256];
    d1[tid] = s1; d2[tid] = s2;
    __syncthreads();
    for (int s = 128; s > 0; s >>= 1) {
        if (tid < s) { d1[tid] += d1[tid + s]; d2[tid] += d2[tid + s]; }
        __syncthreads();
    }
    if (tid == 0) {
        double mm = d1[0] / NTOK;
        double var = d2[0] / NTOK - mm * mm;
        mean[c] = (float)mm;
        inv[c] = rsqrtf((float)var + eps);
    }
}

// apply BN affine (+ optional leaky relu) on [N,C,T]
__global__ void affine_nct(const float* __restrict__ X, const float* __restrict__ mean,
                           const float* __restrict__ inv, const float* __restrict__ g,
                           const float* __restrict__ b, float* __restrict__ Y, int leaky)
{
    int idx = blockIdx.x * 256 + threadIdx.x;
    if (idx >= NCT) return;
    int c = (idx >> 7) & 255;
    float vv = (X[idx] - mean[c]) * inv[c] * g[c] + b[c];
    if (leaky && vv < 0.f) vv *= 0.01f;
    Y[idx] = vv;
}

// apply BN affine (+ optional leaky relu) on [N,C]
__global__ void affine_nc(const float* __restrict__ X, const float* __restrict__ mean,
                          const float* __restrict__ inv, const float* __restrict__ g,
                          const float* __restrict__ b, float* __restrict__ Y, int leaky)
{
    int idx = blockIdx.x * 256 + threadIdx.x;
    if (idx >= NC) return;
    int c = idx & 255;
    float vv = (X[idx] - mean[c]) * inv[c] * g[c] + b[c];
    if (leaky && vv < 0.f) vv *= 0.01f;
    Y[idx] = vv;
}

// ---------------------------------------------------------------------------
extern "C" void kernel_launch(void* const* d_in, const int* in_sizes, int n_in,
                              void* d_out, int out_size)
{
    (void)in_sizes; (void)n_in; (void)out_size;
    const float* data    = (const float*)d_in[0];
    const float* ln_g    = (const float*)d_in[1];
    const float* ln_b    = (const float*)d_in[2];
    const float* tj_wq   = (const float*)d_in[3];
    const float* tj_bq   = (const float*)d_in[4];
    const float* tj_wk   = (const float*)d_in[5];
    const float* tj_bk   = (const float*)d_in[6];
    const float* tj_wv   = (const float*)d_in[7];
    const float* tj_bv   = (const float*)d_in[8];
    const float* tj_bng  = (const float*)d_in[9];
    const float* tj_bnb  = (const float*)d_in[10];
    const float* tj_w1   = (const float*)d_in[11];
    const float* tj_b1   = (const float*)d_in[12];
    const float* tj_w2   = (const float*)d_in[13];
    const float* tj_b2   = (const float*)d_in[14];
    const float* tj_fg   = (const float*)d_in[15];
    const float* tj_fb   = (const float*)d_in[16];
    const float* tr_wq   = (const float*)d_in[17];
    const float* tr_bq   = (const float*)d_in[18];
    const float* tr_wk   = (const float*)d_in[19];
    const float* tr_bk   = (const float*)d_in[20];
    const float* tr_wv   = (const float*)d_in[21];
    const float* tr_bv   = (const float*)d_in[22];
    const float* tr_bng  = (const float*)d_in[23];
    const float* tr_bnb  = (const float*)d_in[24];
    const float* tr_w1   = (const float*)d_in[25];
    const float* tr_b1   = (const float*)d_in[26];
    const float* tr_w2   = (const float*)d_in[27];
    const float* tr_b2   = (const float*)d_in[28];
    const float* tr_fg   = (const float*)d_in[29];
    const float* tr_fb   = (const float*)d_in[30];

    float* buf = nullptr;
    cudaGetSymbolAddress((void**)&buf, g_buf);

    float* embs  = buf + OFF_EMBS;
    float* nodes = buf + OFF_NODES;
    float* xln   = buf + OFF_XLN;
    float* qb    = buf + OFF_Q;
    float* kb    = buf + OFF_K;
    float* vb    = buf + OFF_V;
    float* keb   = buf + OFF_KE;
    float* veb   = buf + OFF_VE;
    float* sb    = buf + OFF_S;
    float* retb  = buf + OFF_RET;
    float* ob    = buf + OFF_O;
    float* ktrb  = buf + OFF_KTR;
    float* vtrb  = buf + OFF_VTR;
    float* hb    = buf + OFF_H;
    float* relay = buf + OFF_RELAY;
    float* krb   = buf + OFF_KR;
    float* vrb   = buf + OFF_VR;
    float* qtrb  = buf + OFF_QTR;
    float* ktrr  = buf + OFF_KTRR;
    float* vtrr  = buf + OFF_VTRR;
    float* zb    = buf + OFF_Z;
    float* rettb = buf + OFF_RETT;
    float* otrb  = buf + OFF_OTR;
    float* htrb  = buf + OFF_HTR;
    float* meanb = buf + OFF_MEAN;
    float* invb  = buf + OFF_INV;

    prep_kernel<<<dim3(NTOK, 32), dim3(32, 8)>>>(data, embs, relay);

    const dim3 g_o4(4, NTOK), g_o16(16, NTOK);
    const dim3 gnc4(4, 7), gnc16(16, 7);

    for (int i = 0; i < ITER; i++) {
        const float* nodes_in = (i == 0) ? embs : nodes;
        // LayerNorm over channels
        ln_kernel<<<dim3(NTOK, 4), dim3(32, 8)>>>(nodes_in, ln_g + i * CD, ln_b + i * CD, xln);

        const float* wq = tj_wq + (size_t)i * CD * CD;
        const float* wk = tj_wk + (size_t)i * CD * CD;
        const float* wv = tj_wv + (size_t)i * CD * CD;
        const float* bq = tj_bq + i * CD;
        const float* bk = tj_bk + i * CD;
        const float* bv = tj_bv + i * CD;

        gemm_nct<0><<<g_o4, 256>>>(wq, bq, xln, qb, nullptr, CD, CD);
        gemm_nct<0><<<g_o4, 256>>>(wk, bk, xln, kb, nullptr, CD, CD);
        gemm_nct<0><<<g_o4, 256>>>(wv, bv, xln, vb, nullptr, CD, CD);
        gemm_nct<0><<<g_o4, 256>>>(wk, bk, embs, keb, nullptr, CD, CD);
        gemm_nct<0><<<g_o4, 256>>>(wv, bv, embs, veb, nullptr, CD, CD);
        gemm_nc<0><<<gnc4, 256>>>(wk, bk, relay, krb, nullptr, CD, CD);
        gemm_nc<0><<<gnc4, 256>>>(wv, bv, relay, vrb, nullptr, CD, CD);

        attn_tju<<<NTOK * NHH, 128>>>(qb, kb, vb, keb, veb, krb, vrb, xln, sb);

        bn_stats_nct<<<256, 256>>>(sb, meanb, invb, 1e-5f);
        affine_nct<<<NCT / 256, 256>>>(sb, meanb, invb, tj_bng + i * CD, tj_bnb + i * CD, retb, 0);

        gemm_nct<1><<<g_o16, 256>>>(tj_w1 + (size_t)i * DFFD * CD, tj_b1 + i * DFFD,
                                    retb, hb, nullptr, DFFD, CD);
        gemm_nct<2><<<g_o4, 256>>>(tj_w2 + (size_t)i * CD * DFFD, tj_b2 + i * CD,
                                   hb, ob, retb, CD, DFFD);

        bn_stats_nct<<<256, 256>>>(ob, meanb, invb, 1e-5f);
        float* nodes_out = (i == ITER - 1) ? (float*)d_out : nodes;
        affine_nct<<<NCT / 256, 256>>>(ob, meanb, invb, tj_fg + i * CD, tj_fb + i * CD,
                                       nodes_out, 1);

        if (i < ITER - 1) {
            const float* rwq = tr_wq + (size_t)i * CD * CD;
            const float* rwk = tr_wk + (size_t)i * CD * CD;
            const float* rwv = tr_wv + (size_t)i * CD * CD;
            const float* rbq = tr_bq + i * CD;
            const float* rbk = tr_bk + i * CD;
            const float* rbv = tr_bv + i * CD;

            gemm_nc<0><<<gnc4, 256>>>(rwq, rbq, relay, qtrb, nullptr, CD, CD);
            gemm_nct<0><<<g_o4, 256>>>(rwk, rbk, nodes, ktrb, nullptr, CD, CD);
            gemm_nct<0><<<g_o4, 256>>>(rwv, rbv, nodes, vtrb, nullptr, CD, CD);
            gemm_nc<0><<<gnc4, 256>>>(rwk, rbk, relay, ktrr, nullptr, CD, CD);
            gemm_nc<0><<<gnc4, 256>>>(rwv, rbv, relay, vtrr, nullptr, CD, CD);

            attn_tru<<<NTOK, 256>>>(qtrb, ktrb, vtrb, ktrr, vtrr, relay, zb);

            bn_stats_nc<<<256, 256>>>(zb, meanb, invb, 1e-5f);
            affine_nc<<<NC / 256, 256>>>(zb, meanb, invb, tr_bng + i * CD, tr_bnb + i * CD,
                                         rettb, 0);

            gemm_nc<1><<<gnc16, 256>>>(tr_w1 + (size_t)i * DFFD * CD, tr_b1 + i * DFFD,
                                       rettb, htrb, nullptr, DFFD, CD);
            gemm_nc<2><<<gnc4, 256>>>(tr_w2 + (size_t)i * CD * DFFD, tr_b2 + i * CD,
                                      htrb, otrb, rettb, CD, DFFD);

            bn_stats_nc<<<256, 256>>>(otrb, meanb, invb, 1e-5f);
            affine_nc<<<NC / 256, 256>>>(otrb, meanb, invb, tr_fg + i * CD, tr_fb + i * CD,
                                         relay, 1);
        }
    }
}

// round 4
// speedup vs baseline: 1.1098x; 1.1098x over previous
#include <cuda_runtime.h>
#include <math.h>
#include <stdint.h>

#define NTOK 200
#define CD   256
#define TD   128
#define NHH  8
#define DKK  32
#define DFFD 1024
#define ITER 4
#define NCT  (NTOK*CD*TD)
#define NC   (NTOK*CD)

#define OFF_EMBS   0
#define OFF_NODES  (1*NCT)
#define OFF_XLN    (2*NCT)
#define OFF_Q      (3*NCT)
#define OFF_K      (4*NCT)
#define OFF_V      (5*NCT)
#define OFF_KE     (6*NCT)
#define OFF_VE     (7*NCT)
#define OFF_S      (8*NCT)
#define OFF_RET    (9*NCT)
#define OFF_O      (10*NCT)
#define OFF_KTR    (11*NCT)
#define OFF_VTR    (12*NCT)
#define OFF_H      (13*NCT)            /* N*DFF*T = 4*NCT */
#define OFF_RELAY  (17*NCT)
#define OFF_KR     (OFF_RELAY+NC)
#define OFF_VR     (OFF_KR+NC)
#define OFF_QTR    (OFF_VR+NC)
#define OFF_KTRR   (OFF_QTR+NC)
#define OFF_VTRR   (OFF_KTRR+NC)
#define OFF_Z      (OFF_VTRR+NC)
#define OFF_RETT   (OFF_Z+NC)
#define OFF_OTR    (OFF_RETT+NC)
#define OFF_HTR    (OFF_OTR+NC)
#define OFF_MEAN   (OFF_HTR+NTOK*DFFD)
#define OFF_INV    (OFF_MEAN+256)
#define BUF_TOTAL  (OFF_INV+256)

__device__ __align__(16) float g_buf[BUF_TOTAL];

__device__ __forceinline__ uint32_t f2tf32(float x) {
    uint32_t r;
    asm("cvt.rna.tf32.f32 %0, %1;" : "=r"(r) : "f"(x));
    return r;
}

#define MMA_TF32(C, A, B)                                                     \
    asm volatile("mma.sync.aligned.m16n8k8.row.col.f32.tf32.tf32.f32 "        \
                 "{%0,%1,%2,%3}, {%4,%5,%6,%7}, {%8,%9}, {%0,%1,%2,%3};\n"    \
                 : "+f"((C)[0]), "+f"((C)[1]), "+f"((C)[2]), "+f"((C)[3])     \
                 : "r"((A)[0]), "r"((A)[1]), "r"((A)[2]), "r"((A)[3]),        \
                   "r"((B)[0]), "r"((B)[1]));

// ---------------------------------------------------------------------------
// prep: embs[n,c,t] = data[b,c,v,t] (n=b*25+v), relay[n,c] = mean_t embs
// ---------------------------------------------------------------------------
__global__ void prep_kernel(const float* __restrict__ data,
                            float* __restrict__ embs, float* __restrict__ relay)
{
    int n = blockIdx.x;
    int b = n / 25, v = n % 25;
    int c = blockIdx.y * 8 + threadIdx.y;
    int tx = threadIdx.x;
    const float* src = data + (((size_t)b * CD + c) * 25 + v) * TD;
    float* dst = embs + ((size_t)n * CD + c) * TD;
    float s = 0.f;
#pragma unroll
    for (int j = 0; j < 4; j++) {
        int t = tx + 32 * j;
        float x = src[t];
        dst[t] = x;
        s += x;
    }
#pragma unroll
    for (int o = 16; o > 0; o >>= 1) s += __shfl_xor_sync(0xffffffffu, s, o);
    if (tx == 0) relay[n * CD + c] = s * (1.0f / 128.0f);
}

// ---------------------------------------------------------------------------
// LayerNorm over channel dim. grid (NTOK, 4), block (32,8)
// ---------------------------------------------------------------------------
__global__ void ln_kernel(const float* __restrict__ X, const float* __restrict__ g,
                          const float* __restrict__ b, float* __restrict__ Y)
{
    int n = blockIdx.x;
    int t = blockIdx.y * 32 + threadIdx.x;
    int tx = threadIdx.x, ty = threadIdx.y;
    float x[32];
    float s1 = 0.f, s2 = 0.f;
#pragma unroll
    for (int j = 0; j < 32; j++) {
        int c = ty + j * 8;
        x[j] = X[((size_t)n * CD + c) * TD + t];
        s1 += x[j];
        s2 += x[j] * x[j];
    }
    __shared__ float sm1[8][32], sm2[8][32], smean[32], sinv[32];
    sm1[ty][tx] = s1; sm2[ty][tx] = s2;
    __syncthreads();
    if (ty == 0) {
        float a = 0.f, bb = 0.f;
#pragma unroll
        for (int qy = 0; qy < 8; qy++) { a += sm1[qy][tx]; bb += sm2[qy][tx]; }
        float m = a * (1.0f / 256.0f);
        float var = bb * (1.0f / 256.0f) - m * m;
        smean[tx] = m;
        sinv[tx] = rsqrtf(var + 1e-6f);
    }
    __syncthreads();
    float m = smean[tx], inv = sinv[tx];
#pragma unroll
    for (int j = 0; j < 32; j++) {
        int c = ty + j * 8;
        Y[((size_t)n * CD + c) * TD + t] = (x[j] - m) * inv * g[c] + b[c];
    }
}

// ---------------------------------------------------------------------------
// TF32 tensor-core GEMM: Y[n,o,t] = sum_c W[o,c]*X[n,c,t] + bias[o]
// T fixed = 128. Block tile: 64 (o) x 128 (t), K-chunk 16.
// 8 warps: warp_o in {0,1}, warp_t in {0..3}; warp tile 32x32.
// EPI: 0 = bias only, 1 = relu, 2 = +Res
// grid (O/64, NTOK), block 256
// ---------------------------------------------------------------------------
template <int EPI>
__global__ __launch_bounds__(256)
void gemm_tf32(const float* __restrict__ W, const float* __restrict__ bias,
               const float* __restrict__ X, float* __restrict__ Y,
               const float* __restrict__ Res, int O, int Cin)
{
    int n = blockIdx.y;
    int o0 = blockIdx.x * 64;
    const float* Xn = X + (size_t)n * Cin * TD;
    int tid = threadIdx.x;
    int lane = tid & 31, wid = tid >> 5;
    int warp_o = wid >> 2, warp_t = wid & 3;
    int g = lane >> 2, q = lane & 3;

    // row stride 20: conflict-free fragment loads (banks 20g+q all distinct)
    __shared__ uint32_t Ws[64 * 20];   // [o][k] k=0..15
    __shared__ uint32_t Xs[128 * 20];  // [t][k] k=0..15

    float acc[2][4][4];
#pragma unroll
    for (int m = 0; m < 2; m++)
#pragma unroll
        for (int nf = 0; nf < 4; nf++)
#pragma unroll
            for (int j = 0; j < 4; j++) acc[m][nf][j] = 0.f;

    for (int k0 = 0; k0 < Cin; k0 += 16) {
        // W tile 64x16 -> Ws[o][k] (tf32-rounded)
        {
            int o = tid >> 2, kq = (tid & 3) * 4;
            float4 w4 = *(const float4*)(W + (size_t)(o0 + o) * Cin + k0 + kq);
            uint32_t* d = &Ws[o * 20 + kq];
            d[0] = f2tf32(w4.x); d[1] = f2tf32(w4.y);
            d[2] = f2tf32(w4.z); d[3] = f2tf32(w4.w);
        }
        // X tile 16x128 -> transposed Xs[t][k] (tf32-rounded)
        {
            int k = tid >> 4;
            int t0 = (tid & 15) * 8;
            const float* src = Xn + (size_t)(k0 + k) * TD + t0;
            float4 x0 = *(const float4*)(src);
            float4 x1 = *(const float4*)(src + 4);
            Xs[(t0 + 0) * 20 + k] = f2tf32(x0.x);
            Xs[(t0 + 1) * 20 + k] = f2tf32(x0.y);
            Xs[(t0 + 2) * 20 + k] = f2tf32(x0.z);
            Xs[(t0 + 3) * 20 + k] = f2tf32(x0.w);
            Xs[(t0 + 4) * 20 + k] = f2tf32(x1.x);
            Xs[(t0 + 5) * 20 + k] = f2tf32(x1.y);
            Xs[(t0 + 6) * 20 + k] = f2tf32(x1.z);
            Xs[(t0 + 7) * 20 + k] = f2tf32(x1.w);
        }
        __syncthreads();

#pragma unroll
        for (int ks = 0; ks < 16; ks += 8) {
            uint32_t a[2][4], b[4][2];
#pragma unroll
            for (int m = 0; m < 2; m++) {
                int row = (warp_o * 32 + m * 16 + g) * 20 + ks + q;
                a[m][0] = Ws[row];
                a[m][1] = Ws[row + 8 * 20];
                a[m][2] = Ws[row + 4];
                a[m][3] = Ws[row + 8 * 20 + 4];
            }
#pragma unroll
            for (int nf = 0; nf < 4; nf++) {
                int tt = (warp_t * 32 + nf * 8 + g) * 20 + ks + q;
                b[nf][0] = Xs[tt];
                b[nf][1] = Xs[tt + 4];
            }
#pragma unroll
            for (int m = 0; m < 2; m++)
#pragma unroll
                for (int nf = 0; nf < 4; nf++)
                    MMA_TF32(acc[m][nf], a[m], b[nf]);
        }
        __syncthreads();
    }

    // epilogue: c0,c1 at (row g, cols 2q,2q+1); c2,c3 at (row g+8)
#pragma unroll
    for (int m = 0; m < 2; m++) {
        int obase = o0 + warp_o * 32 + m * 16 + g;
#pragma unroll
        for (int r = 0; r < 2; r++) {
            int o = obase + r * 8;
            float bs = bias[o];
            float* yrow = Y + ((size_t)n * O + o) * TD;
            const float* rrow = (EPI == 2) ? (Res + ((size_t)n * O + o) * TD) : nullptr;
#pragma unroll
            for (int nf = 0; nf < 4; nf++) {
                int t = warp_t * 32 + nf * 8 + q * 2;
                float v0 = acc[m][nf][r * 2 + 0] + bs;
                float v1 = acc[m][nf][r * 2 + 1] + bs;
                if (EPI == 1) { v0 = fmaxf(v0, 0.f); v1 = fmaxf(v1, 0.f); }
                if (EPI == 2) {
                    float2 rr = *(const float2*)(rrow + t);
                    v0 += rr.x; v1 += rr.y;
                }
                *(float2*)(yrow + t) = make_float2(v0, v1);
            }
        }
    }
}

// ---------------------------------------------------------------------------
// Small GEMM over [N, Cin] tokens (relay path, fp32): Y[n,o] = W[o,:]*X[n,:]+b
// grid (O/64, ceil(N/32)), block 256
// ---------------------------------------------------------------------------
template <int EPI>
__global__ __launch_bounds__(256)
void gemm_nc(const float* __restrict__ W, const float* __restrict__ bias,
             const float* __restrict__ X, float* __restrict__ Y,
             const float* __restrict__ Res, int O, int Cin)
{
    int o0 = blockIdx.x * 64;
    int n0 = blockIdx.y * 32;
    int tid = threadIdx.x;
    int tx = tid & 31, ty = tid >> 5;

    __shared__ float Ws[32][64];
    __shared__ float Xs[32][33];

    float acc[8];
#pragma unroll
    for (int i = 0; i < 8; i++) acc[i] = 0.f;

    for (int k0 = 0; k0 < Cin; k0 += 32) {
#pragma unroll
        for (int r = 0; r < 2; r++) {
            int idx = tid + 256 * r;
            int o = idx >> 3, kq = idx & 7;
            float4 w4 = *(const float4*)(W + (size_t)(o0 + o) * Cin + k0 + kq * 4);
            Ws[kq * 4 + 0][o] = w4.x;
            Ws[kq * 4 + 1][o] = w4.y;
            Ws[kq * 4 + 2][o] = w4.z;
            Ws[kq * 4 + 3][o] = w4.w;
        }
        {
            int nn = tid >> 3, kq = tid & 7;
            int n = n0 + nn;
            float4 x4 = make_float4(0.f, 0.f, 0.f, 0.f);
            if (n < NTOK) x4 = *(const float4*)(X + (size_t)n * Cin + k0 + kq * 4);
            Xs[kq * 4 + 0][nn] = x4.x;
            Xs[kq * 4 + 1][nn] = x4.y;
            Xs[kq * 4 + 2][nn] = x4.z;
            Xs[kq * 4 + 3][nn] = x4.w;
        }
        __syncthreads();
#pragma unroll
        for (int kk = 0; kk < 32; kk++) {
            float bv = Xs[kk][tx];
#pragma unroll
            for (int i = 0; i < 8; i++) acc[i] += Ws[kk][ty * 8 + i] * bv;
        }
        __syncthreads();
    }

    int n = n0 + tx;
    if (n < NTOK) {
#pragma unroll
        for (int i = 0; i < 8; i++) {
            int o = o0 + ty * 8 + i;
            float val = acc[i] + bias[o];
            if (EPI == 1) val = fmaxf(val, 0.f);
            if (EPI == 2) val += Res[(size_t)n * O + o];
            Y[(size_t)n * O + o] = val;
        }
    }
}

// ---------------------------------------------------------------------------
// tju attention (window-3 + emb token + relay token), fused residual add.
// grid NTOK*NHH, block 128 (one thread per t)
// ---------------------------------------------------------------------------
__global__ void attn_tju(const float* __restrict__ q, const float* __restrict__ k,
                         const float* __restrict__ v, const float* __restrict__ ke,
                         const float* __restrict__ ve, const float* __restrict__ kr,
                         const float* __restrict__ vr, const float* __restrict__ xln,
                         float* __restrict__ sout)
{
    int nh = blockIdx.x;
    int n = nh >> 3, h = nh & 7;
    int t = threadIdx.x;
    int rbase = n * CD + h * DKK;
    size_t base = (size_t)rbase * TD;

    float l0 = 0.f, l1 = 0.f, l2 = 0.f, l3 = 0.f, l4 = 0.f;
#pragma unroll 8
    for (int d = 0; d < DKK; d++) {
        size_t off = base + (size_t)d * TD + t;
        float qd = q[off];
        float kc = k[off];
        float km = (t > 0) ? k[off - 1] : 0.f;
        float kp = (t < TD - 1) ? k[off + 1] : 0.f;
        l0 += qd * km;
        l1 += qd * kc;
        l2 += qd * kp;
        l3 += qd * ke[off];
        l4 += qd * kr[rbase + d];
    }
    const float sc = 0.17677669529663687f; // 1/sqrt(32)
    l0 *= sc; l1 *= sc; l2 *= sc; l3 *= sc; l4 *= sc;
    float m = fmaxf(fmaxf(fmaxf(l0, l1), fmaxf(l2, l3)), l4);
    float e0 = expf(l0 - m), e1 = expf(l1 - m), e2 = expf(l2 - m);
    float e3 = expf(l3 - m), e4 = expf(l4 - m);
    float rs = 1.f / (e0 + e1 + e2 + e3 + e4);
    float a0 = e0 * rs, a1 = e1 * rs, a2 = e2 * rs, a3 = e3 * rs, a4 = e4 * rs;

#pragma unroll 8
    for (int d = 0; d < DKK; d++) {
        size_t off = base + (size_t)d * TD + t;
        float vc = v[off];
        float vm = (t > 0) ? v[off - 1] : 0.f;
        float vp = (t < TD - 1) ? v[off + 1] : 0.f;
        float att = a0 * vm + a1 * vc + a2 * vp + a3 * ve[off] + a4 * vr[rbase + d];
        sout[off] = xln[off] + att;
    }
}

// ---------------------------------------------------------------------------
// tru attention (relay over 129 tokens). block 256 = 8 warps, grid 200.
// ---------------------------------------------------------------------------
__global__ void attn_tru(const float* __restrict__ qtr, const float* __restrict__ ktr,
                         const float* __restrict__ vtr, const float* __restrict__ ktrr,
                         const float* __restrict__ vtrr, const float* __restrict__ relay,
                         float* __restrict__ z)
{
    __shared__ float sq[8][DKK];
    __shared__ float slog[8][132];
    int wid = threadIdx.x >> 5, lane = threadIdx.x & 31;
    int nh = blockIdx.x * 8 + wid;
    int n = nh >> 3, h = nh & 7;
    int rbase = n * CD + h * DKK;
    size_t base = (size_t)rbase * TD;
    const float sc = 0.17677669529663687f;

    sq[wid][lane] = qtr[rbase + lane];
    __syncwarp();

    float lg[5];
#pragma unroll
    for (int j = 0; j < 5; j++) {
        int l = lane + 32 * j;
        float acc = -1e30f;
        if (l < 129) {
            acc = 0.f;
            if (l == 0) {
#pragma unroll 8
                for (int d = 0; d < DKK; d++) acc += sq[wid][d] * ktrr[rbase + d];
            } else {
                int t = l - 1;
#pragma unroll 8
                for (int d = 0; d < DKK; d++) acc += sq[wid][d] * ktr[base + (size_t)d * TD + t];
            }
            acc *= sc;
        }
        lg[j] = acc;
    }
    float m = -1e30f;
#pragma unroll
    for (int j = 0; j < 5; j++) m = fmaxf(m, lg[j]);
#pragma unroll
    for (int o = 16; o > 0; o >>= 1) m = fmaxf(m, __shfl_xor_sync(0xffffffffu, m, o));
    float es = 0.f;
#pragma unroll
    for (int j = 0; j < 5; j++) {
        int l = lane + 32 * j;
        if (l < 129) {
            float e = expf(lg[j] - m);
            slog[wid][l] = e;
            es += e;
        }
    }
#pragma unroll
    for (int o = 16; o > 0; o >>= 1) es += __shfl_xor_sync(0xffffffffu, es, o);
    __syncwarp();
    float rinv = 1.f / es;

    int d = lane;
    float att = slog[wid][0] * vtrr[rbase + d];
    const float* vp = vtr + base + (size_t)d * TD;
#pragma unroll 16
    for (int t = 0; t < TD; t++) att += slog[wid][1 + t] * vp[t];
    att *= rinv;
    z[rbase + d] = relay[rbase + d] + att;
}

// ---------------------------------------------------------------------------
// BN stats over (n,t) per channel. grid 256, block 256.
// ---------------------------------------------------------------------------
__global__ void bn_stats_nct(const float* __restrict__ X, float* __restrict__ mean,
                             float* __restrict__ inv, float eps)
{
    int c = blockIdx.x, tid = threadIdx.x;
    float s1 = 0.f, s2 = 0.f;
    for (int i = tid; i < NTOK * TD; i += 256) {
        int n = i >> 7, t = i & 127;
        float x = X[((size_t)n * CD + c) * TD + t];
        s1 += x;
        s2 += x * x;
    }
    __shared__ double d1[256], d2[256];
    d1[tid] = s1; d2[tid] = s2;
    __syncthreads();
    for (int s = 128; s > 0; s >>= 1) {
        if (tid < s) { d1[tid] += d1[tid + s]; d2[tid] += d2[tid + s]; }
        __syncthreads();
    }
    if (tid == 0) {
        double mm = d1[0] / (NTOK * TD);
        double var = d2[0] / (NTOK * TD) - mm * mm;
        mean[c] = (float)mm;
        inv[c] = rsqrtf((float)var + eps);
    }
}

// BN stats over n per channel ([N,C] input). grid 256, block 256.
__global__ void bn_stats_nc(const float* __restrict__ X, float* __restrict__ mean,
                            float* __restrict__ inv, float eps)
{
    int c = blockIdx.x, tid = threadIdx.x;
    float s1 = 0.f, s2 = 0.f;
    for (int n = tid; n < NTOK; n += 256) {
        float x = X[(size_t)n * CD + c];
        s1 += x;
        s2 += x * x;
    }
    __shared__ double d1[256], d2[256];
    d1[tid] = s1; d2[tid] = s2;
    __syncthreads();
    for (int s = 128; s > 0; s >>= 1) {
        if (tid < s) { d1[tid] += d1[tid + s]; d2[tid] += d2[tid + s]; }
        __syncthreads();
    }
    if (tid == 0) {
        double mm = d1[0] / NTOK;
        double var = d2[0] / NTOK - mm * mm;
        mean[c] = (float)mm;
        inv[c] = rsqrtf((float)var + eps);
    }
}

// apply BN affine (+ optional leaky relu) on [N,C,T]
__global__ void affine_nct(const float* __restrict__ X, const float* __restrict__ mean,
                           const float* __restrict__ inv, const float* __restrict__ g,
                           const float* __restrict__ b, float* __restrict__ Y, int leaky)
{
    int idx = blockIdx.x * 256 + threadIdx.x;
    if (idx >= NCT) return;
    int c = (idx >> 7) & 255;
    float vv = (X[idx] - mean[c]) * inv[c] * g[c] + b[c];
    if (leaky && vv < 0.f) vv *= 0.01f;
    Y[idx] = vv;
}

// apply BN affine (+ optional leaky relu) on [N,C]
__global__ void affine_nc(const float* __restrict__ X, const float* __restrict__ mean,
                          const float* __restrict__ inv, const float* __restrict__ g,
                          const float* __restrict__ b, float* __restrict__ Y, int leaky)
{
    int idx = blockIdx.x * 256 + threadIdx.x;
    if (idx >= NC) return;
    int c = idx & 255;
    float vv = (X[idx] - mean[c]) * inv[c] * g[c] + b[c];
    if (leaky && vv < 0.f) vv *= 0.01f;
    Y[idx] = vv;
}

// ---------------------------------------------------------------------------
extern "C" void kernel_launch(void* const* d_in, const int* in_sizes, int n_in,
                              void* d_out, int out_size)
{
    (void)in_sizes; (void)n_in; (void)out_size;
    const float* data    = (const float*)d_in[0];
    const float* ln_g    = (const float*)d_in[1];
    const float* ln_b    = (const float*)d_in[2];
    const float* tj_wq   = (const float*)d_in[3];
    const float* tj_bq   = (const float*)d_in[4];
    const float* tj_wk   = (const float*)d_in[5];
    const float* tj_bk   = (const float*)d_in[6];
    const float* tj_wv   = (const float*)d_in[7];
    const float* tj_bv   = (const float*)d_in[8];
    const float* tj_bng  = (const float*)d_in[9];
    const float* tj_bnb  = (const float*)d_in[10];
    const float* tj_w1   = (const float*)d_in[11];
    const float* tj_b1   = (const float*)d_in[12];
    const float* tj_w2   = (const float*)d_in[13];
    const float* tj_b2   = (const float*)d_in[14];
    const float* tj_fg   = (const float*)d_in[15];
    const float* tj_fb   = (const float*)d_in[16];
    const float* tr_wq   = (const float*)d_in[17];
    const float* tr_bq   = (const float*)d_in[18];
    const float* tr_wk   = (const float*)d_in[19];
    const float* tr_bk   = (const float*)d_in[20];
    const float* tr_wv   = (const float*)d_in[21];
    const float* tr_bv   = (const float*)d_in[22];
    const float* tr_bng  = (const float*)d_in[23];
    const float* tr_bnb  = (const float*)d_in[24];
    const float* tr_w1   = (const float*)d_in[25];
    const float* tr_b1   = (const float*)d_in[26];
    const float* tr_w2   = (const float*)d_in[27];
    const float* tr_b2   = (const float*)d_in[28];
    const float* tr_fg   = (const float*)d_in[29];
    const float* tr_fb   = (const float*)d_in[30];

    float* buf = nullptr;
    cudaGetSymbolAddress((void**)&buf, g_buf);

    float* embs  = buf + OFF_EMBS;
    float* nodes = buf + OFF_NODES;
    float* xln   = buf + OFF_XLN;
    float* qb    = buf + OFF_Q;
    float* kb    = buf + OFF_K;
    float* vb    = buf + OFF_V;
    float* keb   = buf + OFF_KE;
    float* veb   = buf + OFF_VE;
    float* sb    = buf + OFF_S;
    float* retb  = buf + OFF_RET;
    float* ob    = buf + OFF_O;
    float* ktrb  = buf + OFF_KTR;
    float* vtrb  = buf + OFF_VTR;
    float* hb    = buf + OFF_H;
    float* relay = buf + OFF_RELAY;
    float* krb   = buf + OFF_KR;
    float* vrb   = buf + OFF_VR;
    float* qtrb  = buf + OFF_QTR;
    float* ktrr  = buf + OFF_KTRR;
    float* vtrr  = buf + OFF_VTRR;
    float* zb    = buf + OFF_Z;
    float* rettb = buf + OFF_RETT;
    float* otrb  = buf + OFF_OTR;
    float* htrb  = buf + OFF_HTR;
    float* meanb = buf + OFF_MEAN;
    float* invb  = buf + OFF_INV;

    prep_kernel<<<dim3(NTOK, 32), dim3(32, 8)>>>(data, embs, relay);

    const dim3 g_o4(4, NTOK), g_o16(16, NTOK);
    const dim3 gnc4(4, 7), gnc16(16, 7);

    for (int i = 0; i < ITER; i++) {
        const float* nodes_in = (i == 0) ? embs : nodes;
        // LayerNorm over channels
        ln_kernel<<<dim3(NTOK, 4), dim3(32, 8)>>>(nodes_in, ln_g + i * CD, ln_b + i * CD, xln);

        const float* wq = tj_wq + (size_t)i * CD * CD;
        const float* wk = tj_wk + (size_t)i * CD * CD;
        const float* wv = tj_wv + (size_t)i * CD * CD;
        const float* bq = tj_bq + i * CD;
        const float* bk = tj_bk + i * CD;
        const float* bv = tj_bv + i * CD;

        gemm_tf32<0><<<g_o4, 256>>>(wq, bq, xln, qb, nullptr, CD, CD);
        gemm_tf32<0><<<g_o4, 256>>>(wk, bk, xln, kb, nullptr, CD, CD);
        gemm_tf32<0><<<g_o4, 256>>>(wv, bv, xln, vb, nullptr, CD, CD);
        gemm_tf32<0><<<g_o4, 256>>>(wk, bk, embs, keb, nullptr, CD, CD);
        gemm_tf32<0><<<g_o4, 256>>>(wv, bv, embs, veb, nullptr, CD, CD);
        gemm_nc<0><<<gnc4, 256>>>(wk, bk, relay, krb, nullptr, CD, CD);
        gemm_nc<0><<<gnc4, 256>>>(wv, bv, relay, vrb, nullptr, CD, CD);

        attn_tju<<<NTOK * NHH, 128>>>(qb, kb, vb, keb, veb, krb, vrb, xln, sb);

        bn_stats_nct<<<256, 256>>>(sb, meanb, invb, 1e-5f);
        affine_nct<<<NCT / 256, 256>>>(sb, meanb, invb, tj_bng + i * CD, tj_bnb + i * CD, retb, 0);

        gemm_tf32<1><<<g_o16, 256>>>(tj_w1 + (size_t)i * DFFD * CD, tj_b1 + i * DFFD,
                                     retb, hb, nullptr, DFFD, CD);
        gemm_tf32<2><<<g_o4, 256>>>(tj_w2 + (size_t)i * CD * DFFD, tj_b2 + i * CD,
                                    hb, ob, retb, CD, DFFD);

        bn_stats_nct<<<256, 256>>>(ob, meanb, invb, 1e-5f);
        float* nodes_out = (i == ITER - 1) ? (float*)d_out : nodes;
        affine_nct<<<NCT / 256, 256>>>(ob, meanb, invb, tj_fg + i * CD, tj_fb + i * CD,
                                       nodes_out, 1);

        if (i < ITER - 1) {
            const float* rwq = tr_wq + (size_t)i * CD * CD;
            const float* rwk = tr_wk + (size_t)i * CD * CD;
            const float* rwv = tr_wv + (size_t)i * CD * CD;
            const float* rbq = tr_bq + i * CD;
            const float* rbk = tr_bk + i * CD;
            const float* rbv = tr_bv + i * CD;

            gemm_nc<0><<<gnc4, 256>>>(rwq, rbq, relay, qtrb, nullptr, CD, CD);
            gemm_tf32<0><<<g_o4, 256>>>(rwk, rbk, nodes, ktrb, nullptr, CD, CD);
            gemm_tf32<0><<<g_o4, 256>>>(rwv, rbv, nodes, vtrb, nullptr, CD, CD);
            gemm_nc<0><<<gnc4, 256>>>(rwk, rbk, relay, ktrr, nullptr, CD, CD);
            gemm_nc<0><<<gnc4, 256>>>(rwv, rbv, relay, vtrr, nullptr, CD, CD);

            attn_tru<<<NTOK, 256>>>(qtrb, ktrb, vtrb, ktrr, vtrr, relay, zb);

            bn_stats_nc<<<256, 256>>>(zb, meanb, invb, 1e-5f);
            affine_nc<<<NC / 256, 256>>>(zb, meanb, invb, tr_bng + i * CD, tr_bnb + i * CD,
                                         rettb, 0);

            gemm_nc<1><<<gnc16, 256>>>(tr_w1 + (size_t)i * DFFD * CD, tr_b1 + i * DFFD,
                                       rettb, htrb, nullptr, DFFD, CD);
            gemm_nc<2><<<gnc4, 256>>>(tr_w2 + (size_t)i * CD * DFFD, tr_b2 + i * CD,
                                      htrb, otrb, rettb, CD, DFFD);

            bn_stats_nc<<<256, 256>>>(otrb, meanb, invb, 1e-5f);
            affine_nc<<<NC / 256, 256>>>(otrb, meanb, invb, tr_fg + i * CD, tr_fb + i * CD,
                                         relay, 1);
        }
    }
}

// round 5
// speedup vs baseline: 1.5865x; 1.4295x over previous
#include <cuda_runtime.h>
#include <math.h>
#include <stdint.h>

#define NTOK 200
#define CD   256
#define TD   128
#define NHH  8
#define DKK  32
#define DFFD 1024
#define ITER 4
#define NCT  (NTOK*CD*TD)
#define NC   (NTOK*CD)

#define OFF_EMBS   0
#define OFF_NODES  (1*NCT)
#define OFF_XLN    (2*NCT)
#define OFF_Q      (3*NCT)
#define OFF_K      (4*NCT)
#define OFF_V      (5*NCT)
#define OFF_KE     (6*NCT)
#define OFF_VE     (7*NCT)
#define OFF_S      (8*NCT)
#define OFF_RET    (9*NCT)
#define OFF_O      (10*NCT)
#define OFF_KTR    (11*NCT)
#define OFF_VTR    (12*NCT)
#define OFF_H      (13*NCT)            /* N*DFF*T = 4*NCT */
#define OFF_RELAY  (17*NCT)
#define OFF_KR     (OFF_RELAY+NC)
#define OFF_VR     (OFF_KR+NC)
#define OFF_QTR    (OFF_VR+NC)
#define OFF_KTRR   (OFF_QTR+NC)
#define OFF_VTRR   (OFF_KTRR+NC)
#define OFF_Z      (OFF_VTRR+NC)
#define OFF_RETT   (OFF_Z+NC)
#define OFF_OTR    (OFF_RETT+NC)
#define OFF_HTR    (OFF_OTR+NC)
#define OFF_MEAN   (OFF_HTR+NTOK*DFFD)
#define OFF_INV    (OFF_MEAN+256)
#define BUF_TOTAL  (OFF_INV+256)

__device__ __align__(16) float g_buf[BUF_TOTAL];

__device__ __forceinline__ uint32_t f2tf32(float x) {
    uint32_t r;
    asm("cvt.rna.tf32.f32 %0, %1;" : "=r"(r) : "f"(x));
    return r;
}

#define MMA_TF32(C, A, B)                                                     \
    asm volatile("mma.sync.aligned.m16n8k8.row.col.f32.tf32.tf32.f32 "        \
                 "{%0,%1,%2,%3}, {%4,%5,%6,%7}, {%8,%9}, {%0,%1,%2,%3};\n"    \
                 : "+f"((C)[0]), "+f"((C)[1]), "+f"((C)[2]), "+f"((C)[3])     \
                 : "r"((A)[0]), "r"((A)[1]), "r"((A)[2]), "r"((A)[3]),        \
                   "r"((B)[0]), "r"((B)[1]));

// ---------------------------------------------------------------------------
// prep: embs[n,c,t] = data[b,c,v,t] (n=b*25+v), relay[n,c] = mean_t embs
// ---------------------------------------------------------------------------
__global__ void prep_kernel(const float* __restrict__ data,
                            float* __restrict__ embs, float* __restrict__ relay)
{
    int n = blockIdx.x;
    int b = n / 25, v = n % 25;
    int c = blockIdx.y * 8 + threadIdx.y;
    int tx = threadIdx.x;
    const float* src = data + (((size_t)b * CD + c) * 25 + v) * TD;
    float* dst = embs + ((size_t)n * CD + c) * TD;
    float s = 0.f;
#pragma unroll
    for (int j = 0; j < 4; j++) {
        int t = tx + 32 * j;
        float x = src[t];
        dst[t] = x;
        s += x;
    }
#pragma unroll
    for (int o = 16; o > 0; o >>= 1) s += __shfl_xor_sync(0xffffffffu, s, o);
    if (tx == 0) relay[n * CD + c] = s * (1.0f / 128.0f);
}

// ---------------------------------------------------------------------------
// LayerNorm over channel dim. grid (NTOK, 4), block (32,8)
// ---------------------------------------------------------------------------
__global__ void ln_kernel(const float* __restrict__ X, const float* __restrict__ g,
                          const float* __restrict__ b, float* __restrict__ Y)
{
    int n = blockIdx.x;
    int t = blockIdx.y * 32 + threadIdx.x;
    int tx = threadIdx.x, ty = threadIdx.y;
    float x[32];
    float s1 = 0.f, s2 = 0.f;
#pragma unroll
    for (int j = 0; j < 32; j++) {
        int c = ty + j * 8;
        x[j] = X[((size_t)n * CD + c) * TD + t];
        s1 += x[j];
        s2 += x[j] * x[j];
    }
    __shared__ float sm1[8][32], sm2[8][32], smean[32], sinv[32];
    sm1[ty][tx] = s1; sm2[ty][tx] = s2;
    __syncthreads();
    if (ty == 0) {
        float a = 0.f, bb = 0.f;
#pragma unroll
        for (int qy = 0; qy < 8; qy++) { a += sm1[qy][tx]; bb += sm2[qy][tx]; }
        float m = a * (1.0f / 256.0f);
        float var = bb * (1.0f / 256.0f) - m * m;
        smean[tx] = m;
        sinv[tx] = rsqrtf(var + 1e-6f);
    }
    __syncthreads();
    float m = smean[tx], inv = sinv[tx];
#pragma unroll
    for (int j = 0; j < 32; j++) {
        int c = ty + j * 8;
        Y[((size_t)n * CD + c) * TD + t] = (x[j] - m) * inv * g[c] + b[c];
    }
}

// ---------------------------------------------------------------------------
// TF32 tensor-core GEMM: Y[n,o,t] = sum_c W[o,c]*X[n,c,t] + bias[o]
// T fixed = 128. Block tile: 64 (o) x 128 (t), K-chunk 32.
// 8 warps: warp_o in {0,1}, warp_t in {0..3}; warp tile 32x32.
// Natural smem layouts (no transpose):
//   Ws[o][k]  stride 36 (36 mod 32 = 4  -> A-frag bank = 4g+q, bijective)
//   Xs[k][t]  stride 136 (136 mod 32 = 8 -> B-frag bank = 8q+g, bijective)
// Staging = contiguous STS.128 (conflict-free). Register-prefetch next chunk.
// EPI: 0 = bias only, 1 = relu, 2 = +Res
// grid (O/64, NTOK), block 256
// ---------------------------------------------------------------------------
#define WS_STR 36
#define XS_STR 136

template <int EPI>
__global__ __launch_bounds__(256)
void gemm_tf32(const float* __restrict__ W, const float* __restrict__ bias,
               const float* __restrict__ X, float* __restrict__ Y,
               const float* __restrict__ Res, int O, int Cin)
{
    int n = blockIdx.y;
    int o0 = blockIdx.x * 64;
    const float* Xn = X + (size_t)n * Cin * TD;
    int tid = threadIdx.x;
    int lane = tid & 31, wid = tid >> 5;
    int warp_o = wid >> 2, warp_t = wid & 3;
    int g = lane >> 2, q = lane & 3;

    __shared__ __align__(16) uint32_t Ws[64 * WS_STR];
    __shared__ __align__(16) uint32_t Xs[32 * XS_STR];

    // staging assignment
    int wo = tid >> 2, wk = (tid & 3) * 8;   // W: row wo, 2xfloat4 at k=wk
    int xk = tid >> 3, xt = (tid & 7) * 16;  // X: row xk, 4xfloat4 at t=xt

    const float* wp = W + (size_t)(o0 + wo) * Cin + wk;
    const float* xp = Xn + (size_t)xk * TD + xt;

    float4 wreg[2], xreg[4];
    wreg[0] = *(const float4*)(wp);
    wreg[1] = *(const float4*)(wp + 4);
#pragma unroll
    for (int u = 0; u < 4; u++) xreg[u] = *(const float4*)(xp + 4 * u);

#define STORE_TILE()                                                          \
    do {                                                                      \
        uint4 s0, s1;                                                         \
        s0.x = f2tf32(wreg[0].x); s0.y = f2tf32(wreg[0].y);                   \
        s0.z = f2tf32(wreg[0].z); s0.w = f2tf32(wreg[0].w);                   \
        s1.x = f2tf32(wreg[1].x); s1.y = f2tf32(wreg[1].y);                   \
        s1.z = f2tf32(wreg[1].z); s1.w = f2tf32(wreg[1].w);                   \
        *(uint4*)&Ws[wo * WS_STR + wk]     = s0;                              \
        *(uint4*)&Ws[wo * WS_STR + wk + 4] = s1;                              \
        _Pragma("unroll")                                                     \
        for (int u = 0; u < 4; u++) {                                         \
            uint4 xx;                                                         \
            xx.x = f2tf32(xreg[u].x); xx.y = f2tf32(xreg[u].y);               \
            xx.z = f2tf32(xreg[u].z); xx.w = f2tf32(xreg[u].w);               \
            *(uint4*)&Xs[xk * XS_STR + xt + 4 * u] = xx;                      \
        }                                                                     \
    } while (0)

    STORE_TILE();
    __syncthreads();

    float acc[2][4][4];
#pragma unroll
    for (int m = 0; m < 2; m++)
#pragma unroll
        for (int nf = 0; nf < 4; nf++)
#pragma unroll
            for (int j = 0; j < 4; j++) acc[m][nf][j] = 0.f;

    int nchunks = Cin >> 5;
    for (int c = 0; c < nchunks; c++) {
        if (c + 1 < nchunks) {
            // prefetch next chunk into registers (overlaps with MMA below)
            wp += 32;
            xp += 32 * TD;
            wreg[0] = *(const float4*)(wp);
            wreg[1] = *(const float4*)(wp + 4);
#pragma unroll
            for (int u = 0; u < 4; u++) xreg[u] = *(const float4*)(xp + 4 * u);
        }

#pragma unroll
        for (int ks = 0; ks < 32; ks += 8) {
            uint32_t a[2][4], b[4][2];
#pragma unroll
            for (int m = 0; m < 2; m++) {
                int ar = (warp_o * 32 + m * 16 + g) * WS_STR + ks + q;
                a[m][0] = Ws[ar];
                a[m][1] = Ws[ar + 8 * WS_STR];
                a[m][2] = Ws[ar + 4];
                a[m][3] = Ws[ar + 8 * WS_STR + 4];
            }
#pragma unroll
            for (int nf = 0; nf < 4; nf++) {
                int br = (ks + q) * XS_STR + warp_t * 32 + nf * 8 + g;
                b[nf][0] = Xs[br];
                b[nf][1] = Xs[br + 4 * XS_STR];
            }
#pragma unroll
            for (int m = 0; m < 2; m++)
#pragma unroll
                for (int nf = 0; nf < 4; nf++)
                    MMA_TF32(acc[m][nf], a[m], b[nf]);
        }

        if (c + 1 < nchunks) {
            __syncthreads();   // everyone done reading current tile
            STORE_TILE();
            __syncthreads();   // new tile visible
        }
    }
#undef STORE_TILE

    // epilogue: c0,c1 at (row g, cols 2q,2q+1); c2,c3 at (row g+8)
#pragma unroll
    for (int m = 0; m < 2; m++) {
        int obase = o0 + warp_o * 32 + m * 16 + g;
#pragma unroll
        for (int r = 0; r < 2; r++) {
            int o = obase + r * 8;
            float bs = bias[o];
            float* yrow = Y + ((size_t)n * O + o) * TD;
            const float* rrow = (EPI == 2) ? (Res + ((size_t)n * O + o) * TD) : nullptr;
#pragma unroll
            for (int nf = 0; nf < 4; nf++) {
                int t = warp_t * 32 + nf * 8 + q * 2;
                float v0 = acc[m][nf][r * 2 + 0] + bs;
                float v1 = acc[m][nf][r * 2 + 1] + bs;
                if (EPI == 1) { v0 = fmaxf(v0, 0.f); v1 = fmaxf(v1, 0.f); }
                if (EPI == 2) {
                    float2 rr = *(const float2*)(rrow + t);
                    v0 += rr.x; v1 += rr.y;
                }
                *(float2*)(yrow + t) = make_float2(v0, v1);
            }
        }
    }
}

// ---------------------------------------------------------------------------
// Small GEMM over [N, Cin] tokens (relay path, fp32): Y[n,o] = W[o,:]*X[n,:]+b
// grid (O/64, ceil(N/32)), block 256
// ---------------------------------------------------------------------------
template <int EPI>
__global__ __launch_bounds__(256)
void gemm_nc(const float* __restrict__ W, const float* __restrict__ bias,
             const float* __restrict__ X, float* __restrict__ Y,
             const float* __restrict__ Res, int O, int Cin)
{
    int o0 = blockIdx.x * 64;
    int n0 = blockIdx.y * 32;
    int tid = threadIdx.x;
    int tx = tid & 31, ty = tid >> 5;

    __shared__ float Ws[32][64];
    __shared__ float Xs[32][33];

    float acc[8];
#pragma unroll
    for (int i = 0; i < 8; i++) acc[i] = 0.f;

    for (int k0 = 0; k0 < Cin; k0 += 32) {
#pragma unroll
        for (int r = 0; r < 2; r++) {
            int idx = tid + 256 * r;
            int o = idx >> 3, kq = idx & 7;
            float4 w4 = *(const float4*)(W + (size_t)(o0 + o) * Cin + k0 + kq * 4);
            Ws[kq * 4 + 0][o] = w4.x;
            Ws[kq * 4 + 1][o] = w4.y;
            Ws[kq * 4 + 2][o] = w4.z;
            Ws[kq * 4 + 3][o] = w4.w;
        }
        {
            int nn = tid >> 3, kq = tid & 7;
            int n = n0 + nn;
            float4 x4 = make_float4(0.f, 0.f, 0.f, 0.f);
            if (n < NTOK) x4 = *(const float4*)(X + (size_t)n * Cin + k0 + kq * 4);
            Xs[kq * 4 + 0][nn] = x4.x;
            Xs[kq * 4 + 1][nn] = x4.y;
            Xs[kq * 4 + 2][nn] = x4.z;
            Xs[kq * 4 + 3][nn] = x4.w;
        }
        __syncthreads();
#pragma unroll
        for (int kk = 0; kk < 32; kk++) {
            float bv = Xs[kk][tx];
#pragma unroll
            for (int i = 0; i < 8; i++) acc[i] += Ws[kk][ty * 8 + i] * bv;
        }
        __syncthreads();
    }

    int n = n0 + tx;
    if (n < NTOK) {
#pragma unroll
        for (int i = 0; i < 8; i++) {
            int o = o0 + ty * 8 + i;
            float val = acc[i] + bias[o];
            if (EPI == 1) val = fmaxf(val, 0.f);
            if (EPI == 2) val += Res[(size_t)n * O + o];
            Y[(size_t)n * O + o] = val;
        }
    }
}

// ---------------------------------------------------------------------------
// tju attention (window-3 + emb token + relay token), fused residual add.
// grid NTOK*NHH, block 128 (one thread per t)
// ---------------------------------------------------------------------------
__global__ void attn_tju(const float* __restrict__ q, const float* __restrict__ k,
                         const float* __restrict__ v, const float* __restrict__ ke,
                         const float* __restrict__ ve, const float* __restrict__ kr,
                         const float* __restrict__ vr, const float* __restrict__ xln,
                         float* __restrict__ sout)
{
    int nh = blockIdx.x;
    int n = nh >> 3, h = nh & 7;
    int t = threadIdx.x;
    int rbase = n * CD + h * DKK;
    size_t base = (size_t)rbase * TD;

    float l0 = 0.f, l1 = 0.f, l2 = 0.f, l3 = 0.f, l4 = 0.f;
#pragma unroll 8
    for (int d = 0; d < DKK; d++) {
        size_t off = base + (size_t)d * TD + t;
        float qd = q[off];
        float kc = k[off];
        float km = (t > 0) ? k[off - 1] : 0.f;
        float kp = (t < TD - 1) ? k[off + 1] : 0.f;
        l0 += qd * km;
        l1 += qd * kc;
        l2 += qd * kp;
        l3 += qd * ke[off];
        l4 += qd * kr[rbase + d];
    }
    const float sc = 0.17677669529663687f; // 1/sqrt(32)
    l0 *= sc; l1 *= sc; l2 *= sc; l3 *= sc; l4 *= sc;
    float m = fmaxf(fmaxf(fmaxf(l0, l1), fmaxf(l2, l3)), l4);
    float e0 = expf(l0 - m), e1 = expf(l1 - m), e2 = expf(l2 - m);
    float e3 = expf(l3 - m), e4 = expf(l4 - m);
    float rs = 1.f / (e0 + e1 + e2 + e3 + e4);
    float a0 = e0 * rs, a1 = e1 * rs, a2 = e2 * rs, a3 = e3 * rs, a4 = e4 * rs;

#pragma unroll 8
    for (int d = 0; d < DKK; d++) {
        size_t off = base + (size_t)d * TD + t;
        float vc = v[off];
        float vm = (t > 0) ? v[off - 1] : 0.f;
        float vp = (t < TD - 1) ? v[off + 1] : 0.f;
        float att = a0 * vm + a1 * vc + a2 * vp + a3 * ve[off] + a4 * vr[rbase + d];
        sout[off] = xln[off] + att;
    }
}

// ---------------------------------------------------------------------------
// tru attention (relay over 129 tokens). block 256 = 8 warps, grid 200.
// ---------------------------------------------------------------------------
__global__ void attn_tru(const float* __restrict__ qtr, const float* __restrict__ ktr,
                         const float* __restrict__ vtr, const float* __restrict__ ktrr,
                         const float* __restrict__ vtrr, const float* __restrict__ relay,
                         float* __restrict__ z)
{
    __shared__ float sq[8][DKK];
    __shared__ float slog[8][132];
    int wid = threadIdx.x >> 5, lane = threadIdx.x & 31;
    int nh = blockIdx.x * 8 + wid;
    int n = nh >> 3, h = nh & 7;
    int rbase = n * CD + h * DKK;
    size_t base = (size_t)rbase * TD;
    const float sc = 0.17677669529663687f;

    sq[wid][lane] = qtr[rbase + lane];
    __syncwarp();

    float lg[5];
#pragma unroll
    for (int j = 0; j < 5; j++) {
        int l = lane + 32 * j;
        float acc = -1e30f;
        if (l < 129) {
            acc = 0.f;
            if (l == 0) {
#pragma unroll 8
                for (int d = 0; d < DKK; d++) acc += sq[wid][d] * ktrr[rbase + d];
            } else {
                int t = l - 1;
#pragma unroll 8
                for (int d = 0; d < DKK; d++) acc += sq[wid][d] * ktr[base + (size_t)d * TD + t];
            }
            acc *= sc;
        }
        lg[j] = acc;
    }
    float m = -1e30f;
#pragma unroll
    for (int j = 0; j < 5; j++) m = fmaxf(m, lg[j]);
#pragma unroll
    for (int o = 16; o > 0; o >>= 1) m = fmaxf(m, __shfl_xor_sync(0xffffffffu, m, o));
    float es = 0.f;
#pragma unroll
    for (int j = 0; j < 5; j++) {
        int l = lane + 32 * j;
        if (l < 129) {
            float e = expf(lg[j] - m);
            slog[wid][l] = e;
            es += e;
        }
    }
#pragma unroll
    for (int o = 16; o > 0; o >>= 1) es += __shfl_xor_sync(0xffffffffu, es, o);
    __syncwarp();
    float rinv = 1.f / es;

    int d = lane;
    float att = slog[wid][0] * vtrr[rbase + d];
    const float* vp = vtr + base + (size_t)d * TD;
#pragma unroll 16
    for (int t = 0; t < TD; t++) att += slog[wid][1 + t] * vp[t];
    att *= rinv;
    z[rbase + d] = relay[rbase + d] + att;
}

// ---------------------------------------------------------------------------
// BN stats over (n,t) per channel. grid 256, block 256.
// ---------------------------------------------------------------------------
__global__ void bn_stats_nct(const float* __restrict__ X, float* __restrict__ mean,
                             float* __restrict__ inv, float eps)
{
    int c = blockIdx.x, tid = threadIdx.x;
    float s1 = 0.f, s2 = 0.f;
    for (int i = tid; i < NTOK * TD; i += 256) {
        int n = i >> 7, t = i & 127;
        float x = X[((size_t)n * CD + c) * TD + t];
        s1 += x;
        s2 += x * x;
    }
    __shared__ double d1[256], d2[256];
    d1[tid] = s1; d2[tid] = s2;
    __syncthreads();
    for (int s = 128; s > 0; s >>= 1) {
        if (tid < s) { d1[tid] += d1[tid + s]; d2[tid] += d2[tid + s]; }
        __syncthreads();
    }
    if (tid == 0) {
        double mm = d1[0] / (NTOK * TD);
        double var = d2[0] / (NTOK * TD) - mm * mm;
        mean[c] = (float)mm;
        inv[c] = rsqrtf((float)var + eps);
    }
}

// BN stats over n per channel ([N,C] input). grid 256, block 256.
__global__ void bn_stats_nc(const float* __restrict__ X, float* __restrict__ mean,
                            float* __restrict__ inv, float eps)
{
    int c = blockIdx.x, tid = threadIdx.x;
    float s1 = 0.f, s2 = 0.f;
    for (int n = tid; n < NTOK; n += 256) {
        float x = X[(size_t)n * CD + c];
        s1 += x;
        s2 += x * x;
    }
    __shared__ double d1[256], d2[256];
    d1[tid] = s1; d2[tid] = s2;
    __syncthreads();
    for (int s = 128; s > 0; s >>= 1) {
        if (tid < s) { d1[tid] += d1[tid + s]; d2[tid] += d2[tid + s]; }
        __syncthreads();
    }
    if (tid == 0) {
        double mm = d1[0] / NTOK;
        double var = d2[0] / NTOK - mm * mm;
        mean[c] = (float)mm;
        inv[c] = rsqrtf((float)var + eps);
    }
}

// apply BN affine (+ optional leaky relu) on [N,C,T]
__global__ void affine_nct(const float* __restrict__ X, const float* __restrict__ mean,
                           const float* __restrict__ inv, const float* __restrict__ g,
                           const float* __restrict__ b, float* __restrict__ Y, int leaky)
{
    int idx = blockIdx.x * 256 + threadIdx.x;
    if (idx >= NCT) return;
    int c = (idx >> 7) & 255;
    float vv = (X[idx] - mean[c]) * inv[c] * g[c] + b[c];
    if (leaky && vv < 0.f) vv *= 0.01f;
    Y[idx] = vv;
}

// apply BN affine (+ optional leaky relu) on [N,C]
__global__ void affine_nc(const float* __restrict__ X, const float* __restrict__ mean,
                          const float* __restrict__ inv, const float* __restrict__ g,
                          const float* __restrict__ b, float* __restrict__ Y, int leaky)
{
    int idx = blockIdx.x * 256 + threadIdx.x;
    if (idx >= NC) return;
    int c = idx & 255;
    float vv = (X[idx] - mean[c]) * inv[c] * g[c] + b[c];
    if (leaky && vv < 0.f) vv *= 0.01f;
    Y[idx] = vv;
}

// ---------------------------------------------------------------------------
extern "C" void kernel_launch(void* const* d_in, const int* in_sizes, int n_in,
                              void* d_out, int out_size)
{
    (void)in_sizes; (void)n_in; (void)out_size;
    const float* data    = (const float*)d_in[0];
    const float* ln_g    = (const float*)d_in[1];
    const float* ln_b    = (const float*)d_in[2];
    const float* tj_wq   = (const float*)d_in[3];
    const float* tj_bq   = (const float*)d_in[4];
    const float* tj_wk   = (const float*)d_in[5];
    const float* tj_bk   = (const float*)d_in[6];
    const float* tj_wv   = (const float*)d_in[7];
    const float* tj_bv   = (const float*)d_in[8];
    const float* tj_bng  = (const float*)d_in[9];
    const float* tj_bnb  = (const float*)d_in[10];
    const float* tj_w1   = (const float*)d_in[11];
    const float* tj_b1   = (const float*)d_in[12];
    const float* tj_w2   = (const float*)d_in[13];
    const float* tj_b2   = (const float*)d_in[14];
    const float* tj_fg   = (const float*)d_in[15];
    const float* tj_fb   = (const float*)d_in[16];
    const float* tr_wq   = (const float*)d_in[17];
    const float* tr_bq   = (const float*)d_in[18];
    const float* tr_wk   = (const float*)d_in[19];
    const float* tr_bk   = (const float*)d_in[20];
    const float* tr_wv   = (const float*)d_in[21];
    const float* tr_bv   = (const float*)d_in[22];
    const float* tr_bng  = (const float*)d_in[23];
    const float* tr_bnb  = (const float*)d_in[24];
    const float* tr_w1   = (const float*)d_in[25];
    const float* tr_b1   = (const float*)d_in[26];
    const float* tr_w2   = (const float*)d_in[27];
    const float* tr_b2   = (const float*)d_in[28];
    const float* tr_fg   = (const float*)d_in[29];
    const float* tr_fb   = (const float*)d_in[30];

    float* buf = nullptr;
    cudaGetSymbolAddress((void**)&buf, g_buf);

    float* embs  = buf + OFF_EMBS;
    float* nodes = buf + OFF_NODES;
    float* xln   = buf + OFF_XLN;
    float* qb    = buf + OFF_Q;
    float* kb    = buf + OFF_K;
    float* vb    = buf + OFF_V;
    float* keb   = buf + OFF_KE;
    float* veb   = buf + OFF_VE;
    float* sb    = buf + OFF_S;
    float* retb  = buf + OFF_RET;
    float* ob    = buf + OFF_O;
    float* ktrb  = buf + OFF_KTR;
    float* vtrb  = buf + OFF_VTR;
    float* hb    = buf + OFF_H;
    float* relay = buf + OFF_RELAY;
    float* krb   = buf + OFF_KR;
    float* vrb   = buf + OFF_VR;
    float* qtrb  = buf + OFF_QTR;
    float* ktrr  = buf + OFF_KTRR;
    float* vtrr  = buf + OFF_VTRR;
    float* zb    = buf + OFF_Z;
    float* rettb = buf + OFF_RETT;
    float* otrb  = buf + OFF_OTR;
    float* htrb  = buf + OFF_HTR;
    float* meanb = buf + OFF_MEAN;
    float* invb  = buf + OFF_INV;

    prep_kernel<<<dim3(NTOK, 32), dim3(32, 8)>>>(data, embs, relay);

    const dim3 g_o4(4, NTOK), g_o16(16, NTOK);
    const dim3 gnc4(4, 7), gnc16(16, 7);

    for (int i = 0; i < ITER; i++) {
        const float* nodes_in = (i == 0) ? embs : nodes;
        // LayerNorm over channels
        ln_kernel<<<dim3(NTOK, 4), dim3(32, 8)>>>(nodes_in, ln_g + i * CD, ln_b + i * CD, xln);

        const float* wq = tj_wq + (size_t)i * CD * CD;
        const float* wk = tj_wk + (size_t)i * CD * CD;
        const float* wv = tj_wv + (size_t)i * CD * CD;
        const float* bq = tj_bq + i * CD;
        const float* bk = tj_bk + i * CD;
        const float* bv = tj_bv + i * CD;

        gemm_tf32<0><<<g_o4, 256>>>(wq, bq, xln, qb, nullptr, CD, CD);
        gemm_tf32<0><<<g_o4, 256>>>(wk, bk, xln, kb, nullptr, CD, CD);
        gemm_tf32<0><<<g_o4, 256>>>(wv, bv, xln, vb, nullptr, CD, CD);
        gemm_tf32<0><<<g_o4, 256>>>(wk, bk, embs, keb, nullptr, CD, CD);
        gemm_tf32<0><<<g_o4, 256>>>(wv, bv, embs, veb, nullptr, CD, CD);
        gemm_nc<0><<<gnc4, 256>>>(wk, bk, relay, krb, nullptr, CD, CD);
        gemm_nc<0><<<gnc4, 256>>>(wv, bv, relay, vrb, nullptr, CD, CD);

        attn_tju<<<NTOK * NHH, 128>>>(qb, kb, vb, keb, veb, krb, vrb, xln, sb);

        bn_stats_nct<<<256, 256>>>(sb, meanb, invb, 1e-5f);
        affine_nct<<<NCT / 256, 256>>>(sb, meanb, invb, tj_bng + i * CD, tj_bnb + i * CD, retb, 0);

        gemm_tf32<1><<<g_o16, 256>>>(tj_w1 + (size_t)i * DFFD * CD, tj_b1 + i * DFFD,
                                     retb, hb, nullptr, DFFD, CD);
        gemm_tf32<2><<<g_o4, 256>>>(tj_w2 + (size_t)i * CD * DFFD, tj_b2 + i * CD,
                                    hb, ob, retb, CD, DFFD);

        bn_stats_nct<<<256, 256>>>(ob, meanb, invb, 1e-5f);
        float* nodes_out = (i == ITER - 1) ? (float*)d_out : nodes;
        affine_nct<<<NCT / 256, 256>>>(ob, meanb, invb, tj_fg + i * CD, tj_fb + i * CD,
                                       nodes_out, 1);

        if (i < ITER - 1) {
            const float* rwq = tr_wq + (size_t)i * CD * CD;
            const float* rwk = tr_wk + (size_t)i * CD * CD;
            const float* rwv = tr_wv + (size_t)i * CD * CD;
            const float* rbq = tr_bq + i * CD;
            const float* rbk = tr_bk + i * CD;
            const float* rbv = tr_bv + i * CD;

            gemm_nc<0><<<gnc4, 256>>>(rwq, rbq, relay, qtrb, nullptr, CD, CD);
            gemm_tf32<0><<<g_o4, 256>>>(rwk, rbk, nodes, ktrb, nullptr, CD, CD);
            gemm_tf32<0><<<g_o4, 256>>>(rwv, rbv, nodes, vtrb, nullptr, CD, CD);
            gemm_nc<0><<<gnc4, 256>>>(rwk, rbk, relay, ktrr, nullptr, CD, CD);
            gemm_nc<0><<<gnc4, 256>>>(rwv, rbv, relay, vtrr, nullptr, CD, CD);

            attn_tru<<<NTOK, 256>>>(qtrb, ktrb, vtrb, ktrr, vtrr, relay, zb);

            bn_stats_nc<<<256, 256>>>(zb, meanb, invb, 1e-5f);
            affine_nc<<<NC / 256, 256>>>(zb, meanb, invb, tr_bng + i * CD, tr_bnb + i * CD,
                                         rettb, 0);

            gemm_nc<1><<<gnc16, 256>>>(tr_w1 + (size_t)i * DFFD * CD, tr_b1 + i * DFFD,
                                       rettb, htrb, nullptr, DFFD, CD);
            gemm_nc<2><<<gnc4, 256>>>(tr_w2 + (size_t)i * CD * DFFD, tr_b2 + i * CD,
                                      htrb, otrb, rettb, CD, DFFD);

            bn_stats_nc<<<256, 256>>>(otrb, meanb, invb, 1e-5f);
            affine_nc<<<NC / 256, 256>>>(otrb, meanb, invb, tr_fg + i * CD, tr_fb + i * CD,
                                         relay, 1);
        }
    }
}

// round 6
// speedup vs baseline: 1.6782x; 1.0578x over previous
#include <cuda_runtime.h>
#include <math.h>
#include <stdint.h>

#define NTOK 200
#define CD   256
#define TD   128
#define NHH  8
#define DKK  32
#define DFFD 1024
#define ITER 4
#define NCT  (NTOK*CD*TD)
#define NC   (NTOK*CD)

#define OFF_EMBS   0
#define OFF_NODES  (1*NCT)
#define OFF_XLN    (2*NCT)
#define OFF_Q      (3*NCT)
#define OFF_K      (4*NCT)
#define OFF_V      (5*NCT)
#define OFF_KE     (6*NCT)
#define OFF_VE     (7*NCT)
#define OFF_S      (8*NCT)
#define OFF_RET    (9*NCT)
#define OFF_O      (10*NCT)
#define OFF_KTR    (11*NCT)
#define OFF_VTR    (12*NCT)
#define OFF_H      (13*NCT)            /* N*DFF*T = 4*NCT */
#define OFF_RELAY  (17*NCT)
#define OFF_KR     (OFF_RELAY+NC)
#define OFF_VR     (OFF_KR+NC)
#define OFF_QTR    (OFF_VR+NC)
#define OFF_KTRR   (OFF_QTR+NC)
#define OFF_VTRR   (OFF_KTRR+NC)
#define OFF_Z      (OFF_VTRR+NC)
#define OFF_RETT   (OFF_Z+NC)
#define OFF_OTR    (OFF_RETT+NC)
#define OFF_HTR    (OFF_OTR+NC)
#define OFF_MEAN   (OFF_HTR+NTOK*DFFD)
#define OFF_INV    (OFF_MEAN+256)
#define BUF_TOTAL  (OFF_INV+256)

__device__ __align__(16) float g_buf[BUF_TOTAL];

__device__ __forceinline__ uint32_t f2tf32(float x) {
    uint32_t r;
    asm("cvt.rna.tf32.f32 %0, %1;" : "=r"(r) : "f"(x));
    return r;
}

#define MMA_TF32(C, A, B)                                                     \
    asm volatile("mma.sync.aligned.m16n8k8.row.col.f32.tf32.tf32.f32 "        \
                 "{%0,%1,%2,%3}, {%4,%5,%6,%7}, {%8,%9}, {%0,%1,%2,%3};\n"    \
                 : "+f"((C)[0]), "+f"((C)[1]), "+f"((C)[2]), "+f"((C)[3])     \
                 : "r"((A)[0]), "r"((A)[1]), "r"((A)[2]), "r"((A)[3]),        \
                   "r"((B)[0]), "r"((B)[1]));

// ---------------------------------------------------------------------------
// prep: embs[n,c,t] = data[b,c,v,t] (n=b*25+v), relay[n,c] = mean_t embs
// ---------------------------------------------------------------------------
__global__ void prep_kernel(const float* __restrict__ data,
                            float* __restrict__ embs, float* __restrict__ relay)
{
    int n = blockIdx.x;
    int b = n / 25, v = n % 25;
    int c = blockIdx.y * 8 + threadIdx.y;
    int tx = threadIdx.x;
    const float* src = data + (((size_t)b * CD + c) * 25 + v) * TD;
    float* dst = embs + ((size_t)n * CD + c) * TD;
    float s = 0.f;
#pragma unroll
    for (int j = 0; j < 4; j++) {
        int t = tx + 32 * j;
        float x = src[t];
        dst[t] = x;
        s += x;
    }
#pragma unroll
    for (int o = 16; o > 0; o >>= 1) s += __shfl_xor_sync(0xffffffffu, s, o);
    if (tx == 0) relay[n * CD + c] = s * (1.0f / 128.0f);
}

// ---------------------------------------------------------------------------
// LayerNorm over channel dim. grid (NTOK, 4), block (32,8)
// ---------------------------------------------------------------------------
__global__ void ln_kernel(const float* __restrict__ X, const float* __restrict__ g,
                          const float* __restrict__ b, float* __restrict__ Y)
{
    int n = blockIdx.x;
    int t = blockIdx.y * 32 + threadIdx.x;
    int tx = threadIdx.x, ty = threadIdx.y;
    float x[32];
    float s1 = 0.f, s2 = 0.f;
#pragma unroll
    for (int j = 0; j < 32; j++) {
        int c = ty + j * 8;
        x[j] = X[((size_t)n * CD + c) * TD + t];
        s1 += x[j];
        s2 += x[j] * x[j];
    }
    __shared__ float sm1[8][32], sm2[8][32], smean[32], sinv[32];
    sm1[ty][tx] = s1; sm2[ty][tx] = s2;
    __syncthreads();
    if (ty == 0) {
        float a = 0.f, bb = 0.f;
#pragma unroll
        for (int qy = 0; qy < 8; qy++) { a += sm1[qy][tx]; bb += sm2[qy][tx]; }
        float m = a * (1.0f / 256.0f);
        float var = bb * (1.0f / 256.0f) - m * m;
        smean[tx] = m;
        sinv[tx] = rsqrtf(var + 1e-6f);
    }
    __syncthreads();
    float m = smean[tx], inv = sinv[tx];
#pragma unroll
    for (int j = 0; j < 32; j++) {
        int c = ty + j * 8;
        Y[((size_t)n * CD + c) * TD + t] = (x[j] - m) * inv * g[c] + b[c];
    }
}

// ---------------------------------------------------------------------------
// TF32 tensor-core GEMM: Y[n,o,t] = sum_c W[o,c]*X[n,c,t] + bias[o]
// T fixed = 128. Block tile: 64 (o) x 128 (t), K-chunk 32.
// 8 warps: warp_o in {0,1}, warp_t in {0..3}; warp tile 32x32.
// Smem:
//   Wf = W chunk in FRAGMENT order: Wf[frag=mt*4+kt][lane][4 regs]
//        -> one LDS.128 per A-fragment, conflict-free (phase banks 4l..4l+3)
//   Xs = X chunk natural [k][t], stride 132 (132 mod 32 = 4 -> B-frag bank
//        = 4q+g, bijective over warp)
// Staging: Wf via 4 scattered LDG.32 + 1 STS.128 per frag-lane (conflict-free);
//   Xs via float4 loads at xt=(tid&7)*4 + 32u -> STS.128 banks 4*xk+4*(tid&7),
//   distinct per 8-lane phase. Register-prefetch next chunk.
// EPI: 0 = bias only, 1 = relu, 2 = +Res
// grid (O/64, NTOK), block 256
// ---------------------------------------------------------------------------
#define XS_STR 132

template <int EPI>
__global__ __launch_bounds__(256)
void gemm_tf32(const float* __restrict__ W, const float* __restrict__ bias,
               const float* __restrict__ X, float* __restrict__ Y,
               const float* __restrict__ Res, int O, int Cin)
{
    int n = blockIdx.y;
    int o0 = blockIdx.x * 64;
    const float* Xn = X + (size_t)n * Cin * TD;
    int tid = threadIdx.x;
    int lane = tid & 31, wid = tid >> 5;
    int warp_o = wid >> 2, warp_t = wid & 3;
    int g = lane >> 2, q = lane & 3;

    __shared__ __align__(16) uint32_t Wf[16 * 128];      // 8 KB, fragment order
    __shared__ __align__(16) uint32_t Xs[32 * XS_STR];   // 16.5 KB, [k][t]

    // ---- staging assignments ----
    // W: two frag-lanes per thread: (f0 = tid>>5, sl = tid&31) and f1 = f0+8
    int f0 = tid >> 5, sl = tid & 31;
    int slg = sl >> 2, slq = sl & 3;
    int og0 = ((f0 >> 2) << 4) + slg, kg0 = ((f0 & 3) << 3) + slq;
    int og1 = (((f0 + 8) >> 2) << 4) + slg, kg1 = kg0;  // f1&3 == f0&3
    const float* wp0 = W + (size_t)(o0 + og0) * Cin + kg0;
    const float* wp1 = W + (size_t)(o0 + og1) * Cin + kg1;
    // X: row xk, 4 float4 at t = xt + 32u
    int xk = tid >> 3, xt = (tid & 7) * 4;
    const float* xp = Xn + (size_t)xk * TD + xt;

    float wr[8];
    float4 xr[4];
    wr[0] = wp0[0]; wr[1] = wp0[8 * (size_t)Cin];
    wr[2] = wp0[4]; wr[3] = wp0[8 * (size_t)Cin + 4];
    wr[4] = wp1[0]; wr[5] = wp1[8 * (size_t)Cin];
    wr[6] = wp1[4]; wr[7] = wp1[8 * (size_t)Cin + 4];
#pragma unroll
    for (int u = 0; u < 4; u++) xr[u] = *(const float4*)(xp + 32 * u);

#define STORE_TILE()                                                          \
    do {                                                                      \
        uint4 s0, s1;                                                         \
        s0.x = f2tf32(wr[0]); s0.y = f2tf32(wr[1]);                           \
        s0.z = f2tf32(wr[2]); s0.w = f2tf32(wr[3]);                           \
        s1.x = f2tf32(wr[4]); s1.y = f2tf32(wr[5]);                           \
        s1.z = f2tf32(wr[6]); s1.w = f2tf32(wr[7]);                           \
        *(uint4*)&Wf[(f0 * 128) + sl * 4]       = s0;                         \
        *(uint4*)&Wf[((f0 + 8) * 128) + sl * 4] = s1;                         \
        _Pragma("unroll")                                                     \
        for (int u = 0; u < 4; u++) {                                         \
            uint4 xx;                                                         \
            xx.x = f2tf32(xr[u].x); xx.y = f2tf32(xr[u].y);                   \
            xx.z = f2tf32(xr[u].z); xx.w = f2tf32(xr[u].w);                   \
            *(uint4*)&Xs[xk * XS_STR + xt + 32 * u] = xx;                     \
        }                                                                     \
    } while (0)

    STORE_TILE();
    __syncthreads();

    float acc[2][4][4];
#pragma unroll
    for (int m = 0; m < 2; m++)
#pragma unroll
        for (int nf = 0; nf < 4; nf++)
#pragma unroll
            for (int j = 0; j < 4; j++) acc[m][nf][j] = 0.f;

    int cidx = warp_t * 32 + g;   // base t index for B-fragments
    int nchunks = Cin >> 5;
    for (int c = 0; c < nchunks; c++) {
        if (c + 1 < nchunks) {
            wp0 += 32; wp1 += 32;
            xp += 32 * TD;
            wr[0] = wp0[0]; wr[1] = wp0[8 * (size_t)Cin];
            wr[2] = wp0[4]; wr[3] = wp0[8 * (size_t)Cin + 4];
            wr[4] = wp1[0]; wr[5] = wp1[8 * (size_t)Cin];
            wr[6] = wp1[4]; wr[7] = wp1[8 * (size_t)Cin + 4];
#pragma unroll
            for (int u = 0; u < 4; u++) xr[u] = *(const float4*)(xp + 32 * u);
        }

#pragma unroll
        for (int kt = 0; kt < 4; kt++) {
            int ks = kt * 8;
            uint32_t a[2][4], b[4][2];
#pragma unroll
            for (int m = 0; m < 2; m++) {
                *(uint4*)a[m] =
                    *(const uint4*)&Wf[((warp_o * 2 + m) * 4 + kt) * 128 + lane * 4];
            }
            const uint32_t* xrow0 = &Xs[(ks + q) * XS_STR + cidx];
            const uint32_t* xrow1 = xrow0 + 4 * XS_STR;
#pragma unroll
            for (int nf = 0; nf < 4; nf++) {
                b[nf][0] = xrow0[nf * 8];
                b[nf][1] = xrow1[nf * 8];
            }
#pragma unroll
            for (int m = 0; m < 2; m++)
#pragma unroll
                for (int nf = 0; nf < 4; nf++)
                    MMA_TF32(acc[m][nf], a[m], b[nf]);
        }

        if (c + 1 < nchunks) {
            __syncthreads();   // everyone done reading current tile
            STORE_TILE();
            __syncthreads();   // new tile visible
        }
    }
#undef STORE_TILE

    // epilogue: c0,c1 at (row g, cols 2q,2q+1); c2,c3 at (row g+8)
#pragma unroll
    for (int m = 0; m < 2; m++) {
        int obase = o0 + warp_o * 32 + m * 16 + g;
#pragma unroll
        for (int r = 0; r < 2; r++) {
            int o = obase + r * 8;
            float bs = bias[o];
            float* yrow = Y + ((size_t)n * O + o) * TD;
            const float* rrow = (EPI == 2) ? (Res + ((size_t)n * O + o) * TD) : nullptr;
#pragma unroll
            for (int nf = 0; nf < 4; nf++) {
                int t = warp_t * 32 + nf * 8 + q * 2;
                float v0 = acc[m][nf][r * 2 + 0] + bs;
                float v1 = acc[m][nf][r * 2 + 1] + bs;
                if (EPI == 1) { v0 = fmaxf(v0, 0.f); v1 = fmaxf(v1, 0.f); }
                if (EPI == 2) {
                    float2 rr = *(const float2*)(rrow + t);
                    v0 += rr.x; v1 += rr.y;
                }
                *(float2*)(yrow + t) = make_float2(v0, v1);
            }
        }
    }
}

// ---------------------------------------------------------------------------
// Small GEMM over [N, Cin] tokens (relay path, fp32): Y[n,o] = W[o,:]*X[n,:]+b
// grid (O/64, ceil(N/32)), block 256
// ---------------------------------------------------------------------------
template <int EPI>
__global__ __launch_bounds__(256)
void gemm_nc(const float* __restrict__ W, const float* __restrict__ bias,
             const float* __restrict__ X, float* __restrict__ Y,
             const float* __restrict__ Res, int O, int Cin)
{
    int o0 = blockIdx.x * 64;
    int n0 = blockIdx.y * 32;
    int tid = threadIdx.x;
    int tx = tid & 31, ty = tid >> 5;

    __shared__ float Ws[32][64];
    __shared__ float Xs[32][33];

    float acc[8];
#pragma unroll
    for (int i = 0; i < 8; i++) acc[i] = 0.f;

    for (int k0 = 0; k0 < Cin; k0 += 32) {
#pragma unroll
        for (int r = 0; r < 2; r++) {
            int idx = tid + 256 * r;
            int o = idx >> 3, kq = idx & 7;
            float4 w4 = *(const float4*)(W + (size_t)(o0 + o) * Cin + k0 + kq * 4);
            Ws[kq * 4 + 0][o] = w4.x;
            Ws[kq * 4 + 1][o] = w4.y;
            Ws[kq * 4 + 2][o] = w4.z;
            Ws[kq * 4 + 3][o] = w4.w;
        }
        {
            int nn = tid >> 3, kq = tid & 7;
            int n = n0 + nn;
            float4 x4 = make_float4(0.f, 0.f, 0.f, 0.f);
            if (n < NTOK) x4 = *(const float4*)(X + (size_t)n * Cin + k0 + kq * 4);
            Xs[kq * 4 + 0][nn] = x4.x;
            Xs[kq * 4 + 1][nn] = x4.y;
            Xs[kq * 4 + 2][nn] = x4.z;
            Xs[kq * 4 + 3][nn] = x4.w;
        }
        __syncthreads();
#pragma unroll
        for (int kk = 0; kk < 32; kk++) {
            float bv = Xs[kk][tx];
#pragma unroll
            for (int i = 0; i < 8; i++) acc[i] += Ws[kk][ty * 8 + i] * bv;
        }
        __syncthreads();
    }

    int n = n0 + tx;
    if (n < NTOK) {
#pragma unroll
        for (int i = 0; i < 8; i++) {
            int o = o0 + ty * 8 + i;
            float val = acc[i] + bias[o];
            if (EPI == 1) val = fmaxf(val, 0.f);
            if (EPI == 2) val += Res[(size_t)n * O + o];
            Y[(size_t)n * O + o] = val;
        }
    }
}

// ---------------------------------------------------------------------------
// tju attention (window-3 + emb token + relay token), fused residual add.
// grid NTOK*NHH, block 128 (one thread per t)
// ---------------------------------------------------------------------------
__global__ void attn_tju(const float* __restrict__ q, const float* __restrict__ k,
                         const float* __restrict__ v, const float* __restrict__ ke,
                         const float* __restrict__ ve, const float* __restrict__ kr,
                         const float* __restrict__ vr, const float* __restrict__ xln,
                         float* __restrict__ sout)
{
    int nh = blockIdx.x;
    int n = nh >> 3, h = nh & 7;
    int t = threadIdx.x;
    int rbase = n * CD + h * DKK;
    size_t base = (size_t)rbase * TD;

    float l0 = 0.f, l1 = 0.f, l2 = 0.f, l3 = 0.f, l4 = 0.f;
#pragma unroll 8
    for (int d = 0; d < DKK; d++) {
        size_t off = base + (size_t)d * TD + t;
        float qd = q[off];
        float kc = k[off];
        float km = (t > 0) ? k[off - 1] : 0.f;
        float kp = (t < TD - 1) ? k[off + 1] : 0.f;
        l0 += qd * km;
        l1 += qd * kc;
        l2 += qd * kp;
        l3 += qd * ke[off];
        l4 += qd * kr[rbase + d];
    }
    const float sc = 0.17677669529663687f; // 1/sqrt(32)
    l0 *= sc; l1 *= sc; l2 *= sc; l3 *= sc; l4 *= sc;
    float m = fmaxf(fmaxf(fmaxf(l0, l1), fmaxf(l2, l3)), l4);
    float e0 = expf(l0 - m), e1 = expf(l1 - m), e2 = expf(l2 - m);
    float e3 = expf(l3 - m), e4 = expf(l4 - m);
    float rs = 1.f / (e0 + e1 + e2 + e3 + e4);
    float a0 = e0 * rs, a1 = e1 * rs, a2 = e2 * rs, a3 = e3 * rs, a4 = e4 * rs;

#pragma unroll 8
    for (int d = 0; d < DKK; d++) {
        size_t off = base + (size_t)d * TD + t;
        float vc = v[off];
        float vm = (t > 0) ? v[off - 1] : 0.f;
        float vp = (t < TD - 1) ? v[off + 1] : 0.f;
        float att = a0 * vm + a1 * vc + a2 * vp + a3 * ve[off] + a4 * vr[rbase + d];
        sout[off] = xln[off] + att;
    }
}

// ---------------------------------------------------------------------------
// tru attention (relay over 129 tokens). block 256 = 8 warps, grid 200.
// ---------------------------------------------------------------------------
__global__ void attn_tru(const float* __restrict__ qtr, const float* __restrict__ ktr,
                         const float* __restrict__ vtr, const float* __restrict__ ktrr,
                         const float* __restrict__ vtrr, const float* __restrict__ relay,
                         float* __restrict__ z)
{
    __shared__ float sq[8][DKK];
    __shared__ float slog[8][132];
    int wid = threadIdx.x >> 5, lane = threadIdx.x & 31;
    int nh = blockIdx.x * 8 + wid;
    int n = nh >> 3, h = nh & 7;
    int rbase = n * CD + h * DKK;
    size_t base = (size_t)rbase * TD;
    const float sc = 0.17677669529663687f;

    sq[wid][lane] = qtr[rbase + lane];
    __syncwarp();

    float lg[5];
#pragma unroll
    for (int j = 0; j < 5; j++) {
        int l = lane + 32 * j;
        float acc = -1e30f;
        if (l < 129) {
            acc = 0.f;
            if (l == 0) {
#pragma unroll 8
                for (int d = 0; d < DKK; d++) acc += sq[wid][d] * ktrr[rbase + d];
            } else {
                int t = l - 1;
#pragma unroll 8
                for (int d = 0; d < DKK; d++) acc += sq[wid][d] * ktr[base + (size_t)d * TD + t];
            }
            acc *= sc;
        }
        lg[j] = acc;
    }
    float m = -1e30f;
#pragma unroll
    for (int j = 0; j < 5; j++) m = fmaxf(m, lg[j]);
#pragma unroll
    for (int o = 16; o > 0; o >>= 1) m = fmaxf(m, __shfl_xor_sync(0xffffffffu, m, o));
    float es = 0.f;
#pragma unroll
    for (int j = 0; j < 5; j++) {
        int l = lane + 32 * j;
        if (l < 129) {
            float e = expf(lg[j] - m);
            slog[wid][l] = e;
            es += e;
        }
    }
#pragma unroll
    for (int o = 16; o > 0; o >>= 1) es += __shfl_xor_sync(0xffffffffu, es, o);
    __syncwarp();
    float rinv = 1.f / es;

    int d = lane;
    float att = slog[wid][0] * vtrr[rbase + d];
    const float* vp = vtr + base + (size_t)d * TD;
#pragma unroll 16
    for (int t = 0; t < TD; t++) att += slog[wid][1 + t] * vp[t];
    att *= rinv;
    z[rbase + d] = relay[rbase + d] + att;
}

// ---------------------------------------------------------------------------
// BN stats over (n,t) per channel. grid 256, block 256.
// ---------------------------------------------------------------------------
__global__ void bn_stats_nct(const float* __restrict__ X, float* __restrict__ mean,
                             float* __restrict__ inv, float eps)
{
    int c = blockIdx.x, tid = threadIdx.x;
    float s1 = 0.f, s2 = 0.f;
    for (int i = tid; i < NTOK * TD; i += 256) {
        int n = i >> 7, t = i & 127;
        float x = X[((size_t)n * CD + c) * TD + t];
        s1 += x;
        s2 += x * x;
    }
    __shared__ double d1[256], d2[256];
    d1[tid] = s1; d2[tid] = s2;
    __syncthreads();
    for (int s = 128; s > 0; s >>= 1) {
        if (tid < s) { d1[tid] += d1[tid + s]; d2[tid] += d2[tid + s]; }
        __syncthreads();
    }
    if (tid == 0) {
        double mm = d1[0] / (NTOK * TD);
        double var = d2[0] / (NTOK * TD) - mm * mm;
        mean[c] = (float)mm;
        inv[c] = rsqrtf((float)var + eps);
    }
}

// BN stats over n per channel ([N,C] input). grid 256, block 256.
__global__ void bn_stats_nc(const float* __restrict__ X, float* __restrict__ mean,
                            float* __restrict__ inv, float eps)
{
    int c = blockIdx.x, tid = threadIdx.x;
    float s1 = 0.f, s2 = 0.f;
    for (int n = tid; n < NTOK; n += 256) {
        float x = X[(size_t)n * CD + c];
        s1 += x;
        s2 += x * x;
    }
    __shared__ double d1[256], d2[256];
    d1[tid] = s1; d2[tid] = s2;
    __syncthreads();
    for (int s = 128; s > 0; s >>= 1) {
        if (tid < s) { d1[tid] += d1[tid + s]; d2[tid] += d2[tid + s]; }
        __syncthreads();
    }
    if (tid == 0) {
        double mm = d1[0] / NTOK;
        double var = d2[0] / NTOK - mm * mm;
        mean[c] = (float)mm;
        inv[c] = rsqrtf((float)var + eps);
    }
}

// apply BN affine (+ optional leaky relu) on [N,C,T]
__global__ void affine_nct(const float* __restrict__ X, const float* __restrict__ mean,
                           const float* __restrict__ inv, const float* __restrict__ g,
                           const float* __restrict__ b, float* __restrict__ Y, int leaky)
{
    int idx = blockIdx.x * 256 + threadIdx.x;
    if (idx >= NCT) return;
    int c = (idx >> 7) & 255;
    float vv = (X[idx] - mean[c]) * inv[c] * g[c] + b[c];
    if (leaky && vv < 0.f) vv *= 0.01f;
    Y[idx] = vv;
}

// apply BN affine (+ optional leaky relu) on [N,C]
__global__ void affine_nc(const float* __restrict__ X, const float* __restrict__ mean,
                          const float* __restrict__ inv, const float* __restrict__ g,
                          const float* __restrict__ b, float* __restrict__ Y, int leaky)
{
    int idx = blockIdx.x * 256 + threadIdx.x;
    if (idx >= NC) return;
    int c = idx & 255;
    float vv = (X[idx] - mean[c]) * inv[c] * g[c] + b[c];
    if (leaky && vv < 0.f) vv *= 0.01f;
    Y[idx] = vv;
}

// ---------------------------------------------------------------------------
extern "C" void kernel_launch(void* const* d_in, const int* in_sizes, int n_in,
                              void* d_out, int out_size)
{
    (void)in_sizes; (void)n_in; (void)out_size;
    const float* data    = (const float*)d_in[0];
    const float* ln_g    = (const float*)d_in[1];
    const float* ln_b    = (const float*)d_in[2];
    const float* tj_wq   = (const float*)d_in[3];
    const float* tj_bq   = (const float*)d_in[4];
    const float* tj_wk   = (const float*)d_in[5];
    const float* tj_bk   = (const float*)d_in[6];
    const float* tj_wv   = (const float*)d_in[7];
    const float* tj_bv   = (const float*)d_in[8];
    const float* tj_bng  = (const float*)d_in[9];
    const float* tj_bnb  = (const float*)d_in[10];
    const float* tj_w1   = (const float*)d_in[11];
    const float* tj_b1   = (const float*)d_in[12];
    const float* tj_w2   = (const float*)d_in[13];
    const float* tj_b2   = (const float*)d_in[14];
    const float* tj_fg   = (const float*)d_in[15];
    const float* tj_fb   = (const float*)d_in[16];
    const float* tr_wq   = (const float*)d_in[17];
    const float* tr_bq   = (const float*)d_in[18];
    const float* tr_wk   = (const float*)d_in[19];
    const float* tr_bk   = (const float*)d_in[20];
    const float* tr_wv   = (const float*)d_in[21];
    const float* tr_bv   = (const float*)d_in[22];
    const float* tr_bng  = (const float*)d_in[23];
    const float* tr_bnb  = (const float*)d_in[24];
    const float* tr_w1   = (const float*)d_in[25];
    const float* tr_b1   = (const float*)d_in[26];
    const float* tr_w2   = (const float*)d_in[27];
    const float* tr_b2   = (const float*)d_in[28];
    const float* tr_fg   = (const float*)d_in[29];
    const float* tr_fb   = (const float*)d_in[30];

    float* buf = nullptr;
    cudaGetSymbolAddress((void**)&buf, g_buf);

    float* embs  = buf + OFF_EMBS;
    float* nodes = buf + OFF_NODES;
    float* xln   = buf + OFF_XLN;
    float* qb    = buf + OFF_Q;
    float* kb    = buf + OFF_K;
    float* vb    = buf + OFF_V;
    float* keb   = buf + OFF_KE;
    float* veb   = buf + OFF_VE;
    float* sb    = buf + OFF_S;
    float* retb  = buf + OFF_RET;
    float* ob    = buf + OFF_O;
    float* ktrb  = buf + OFF_KTR;
    float* vtrb  = buf + OFF_VTR;
    float* hb    = buf + OFF_H;
    float* relay = buf + OFF_RELAY;
    float* krb   = buf + OFF_KR;
    float* vrb   = buf + OFF_VR;
    float* qtrb  = buf + OFF_QTR;
    float* ktrr  = buf + OFF_KTRR;
    float* vtrr  = buf + OFF_VTRR;
    float* zb    = buf + OFF_Z;
    float* rettb = buf + OFF_RETT;
    float* otrb  = buf + OFF_OTR;
    float* htrb  = buf + OFF_HTR;
    float* meanb = buf + OFF_MEAN;
    float* invb  = buf + OFF_INV;

    prep_kernel<<<dim3(NTOK, 32), dim3(32, 8)>>>(data, embs, relay);

    const dim3 g_o4(4, NTOK), g_o16(16, NTOK);
    const dim3 gnc4(4, 7), gnc16(16, 7);

    for (int i = 0; i < ITER; i++) {
        const float* nodes_in = (i == 0) ? embs : nodes;
        // LayerNorm over channels
        ln_kernel<<<dim3(NTOK, 4), dim3(32, 8)>>>(nodes_in, ln_g + i * CD, ln_b + i * CD, xln);

        const float* wq = tj_wq + (size_t)i * CD * CD;
        const float* wk = tj_wk + (size_t)i * CD * CD;
        const float* wv = tj_wv + (size_t)i * CD * CD;
        const float* bq = tj_bq + i * CD;
        const float* bk = tj_bk + i * CD;
        const float* bv = tj_bv + i * CD;

        gemm_tf32<0><<<g_o4, 256>>>(wq, bq, xln, qb, nullptr, CD, CD);
        gemm_tf32<0><<<g_o4, 256>>>(wk, bk, xln, kb, nullptr, CD, CD);
        gemm_tf32<0><<<g_o4, 256>>>(wv, bv, xln, vb, nullptr, CD, CD);
        gemm_tf32<0><<<g_o4, 256>>>(wk, bk, embs, keb, nullptr, CD, CD);
        gemm_tf32<0><<<g_o4, 256>>>(wv, bv, embs, veb, nullptr, CD, CD);
        gemm_nc<0><<<gnc4, 256>>>(wk, bk, relay, krb, nullptr, CD, CD);
        gemm_nc<0><<<gnc4, 256>>>(wv, bv, relay, vrb, nullptr, CD, CD);

        attn_tju<<<NTOK * NHH, 128>>>(qb, kb, vb, keb, veb, krb, vrb, xln, sb);

        bn_stats_nct<<<256, 256>>>(sb, meanb, invb, 1e-5f);
        affine_nct<<<NCT / 256, 256>>>(sb, meanb, invb, tj_bng + i * CD, tj_bnb + i * CD, retb, 0);

        gemm_tf32<1><<<g_o16, 256>>>(tj_w1 + (size_t)i * DFFD * CD, tj_b1 + i * DFFD,
                                     retb, hb, nullptr, DFFD, CD);
        gemm_tf32<2><<<g_o4, 256>>>(tj_w2 + (size_t)i * CD * DFFD, tj_b2 + i * CD,
                                    hb, ob, retb, CD, DFFD);

        bn_stats_nct<<<256, 256>>>(ob, meanb, invb, 1e-5f);
        float* nodes_out = (i == ITER - 1) ? (float*)d_out : nodes;
        affine_nct<<<NCT / 256, 256>>>(ob, meanb, invb, tj_fg + i * CD, tj_fb + i * CD,
                                       nodes_out, 1);

        if (i < ITER - 1) {
            const float* rwq = tr_wq + (size_t)i * CD * CD;
            const float* rwk = tr_wk + (size_t)i * CD * CD;
            const float* rwv = tr_wv + (size_t)i * CD * CD;
            const float* rbq = tr_bq + i * CD;
            const float* rbk = tr_bk + i * CD;
            const float* rbv = tr_bv + i * CD;

            gemm_nc<0><<<gnc4, 256>>>(rwq, rbq, relay, qtrb, nullptr, CD, CD);
            gemm_tf32<0><<<g_o4, 256>>>(rwk, rbk, nodes, ktrb, nullptr, CD, CD);
            gemm_tf32<0><<<g_o4, 256>>>(rwv, rbv, nodes, vtrb, nullptr, CD, CD);
            gemm_nc<0><<<gnc4, 256>>>(rwk, rbk, relay, ktrr, nullptr, CD, CD);
            gemm_nc<0><<<gnc4, 256>>>(rwv, rbv, relay, vtrr, nullptr, CD, CD);

            attn_tru<<<NTOK, 256>>>(qtrb, ktrb, vtrb, ktrr, vtrr, relay, zb);

            bn_stats_nc<<<256, 256>>>(zb, meanb, invb, 1e-5f);
            affine_nc<<<NC / 256, 256>>>(zb, meanb, invb, tr_bng + i * CD, tr_bnb + i * CD,
                                         rettb, 0);

            gemm_nc<1><<<gnc16, 256>>>(tr_w1 + (size_t)i * DFFD * CD, tr_b1 + i * DFFD,
                                       rettb, htrb, nullptr, DFFD, CD);
            gemm_nc<2><<<gnc4, 256>>>(tr_w2 + (size_t)i * CD * DFFD, tr_b2 + i * CD,
                                      htrb, otrb, rettb, CD, DFFD);

            bn_stats_nc<<<256, 256>>>(otrb, meanb, invb, 1e-5f);
            affine_nc<<<NC / 256, 256>>>(otrb, meanb, invb, tr_fg + i * CD, tr_fb + i * CD,
                                         relay, 1);
        }
    }
}

// round 7
// speedup vs baseline: 1.8194x; 1.0841x over previous
#include <cuda_runtime.h>
#include <math.h>
#include <stdint.h>

#define NTOK 200
#define CD   256
#define TD   128
#define NHH  8
#define DKK  32
#define DFFD 1024
#define ITER 4
#define NCT  (NTOK*CD*TD)
#define NC   (NTOK*CD)

#define OFF_EMBS   0
#define OFF_NODES  (1*NCT)
#define OFF_XLN    (2*NCT)
#define OFF_Q      (3*NCT)
#define OFF_K      (4*NCT)
#define OFF_V      (5*NCT)
#define OFF_KE     (6*NCT)
#define OFF_VE     (7*NCT)
#define OFF_S      (8*NCT)
#define OFF_RET    (9*NCT)
#define OFF_O      (10*NCT)
#define OFF_KTR    (11*NCT)
#define OFF_VTR    (12*NCT)
#define OFF_H      (13*NCT)            /* N*DFF*T = 4*NCT */
#define OFF_RELAY  (17*NCT)
#define OFF_KR     (OFF_RELAY+NC)
#define OFF_VR     (OFF_KR+NC)
#define OFF_QTR    (OFF_VR+NC)
#define OFF_KTRR   (OFF_QTR+NC)
#define OFF_VTRR   (OFF_KTRR+NC)
#define OFF_Z      (OFF_VTRR+NC)
#define OFF_RETT   (OFF_Z+NC)
#define OFF_OTR    (OFF_RETT+NC)
#define OFF_HTR    (OFF_OTR+NC)
#define OFF_MEAN   (OFF_HTR+NTOK*DFFD)
#define OFF_INV    (OFF_MEAN+256)
#define BUF_TOTAL  (OFF_INV+256)

__device__ __align__(16) float g_buf[BUF_TOTAL];

__device__ __forceinline__ uint32_t f2tf32(float x) {
    uint32_t r;
    asm("cvt.rna.tf32.f32 %0, %1;" : "=r"(r) : "f"(x));
    return r;
}

#define MMA_TF32(C, A, B)                                                     \
    asm volatile("mma.sync.aligned.m16n8k8.row.col.f32.tf32.tf32.f32 "        \
                 "{%0,%1,%2,%3}, {%4,%5,%6,%7}, {%8,%9}, {%0,%1,%2,%3};\n"    \
                 : "+f"((C)[0]), "+f"((C)[1]), "+f"((C)[2]), "+f"((C)[3])     \
                 : "r"((A)[0]), "r"((A)[1]), "r"((A)[2]), "r"((A)[3]),        \
                   "r"((B)[0]), "r"((B)[1]));

// ---------------------------------------------------------------------------
// prep: embs[n,c,t] = data[b,c,v,t] (n=b*25+v), relay[n,c] = mean_t embs
// ---------------------------------------------------------------------------
__global__ void prep_kernel(const float* __restrict__ data,
                            float* __restrict__ embs, float* __restrict__ relay)
{
    int n = blockIdx.x;
    int b = n / 25, v = n % 25;
    int c = blockIdx.y * 8 + threadIdx.y;
    int tx = threadIdx.x;
    const float* src = data + (((size_t)b * CD + c) * 25 + v) * TD;
    float* dst = embs + ((size_t)n * CD + c) * TD;
    float s = 0.f;
#pragma unroll
    for (int j = 0; j < 4; j++) {
        int t = tx + 32 * j;
        float x = src[t];
        dst[t] = x;
        s += x;
    }
#pragma unroll
    for (int o = 16; o > 0; o >>= 1) s += __shfl_xor_sync(0xffffffffu, s, o);
    if (tx == 0) relay[n * CD + c] = s * (1.0f / 128.0f);
}

// ---------------------------------------------------------------------------
// LayerNorm over channel dim. grid (NTOK, 4), block (32,8)
// ---------------------------------------------------------------------------
__global__ void ln_kernel(const float* __restrict__ X, const float* __restrict__ g,
                          const float* __restrict__ b, float* __restrict__ Y)
{
    int n = blockIdx.x;
    int t = blockIdx.y * 32 + threadIdx.x;
    int tx = threadIdx.x, ty = threadIdx.y;
    float x[32];
    float s1 = 0.f, s2 = 0.f;
#pragma unroll
    for (int j = 0; j < 32; j++) {
        int c = ty + j * 8;
        x[j] = X[((size_t)n * CD + c) * TD + t];
        s1 += x[j];
        s2 += x[j] * x[j];
    }
    __shared__ float sm1[8][32], sm2[8][32], smean[32], sinv[32];
    sm1[ty][tx] = s1; sm2[ty][tx] = s2;
    __syncthreads();
    if (ty == 0) {
        float a = 0.f, bb = 0.f;
#pragma unroll
        for (int qy = 0; qy < 8; qy++) { a += sm1[qy][tx]; bb += sm2[qy][tx]; }
        float m = a * (1.0f / 256.0f);
        float var = bb * (1.0f / 256.0f) - m * m;
        smean[tx] = m;
        sinv[tx] = rsqrtf(var + 1e-6f);
    }
    __syncthreads();
    float m = smean[tx], inv = sinv[tx];
#pragma unroll
    for (int j = 0; j < 32; j++) {
        int c = ty + j * 8;
        Y[((size_t)n * CD + c) * TD + t] = (x[j] - m) * inv * g[c] + b[c];
    }
}

// ---------------------------------------------------------------------------
// TF32 tensor-core GEMM: Y[n,o,t] = sum_c W[o,c]*X[n,c,t] + bias[o]
// T fixed = 128. Block tile: 128 (o) x 128 (t), K-chunk 32, DOUBLE-BUFFERED.
// 8 warps: warp_o in {0,1} (64 o each), warp_t in {0..3} (32 t each).
// Warp tile 64x32: acc[m=4][nf=4][4].
// Smem per buffer (uint32 units):
//   Wf[32 frags][128]  frag f = mt*4+kt (mt=0..7 over 128 o, kt=0..3 over k32)
//                      -> A-frag = one LDS.128, conflict-free
//   Xs[32][132]        natural [k][t]; 132 mod 32 = 4 -> b-frag bank 4q+g bijective
// One __syncthreads per chunk; staging stores overlap MMA of current chunk.
// EPI: 0 = bias only, 1 = relu, 2 = +Res
// grid (O/128, NTOK), block 256, dynamic smem 66560 B
// ---------------------------------------------------------------------------
#define XS_STR   132
#define WF_U32   (32 * 128)                 /* 4096  */
#define BUFU     (WF_U32 + 32 * XS_STR)     /* 8320  */
#define GEMM_SMEM (2 * BUFU * 4)            /* 66560 */

template <int EPI>
__global__ __launch_bounds__(256)
void gemm_tf32(const float* __restrict__ W, const float* __restrict__ bias,
               const float* __restrict__ X, float* __restrict__ Y,
               const float* __restrict__ Res, int O, int Cin)
{
    extern __shared__ __align__(16) uint32_t smem_dyn[];

    int n = blockIdx.y;
    int o0 = blockIdx.x * 128;
    const float* Xn = X + (size_t)n * Cin * TD;
    int tid = threadIdx.x;
    int lane = tid & 31, wid = tid >> 5;
    int warp_o = wid >> 2, warp_t = wid & 3;
    int g = lane >> 2, q = lane & 3;

    // ---- staging assignments ----
    // W: 4 frag-lanes per thread: f in {f0, f0+8, f0+16, f0+24}, lane sl.
    int f0 = tid >> 5, sl = tid & 31;
    int slg = sl >> 2, slq = sl & 3;
    // X: row xk, 4 float4 at t = xt + 32u
    int xk = tid >> 3, xt = (tid & 7) * 4;

    const float* wptr[4];
#pragma unroll
    for (int j = 0; j < 4; j++) {
        int f = f0 + 8 * j;
        int mt = f >> 2, kt = f & 3;
        wptr[j] = W + (size_t)(o0 + mt * 16 + slg) * Cin + kt * 8 + slq;
    }
    const float* xp = Xn + (size_t)xk * TD + xt;
    size_t wstep8 = 8 * (size_t)Cin;

    float wr[4][4];
    float4 xr[4];

#define LOAD_REGS()                                                           \
    do {                                                                      \
        _Pragma("unroll")                                                     \
        for (int j = 0; j < 4; j++) {                                         \
            wr[j][0] = wptr[j][0];                                            \
            wr[j][1] = wptr[j][wstep8];                                       \
            wr[j][2] = wptr[j][4];                                            \
            wr[j][3] = wptr[j][wstep8 + 4];                                   \
        }                                                                     \
        _Pragma("unroll")                                                     \
        for (int u = 0; u < 4; u++) xr[u] = *(const float4*)(xp + 32 * u);    \
    } while (0)

#define STORE_TILE(BUF)                                                       \
    do {                                                                      \
        uint32_t* Wb = smem_dyn + (BUF) * BUFU;                               \
        uint32_t* Xb = Wb + WF_U32;                                           \
        _Pragma("unroll")                                                     \
        for (int j = 0; j < 4; j++) {                                         \
            uint4 s;                                                          \
            s.x = f2tf32(wr[j][0]); s.y = f2tf32(wr[j][1]);                   \
            s.z = f2tf32(wr[j][2]); s.w = f2tf32(wr[j][3]);                   \
            *(uint4*)&Wb[(f0 + 8 * j) * 128 + sl * 4] = s;                    \
        }                                                                     \
        _Pragma("unroll")                                                     \
        for (int u = 0; u < 4; u++) {                                         \
            uint4 xx;                                                         \
            xx.x = f2tf32(xr[u].x); xx.y = f2tf32(xr[u].y);                   \
            xx.z = f2tf32(xr[u].z); xx.w = f2tf32(xr[u].w);                   \
            *(uint4*)&Xb[xk * XS_STR + xt + 32 * u] = xx;                     \
        }                                                                     \
    } while (0)

    LOAD_REGS();
    STORE_TILE(0);
    __syncthreads();

    float acc[4][4][4];
#pragma unroll
    for (int m = 0; m < 4; m++)
#pragma unroll
        for (int nf = 0; nf < 4; nf++)
#pragma unroll
            for (int j = 0; j < 4; j++) acc[m][nf][j] = 0.f;

    int cidx = warp_t * 32 + g;   // base t for B-fragments
    int nchunks = Cin >> 5;
    for (int c = 0; c < nchunks; c++) {
        int cur = c & 1;
        if (c + 1 < nchunks) {
#pragma unroll
            for (int j = 0; j < 4; j++) wptr[j] += 32;
            xp += 32 * TD;
            LOAD_REGS();
        }

        const uint32_t* Wb = smem_dyn + cur * BUFU;
        const uint32_t* Xb = Wb + WF_U32;
#pragma unroll
        for (int kt = 0; kt < 4; kt++) {
            uint32_t a[4][4], b[4][2];
#pragma unroll
            for (int m = 0; m < 4; m++) {
                int f = (warp_o * 4 + m) * 4 + kt;
                *(uint4*)a[m] = *(const uint4*)&Wb[f * 128 + lane * 4];
            }
            const uint32_t* xrow0 = &Xb[(kt * 8 + q) * XS_STR + cidx];
            const uint32_t* xrow1 = xrow0 + 4 * XS_STR;
#pragma unroll
            for (int nf = 0; nf < 4; nf++) {
                b[nf][0] = xrow0[nf * 8];
                b[nf][1] = xrow1[nf * 8];
            }
#pragma unroll
            for (int m = 0; m < 4; m++)
#pragma unroll
                for (int nf = 0; nf < 4; nf++)
                    MMA_TF32(acc[m][nf], a[m], b[nf]);
        }

        if (c + 1 < nchunks) {
            STORE_TILE(1 - cur);   // other buffer: no conflict with readers
            __syncthreads();
        }
    }
#undef STORE_TILE
#undef LOAD_REGS

    // epilogue: c0,c1 at (row g, cols 2q,2q+1); c2,c3 at (row g+8)
#pragma unroll
    for (int m = 0; m < 4; m++) {
        int obase = o0 + warp_o * 64 + m * 16 + g;
#pragma unroll
        for (int r = 0; r < 2; r++) {
            int o = obase + r * 8;
            float bs = bias[o];
            float* yrow = Y + ((size_t)n * O + o) * TD;
            const float* rrow = (EPI == 2) ? (Res + ((size_t)n * O + o) * TD) : nullptr;
#pragma unroll
            for (int nf = 0; nf < 4; nf++) {
                int t = warp_t * 32 + nf * 8 + q * 2;
                float v0 = acc[m][nf][r * 2 + 0] + bs;
                float v1 = acc[m][nf][r * 2 + 1] + bs;
                if (EPI == 1) { v0 = fmaxf(v0, 0.f); v1 = fmaxf(v1, 0.f); }
                if (EPI == 2) {
                    float2 rr = *(const float2*)(rrow + t);
                    v0 += rr.x; v1 += rr.y;
                }
                *(float2*)(yrow + t) = make_float2(v0, v1);
            }
        }
    }
}

// ---------------------------------------------------------------------------
// Small GEMM over [N, Cin] tokens (relay path, fp32): Y[n,o] = W[o,:]*X[n,:]+b
// grid (O/64, ceil(N/32)), block 256
// ---------------------------------------------------------------------------
template <int EPI>
__global__ __launch_bounds__(256)
void gemm_nc(const float* __restrict__ W, const float* __restrict__ bias,
             const float* __restrict__ X, float* __restrict__ Y,
             const float* __restrict__ Res, int O, int Cin)
{
    int o0 = blockIdx.x * 64;
    int n0 = blockIdx.y * 32;
    int tid = threadIdx.x;
    int tx = tid & 31, ty = tid >> 5;

    __shared__ float Ws[32][64];
    __shared__ float Xs[32][33];

    float acc[8];
#pragma unroll
    for (int i = 0; i < 8; i++) acc[i] = 0.f;

    for (int k0 = 0; k0 < Cin; k0 += 32) {
#pragma unroll
        for (int r = 0; r < 2; r++) {
            int idx = tid + 256 * r;
            int o = idx >> 3, kq = idx & 7;
            float4 w4 = *(const float4*)(W + (size_t)(o0 + o) * Cin + k0 + kq * 4);
            Ws[kq * 4 + 0][o] = w4.x;
            Ws[kq * 4 + 1][o] = w4.y;
            Ws[kq * 4 + 2][o] = w4.z;
            Ws[kq * 4 + 3][o] = w4.w;
        }
        {
            int nn = tid >> 3, kq = tid & 7;
            int n = n0 + nn;
            float4 x4 = make_float4(0.f, 0.f, 0.f, 0.f);
            if (n < NTOK) x4 = *(const float4*)(X + (size_t)n * Cin + k0 + kq * 4);
            Xs[kq * 4 + 0][nn] = x4.x;
            Xs[kq * 4 + 1][nn] = x4.y;
            Xs[kq * 4 + 2][nn] = x4.z;
            Xs[kq * 4 + 3][nn] = x4.w;
        }
        __syncthreads();
#pragma unroll
        for (int kk = 0; kk < 32; kk++) {
            float bv = Xs[kk][tx];
#pragma unroll
            for (int i = 0; i < 8; i++) acc[i] += Ws[kk][ty * 8 + i] * bv;
        }
        __syncthreads();
    }

    int n = n0 + tx;
    if (n < NTOK) {
#pragma unroll
        for (int i = 0; i < 8; i++) {
            int o = o0 + ty * 8 + i;
            float val = acc[i] + bias[o];
            if (EPI == 1) val = fmaxf(val, 0.f);
            if (EPI == 2) val += Res[(size_t)n * O + o];
            Y[(size_t)n * O + o] = val;
        }
    }
}

// ---------------------------------------------------------------------------
// tju attention (window-3 + emb token + relay token), fused residual add.
// grid NTOK*NHH, block 128 (one thread per t)
// ---------------------------------------------------------------------------
__global__ void attn_tju(const float* __restrict__ q, const float* __restrict__ k,
                         const float* __restrict__ v, const float* __restrict__ ke,
                         const float* __restrict__ ve, const float* __restrict__ kr,
                         const float* __restrict__ vr, const float* __restrict__ xln,
                         float* __restrict__ sout)
{
    int nh = blockIdx.x;
    int n = nh >> 3, h = nh & 7;
    int t = threadIdx.x;
    int rbase = n * CD + h * DKK;
    size_t base = (size_t)rbase * TD;

    float l0 = 0.f, l1 = 0.f, l2 = 0.f, l3 = 0.f, l4 = 0.f;
#pragma unroll 8
    for (int d = 0; d < DKK; d++) {
        size_t off = base + (size_t)d * TD + t;
        float qd = q[off];
        float kc = k[off];
        float km = (t > 0) ? k[off - 1] : 0.f;
        float kp = (t < TD - 1) ? k[off + 1] : 0.f;
        l0 += qd * km;
        l1 += qd * kc;
        l2 += qd * kp;
        l3 += qd * ke[off];
        l4 += qd * kr[rbase + d];
    }
    const float sc = 0.17677669529663687f; // 1/sqrt(32)
    l0 *= sc; l1 *= sc; l2 *= sc; l3 *= sc; l4 *= sc;
    float m = fmaxf(fmaxf(fmaxf(l0, l1), fmaxf(l2, l3)), l4);
    float e0 = expf(l0 - m), e1 = expf(l1 - m), e2 = expf(l2 - m);
    float e3 = expf(l3 - m), e4 = expf(l4 - m);
    float rs = 1.f / (e0 + e1 + e2 + e3 + e4);
    float a0 = e0 * rs, a1 = e1 * rs, a2 = e2 * rs, a3 = e3 * rs, a4 = e4 * rs;

#pragma unroll 8
    for (int d = 0; d < DKK; d++) {
        size_t off = base + (size_t)d * TD + t;
        float vc = v[off];
        float vm = (t > 0) ? v[off - 1] : 0.f;
        float vp = (t < TD - 1) ? v[off + 1] : 0.f;
        float att = a0 * vm + a1 * vc + a2 * vp + a3 * ve[off] + a4 * vr[rbase + d];
        sout[off] = xln[off] + att;
    }
}

// ---------------------------------------------------------------------------
// tru attention (relay over 129 tokens). block 256 = 8 warps, grid 200.
// ---------------------------------------------------------------------------
__global__ void attn_tru(const float* __restrict__ qtr, const float* __restrict__ ktr,
                         const float* __restrict__ vtr, const float* __restrict__ ktrr,
                         const float* __restrict__ vtrr, const float* __restrict__ relay,
                         float* __restrict__ z)
{
    __shared__ float sq[8][DKK];
    __shared__ float slog[8][132];
    int wid = threadIdx.x >> 5, lane = threadIdx.x & 31;
    int nh = blockIdx.x * 8 + wid;
    int n = nh >> 3, h = nh & 7;
    int rbase = n * CD + h * DKK;
    size_t base = (size_t)rbase * TD;
    const float sc = 0.17677669529663687f;

    sq[wid][lane] = qtr[rbase + lane];
    __syncwarp();

    float lg[5];
#pragma unroll
    for (int j = 0; j < 5; j++) {
        int l = lane + 32 * j;
        float acc = -1e30f;
        if (l < 129) {
            acc = 0.f;
            if (l == 0) {
#pragma unroll 8
                for (int d = 0; d < DKK; d++) acc += sq[wid][d] * ktrr[rbase + d];
            } else {
                int t = l - 1;
#pragma unroll 8
                for (int d = 0; d < DKK; d++) acc += sq[wid][d] * ktr[base + (size_t)d * TD + t];
            }
            acc *= sc;
        }
        lg[j] = acc;
    }
    float m = -1e30f;
#pragma unroll
    for (int j = 0; j < 5; j++) m = fmaxf(m, lg[j]);
#pragma unroll
    for (int o = 16; o > 0; o >>= 1) m = fmaxf(m, __shfl_xor_sync(0xffffffffu, m, o));
    float es = 0.f;
#pragma unroll
    for (int j = 0; j < 5; j++) {
        int l = lane + 32 * j;
        if (l < 129) {
            float e = expf(lg[j] - m);
            slog[wid][l] = e;
            es += e;
        }
    }
#pragma unroll
    for (int o = 16; o > 0; o >>= 1) es += __shfl_xor_sync(0xffffffffu, es, o);
    __syncwarp();
    float rinv = 1.f / es;

    int d = lane;
    float att = slog[wid][0] * vtrr[rbase + d];
    const float* vp = vtr + base + (size_t)d * TD;
#pragma unroll 16
    for (int t = 0; t < TD; t++) att += slog[wid][1 + t] * vp[t];
    att *= rinv;
    z[rbase + d] = relay[rbase + d] + att;
}

// ---------------------------------------------------------------------------
// BN stats over (n,t) per channel. grid 256, block 256.
// ---------------------------------------------------------------------------
__global__ void bn_stats_nct(const float* __restrict__ X, float* __restrict__ mean,
                             float* __restrict__ inv, float eps)
{
    int c = blockIdx.x, tid = threadIdx.x;
    float s1 = 0.f, s2 = 0.f;
    for (int i = tid; i < NTOK * TD; i += 256) {
        int n = i >> 7, t = i & 127;
        float x = X[((size_t)n * CD + c) * TD + t];
        s1 += x;
        s2 += x * x;
    }
    __shared__ double d1[256], d2[256];
    d1[tid] = s1; d2[tid] = s2;
    __syncthreads();
    for (int s = 128; s > 0; s >>= 1) {
        if (tid < s) { d1[tid] += d1[tid + s]; d2[tid] += d2[tid + s]; }
        __syncthreads();
    }
    if (tid == 0) {
        double mm = d1[0] / (NTOK * TD);
        double var = d2[0] / (NTOK * TD) - mm * mm;
        mean[c] = (float)mm;
        inv[c] = rsqrtf((float)var + eps);
    }
}

// BN stats over n per channel ([N,C] input). grid 256, block 256.
__global__ void bn_stats_nc(const float* __restrict__ X, float* __restrict__ mean,
                            float* __restrict__ inv, float eps)
{
    int c = blockIdx.x, tid = threadIdx.x;
    float s1 = 0.f, s2 = 0.f;
    for (int n = tid; n < NTOK; n += 256) {
        float x = X[(size_t)n * CD + c];
        s1 += x;
        s2 += x * x;
    }
    __shared__ double d1[256], d2[256];
    d1[tid] = s1; d2[tid] = s2;
    __syncthreads();
    for (int s = 128; s > 0; s >>= 1) {
        if (tid < s) { d1[tid] += d1[tid + s]; d2[tid] += d2[tid + s]; }
        __syncthreads();
    }
    if (tid == 0) {
        double mm = d1[0] / NTOK;
        double var = d2[0] / NTOK - mm * mm;
        mean[c] = (float)mm;
        inv[c] = rsqrtf((float)var + eps);
    }
}

// apply BN affine (+ optional leaky relu) on [N,C,T]
__global__ void affine_nct(const float* __restrict__ X, const float* __restrict__ mean,
                           const float* __restrict__ inv, const float* __restrict__ g,
                           const float* __restrict__ b, float* __restrict__ Y, int leaky)
{
    int idx = blockIdx.x * 256 + threadIdx.x;
    if (idx >= NCT) return;
    int c = (idx >> 7) & 255;
    float vv = (X[idx] - mean[c]) * inv[c] * g[c] + b[c];
    if (leaky && vv < 0.f) vv *= 0.01f;
    Y[idx] = vv;
}

// apply BN affine (+ optional leaky relu) on [N,C]
__global__ void affine_nc(const float* __restrict__ X, const float* __restrict__ mean,
                          const float* __restrict__ inv, const float* __restrict__ g,
                          const float* __restrict__ b, float* __restrict__ Y, int leaky)
{
    int idx = blockIdx.x * 256 + threadIdx.x;
    if (idx >= NC) return;
    int c = idx & 255;
    float vv = (X[idx] - mean[c]) * inv[c] * g[c] + b[c];
    if (leaky && vv < 0.f) vv *= 0.01f;
    Y[idx] = vv;
}

// ---------------------------------------------------------------------------
extern "C" void kernel_launch(void* const* d_in, const int* in_sizes, int n_in,
                              void* d_out, int out_size)
{
    (void)in_sizes; (void)n_in; (void)out_size;
    const float* data    = (const float*)d_in[0];
    const float* ln_g    = (const float*)d_in[1];
    const float* ln_b    = (const float*)d_in[2];
    const float* tj_wq   = (const float*)d_in[3];
    const float* tj_bq   = (const float*)d_in[4];
    const float* tj_wk   = (const float*)d_in[5];
    const float* tj_bk   = (const float*)d_in[6];
    const float* tj_wv   = (const float*)d_in[7];
    const float* tj_bv   = (const float*)d_in[8];
    const float* tj_bng  = (const float*)d_in[9];
    const float* tj_bnb  = (const float*)d_in[10];
    const float* tj_w1   = (const float*)d_in[11];
    const float* tj_b1   = (const float*)d_in[12];
    const float* tj_w2   = (const float*)d_in[13];
    const float* tj_b2   = (const float*)d_in[14];
    const float* tj_fg   = (const float*)d_in[15];
    const float* tj_fb   = (const float*)d_in[16];
    const float* tr_wq   = (const float*)d_in[17];
    const float* tr_bq   = (const float*)d_in[18];
    const float* tr_wk   = (const float*)d_in[19];
    const float* tr_bk   = (const float*)d_in[20];
    const float* tr_wv   = (const float*)d_in[21];
    const float* tr_bv   = (const float*)d_in[22];
    const float* tr_bng  = (const float*)d_in[23];
    const float* tr_bnb  = (const float*)d_in[24];
    const float* tr_w1   = (const float*)d_in[25];
    const float* tr_b1   = (const float*)d_in[26];
    const float* tr_w2   = (const float*)d_in[27];
    const float* tr_b2   = (const float*)d_in[28];
    const float* tr_fg   = (const float*)d_in[29];
    const float* tr_fb   = (const float*)d_in[30];

    float* buf = nullptr;
    cudaGetSymbolAddress((void**)&buf, g_buf);

    float* embs  = buf + OFF_EMBS;
    float* nodes = buf + OFF_NODES;
    float* xln   = buf + OFF_XLN;
    float* qb    = buf + OFF_Q;
    float* kb    = buf + OFF_K;
    float* vb    = buf + OFF_V;
    float* keb   = buf + OFF_KE;
    float* veb   = buf + OFF_VE;
    float* sb    = buf + OFF_S;
    float* retb  = buf + OFF_RET;
    float* ob    = buf + OFF_O;
    float* ktrb  = buf + OFF_KTR;
    float* vtrb  = buf + OFF_VTR;
    float* hb    = buf + OFF_H;
    float* relay = buf + OFF_RELAY;
    float* krb   = buf + OFF_KR;
    float* vrb   = buf + OFF_VR;
    float* qtrb  = buf + OFF_QTR;
    float* ktrr  = buf + OFF_KTRR;
    float* vtrr  = buf + OFF_VTRR;
    float* zb    = buf + OFF_Z;
    float* rettb = buf + OFF_RETT;
    float* otrb  = buf + OFF_OTR;
    float* htrb  = buf + OFF_HTR;
    float* meanb = buf + OFF_MEAN;
    float* invb  = buf + OFF_INV;

    // raise dynamic smem limit for the big GEMM (idempotent)
    cudaFuncSetAttribute(gemm_tf32<0>, cudaFuncAttributeMaxDynamicSharedMemorySize, GEMM_SMEM);
    cudaFuncSetAttribute(gemm_tf32<1>, cudaFuncAttributeMaxDynamicSharedMemorySize, GEMM_SMEM);
    cudaFuncSetAttribute(gemm_tf32<2>, cudaFuncAttributeMaxDynamicSharedMemorySize, GEMM_SMEM);

    prep_kernel<<<dim3(NTOK, 32), dim3(32, 8)>>>(data, embs, relay);

    const dim3 g_o2(2, NTOK), g_o8(8, NTOK);
    const dim3 gnc4(4, 7), gnc16(16, 7);

    for (int i = 0; i < ITER; i++) {
        const float* nodes_in = (i == 0) ? embs : nodes;
        // LayerNorm over channels
        ln_kernel<<<dim3(NTOK, 4), dim3(32, 8)>>>(nodes_in, ln_g + i * CD, ln_b + i * CD, xln);

        const float* wq = tj_wq + (size_t)i * CD * CD;
        const float* wk = tj_wk + (size_t)i * CD * CD;
        const float* wv = tj_wv + (size_t)i * CD * CD;
        const float* bq = tj_bq + i * CD;
        const float* bk = tj_bk + i * CD;
        const float* bv = tj_bv + i * CD;

        gemm_tf32<0><<<g_o2, 256, GEMM_SMEM>>>(wq, bq, xln, qb, nullptr, CD, CD);
        gemm_tf32<0><<<g_o2, 256, GEMM_SMEM>>>(wk, bk, xln, kb, nullptr, CD, CD);
        gemm_tf32<0><<<g_o2, 256, GEMM_SMEM>>>(wv, bv, xln, vb, nullptr, CD, CD);
        gemm_tf32<0><<<g_o2, 256, GEMM_SMEM>>>(wk, bk, embs, keb, nullptr, CD, CD);
        gemm_tf32<0><<<g_o2, 256, GEMM_SMEM>>>(wv, bv, embs, veb, nullptr, CD, CD);
        gemm_nc<0><<<gnc4, 256>>>(wk, bk, relay, krb, nullptr, CD, CD);
        gemm_nc<0><<<gnc4, 256>>>(wv, bv, relay, vrb, nullptr, CD, CD);

        attn_tju<<<NTOK * NHH, 128>>>(qb, kb, vb, keb, veb, krb, vrb, xln, sb);

        bn_stats_nct<<<256, 256>>>(sb, meanb, invb, 1e-5f);
        affine_nct<<<NCT / 256, 256>>>(sb, meanb, invb, tj_bng + i * CD, tj_bnb + i * CD, retb, 0);

        gemm_tf32<1><<<g_o8, 256, GEMM_SMEM>>>(tj_w1 + (size_t)i * DFFD * CD, tj_b1 + i * DFFD,
                                               retb, hb, nullptr, DFFD, CD);
        gemm_tf32<2><<<g_o2, 256, GEMM_SMEM>>>(tj_w2 + (size_t)i * CD * DFFD, tj_b2 + i * CD,
                                               hb, ob, retb, CD, DFFD);

        bn_stats_nct<<<256, 256>>>(ob, meanb, invb, 1e-5f);
        float* nodes_out = (i == ITER - 1) ? (float*)d_out : nodes;
        affine_nct<<<NCT / 256, 256>>>(ob, meanb, invb, tj_fg + i * CD, tj_fb + i * CD,
                                       nodes_out, 1);

        if (i < ITER - 1) {
            const float* rwq = tr_wq + (size_t)i * CD * CD;
            const float* rwk = tr_wk + (size_t)i * CD * CD;
            const float* rwv = tr_wv + (size_t)i * CD * CD;
            const float* rbq = tr_bq + i * CD;
            const float* rbk = tr_bk + i * CD;
            const float* rbv = tr_bv + i * CD;

            gemm_nc<0><<<gnc4, 256>>>(rwq, rbq, relay, qtrb, nullptr, CD, CD);
            gemm_tf32<0><<<g_o2, 256, GEMM_SMEM>>>(rwk, rbk, nodes, ktrb, nullptr, CD, CD);
            gemm_tf32<0><<<g_o2, 256, GEMM_SMEM>>>(rwv, rbv, nodes, vtrb, nullptr, CD, CD);
            gemm_nc<0><<<gnc4, 256>>>(rwk, rbk, relay, ktrr, nullptr, CD, CD);
            gemm_nc<0><<<gnc4, 256>>>(rwv, rbv, relay, vtrr, nullptr, CD, CD);

            attn_tru<<<NTOK, 256>>>(qtrb, ktrb, vtrb, ktrr, vtrr, relay, zb);

            bn_stats_nc<<<256, 256>>>(zb, meanb, invb, 1e-5f);
            affine_nc<<<NC / 256, 256>>>(zb, meanb, invb, tr_bng + i * CD, tr_bnb + i * CD,
                                         rettb, 0);

            gemm_nc<1><<<gnc16, 256>>>(tr_w1 + (size_t)i * DFFD * CD, tr_b1 + i * DFFD,
                                       rettb, htrb, nullptr, DFFD, CD);
            gemm_nc<2><<<gnc4, 256>>>(tr_w2 + (size_t)i * CD * DFFD, tr_b2 + i * CD,
                                      htrb, otrb, rettb, CD, DFFD);

            bn_stats_nc<<<256, 256>>>(otrb, meanb, invb, 1e-5f);
            affine_nc<<<NC / 256, 256>>>(otrb, meanb, invb, tr_fg + i * CD, tr_fb + i * CD,
                                         relay, 1);
        }
    }
}

// round 8
// speedup vs baseline: 2.6034x; 1.4310x over previous
#include <cuda_runtime.h>
#include <math.h>
#include <stdint.h>

#define NTOK 200
#define CD   256
#define TD   128
#define NHH  8
#define DKK  32
#define DFFD 1024
#define ITER 4
#define NCT  (NTOK*CD*TD)
#define NC   (NTOK*CD)

#define OFF_EMBS   0
#define OFF_NODES  (1*NCT)
#define OFF_XLN    (2*NCT)
#define OFF_Q      (3*NCT)
#define OFF_K      (4*NCT)
#define OFF_V      (5*NCT)
#define OFF_KE     (6*NCT)
#define OFF_VE     (7*NCT)
#define OFF_S      (8*NCT)
#define OFF_RET    (9*NCT)
#define OFF_O      (10*NCT)
#define OFF_KTR    (11*NCT)
#define OFF_VTR    (12*NCT)
#define OFF_H      (13*NCT)            /* N*DFF*T = 4*NCT ; holds tf32 */
#define OFF_RELAY  (17*NCT)
#define OFF_KR     (OFF_RELAY+NC)
#define OFF_VR     (OFF_KR+NC)
#define OFF_QTR    (OFF_VR+NC)
#define OFF_KTRR   (OFF_QTR+NC)
#define OFF_VTRR   (OFF_KTRR+NC)
#define OFF_Z      (OFF_VTRR+NC)
#define OFF_RETT   (OFF_Z+NC)
#define OFF_OTR    (OFF_RETT+NC)
#define OFF_HTR    (OFF_OTR+NC)
#define OFF_MEAN   (OFF_HTR+NTOK*DFFD)
#define OFF_INV    (OFF_MEAN+256)

/* tf32 shadows */
#define WT_QKV     (CD*CD*ITER)
#define WT_FFN     (DFFD*CD*ITER)
#define OFF_WQ_T   (OFF_INV+256)
#define OFF_WK_T   (OFF_WQ_T+WT_QKV)
#define OFF_WV_T   (OFF_WK_T+WT_QKV)
#define OFF_RWK_T  (OFF_WV_T+WT_QKV)
#define OFF_RWV_T  (OFF_RWK_T+WT_QKV)
#define OFF_W1_T   (OFF_RWV_T+WT_QKV)
#define OFF_W2_T   (OFF_W1_T+WT_FFN)
#define OFF_XLN_T  (OFF_W2_T+WT_FFN)
#define OFF_EMBS_T (OFF_XLN_T+NCT)
#define OFF_RET_T  (OFF_EMBS_T+NCT)
#define OFF_NODES_T (OFF_RET_T+NCT)
#define BUF_TOTAL  (OFF_NODES_T+NCT)

__device__ __align__(16) float g_buf[BUF_TOTAL];

__device__ __forceinline__ uint32_t f2tf32(float x) {
    uint32_t r;
    asm("cvt.rna.tf32.f32 %0, %1;" : "=r"(r) : "f"(x));
    return r;
}

#define MMA_TF32(C, A, B)                                                     \
    asm volatile("mma.sync.aligned.m16n8k8.row.col.f32.tf32.tf32.f32 "        \
                 "{%0,%1,%2,%3}, {%4,%5,%6,%7}, {%8,%9}, {%0,%1,%2,%3};\n"    \
                 : "+f"((C)[0]), "+f"((C)[1]), "+f"((C)[2]), "+f"((C)[3])     \
                 : "r"((A)[0]), "r"((A)[1]), "r"((A)[2]), "r"((A)[3]),        \
                   "r"((B)[0]), "r"((B)[1]));

#define CP16(daddr, src)                                                      \
    asm volatile("cp.async.cg.shared.global [%0], [%1], 16;"                  \
                 :: "r"(daddr), "l"(src))
#define CP_COMMIT asm volatile("cp.async.commit_group;")
#define CP_WAIT(N) asm volatile("cp.async.wait_group %0;" :: "n"(N))

// ---------------------------------------------------------------------------
// Convert W (fp32, [layer][O][Cin]) into fragment-major tf32 layout:
// [layer][o_blk][chunk][frag=32][lane=32][4].  One thread per output element.
// grid ((O*Cin+255)/256, ITER)
// ---------------------------------------------------------------------------
__global__ void conv_w_frag(const float* __restrict__ W, uint32_t* __restrict__ Wt,
                            int O, int Cin)
{
    size_t base = (size_t)blockIdx.y * O * Cin;
    int idx = blockIdx.x * 256 + threadIdx.x;
    if (idx >= O * Cin) return;
    int NCH = Cin >> 5;
    int j = idx & 3, sl = (idx >> 2) & 31, f = (idx >> 7) & 31;
    int rest = idx >> 12;
    int c = rest % NCH, ob = rest / NCH;
    int r = ob * 128 + (f >> 2) * 16 + (sl >> 2) + ((j & 1) << 3);
    int col = c * 32 + (f & 3) * 8 + (sl & 3) + ((j >> 1) << 2);
    Wt[base + idx] = f2tf32(W[base + (size_t)r * Cin + col]);
}

// ---------------------------------------------------------------------------
// prep: embs[n,c,t] = data[b,c,v,t], embs_t = tf32(embs), relay = mean_t
// ---------------------------------------------------------------------------
__global__ void prep_kernel(const float* __restrict__ data,
                            float* __restrict__ embs, uint32_t* __restrict__ embs_t,
                            float* __restrict__ relay)
{
    int n = blockIdx.x;
    int b = n / 25, v = n % 25;
    int c = blockIdx.y * 8 + threadIdx.y;
    int tx = threadIdx.x;
    const float* src = data + (((size_t)b * CD + c) * 25 + v) * TD;
    size_t dof = ((size_t)n * CD + c) * TD;
    float s = 0.f;
#pragma unroll
    for (int j = 0; j < 4; j++) {
        int t = tx + 32 * j;
        float x = src[t];
        embs[dof + t] = x;
        embs_t[dof + t] = f2tf32(x);
        s += x;
    }
#pragma unroll
    for (int o = 16; o > 0; o >>= 1) s += __shfl_xor_sync(0xffffffffu, s, o);
    if (tx == 0) relay[n * CD + c] = s * (1.0f / 128.0f);
}

// ---------------------------------------------------------------------------
// LayerNorm over channel dim; writes fp32 + tf32. grid (NTOK,4), block (32,8)
// ---------------------------------------------------------------------------
__global__ void ln_kernel(const float* __restrict__ X, const float* __restrict__ g,
                          const float* __restrict__ b, float* __restrict__ Y,
                          uint32_t* __restrict__ Yt)
{
    int n = blockIdx.x;
    int t = blockIdx.y * 32 + threadIdx.x;
    int tx = threadIdx.x, ty = threadIdx.y;
    float x[32];
    float s1 = 0.f, s2 = 0.f;
#pragma unroll
    for (int j = 0; j < 32; j++) {
        int c = ty + j * 8;
        x[j] = X[((size_t)n * CD + c) * TD + t];
        s1 += x[j];
        s2 += x[j] * x[j];
    }
    __shared__ float sm1[8][32], sm2[8][32], smean[32], sinv[32];
    sm1[ty][tx] = s1; sm2[ty][tx] = s2;
    __syncthreads();
    if (ty == 0) {
        float a = 0.f, bb = 0.f;
#pragma unroll
        for (int qy = 0; qy < 8; qy++) { a += sm1[qy][tx]; bb += sm2[qy][tx]; }
        float m = a * (1.0f / 256.0f);
        float var = bb * (1.0f / 256.0f) - m * m;
        smean[tx] = m;
        sinv[tx] = rsqrtf(var + 1e-6f);
    }
    __syncthreads();
    float m = smean[tx], inv = sinv[tx];
#pragma unroll
    for (int j = 0; j < 32; j++) {
        int c = ty + j * 8;
        float vv = (x[j] - m) * inv * g[c] + b[c];
        size_t off = ((size_t)n * CD + c) * TD + t;
        Y[off] = vv;
        Yt[off] = f2tf32(vv);
    }
}

// ---------------------------------------------------------------------------
// TF32 GEMM, pre-converted operands + cp.async 3-stage pipeline.
// Y[n,o,t] = sum_c W[o,c]*X[n,c,t] + bias[o]; block tile 128x128, K-chunk 32.
// Wt: fragment-major per (o_blk, chunk): 4096 u32 contiguous = smem image.
// Xt: natural [c][t] tf32.
// smem per stage: Wf 4096 u32 + Xs[32][132]; 3 stages, 1 barrier/chunk.
// EPI: 0 = bias(->float Y), 1 = relu(->tf32 Y), 2 = +Res(->float Y)
// grid (O/128, NTOK), block 256, 2 blocks/SM.
// ---------------------------------------------------------------------------
#define XS_STR   132
#define WF_U32   (32 * 128)                 /* 4096 */
#define BUFU     (WF_U32 + 32 * XS_STR)     /* 8320 u32 */
#define GEMM_SMEM (3 * BUFU * 4)            /* 99840 B */

template <int EPI>
__global__ __launch_bounds__(256, 2)
void gemm_pre(const uint32_t* __restrict__ Wt, const float* __restrict__ bias,
              const uint32_t* __restrict__ Xt, void* __restrict__ Yout,
              const float* __restrict__ Res, int O, int Cin)
{
    extern __shared__ __align__(16) uint32_t smem_dyn[];
    uint32_t smem_base = (uint32_t)__cvta_generic_to_shared(smem_dyn);

    int n = blockIdx.y;
    int nchunks = Cin >> 5;
    const uint32_t* Wblk = Wt + (size_t)blockIdx.x * nchunks * (WF_U32);
    const uint32_t* Xn = Xt + (size_t)n * Cin * TD;
    int tid = threadIdx.x;
    int lane = tid & 31, wid = tid >> 5;
    int warp_o = wid >> 2, warp_t = wid & 3;
    int g = lane >> 2, q = lane & 3;

#define ISSUE(c)                                                              \
    do {                                                                      \
        int bsel = (c) % 3;                                                   \
        uint32_t wb = smem_base + bsel * (BUFU * 4);                          \
        uint32_t xb = wb + WF_U32 * 4;                                        \
        const uint32_t* wsrc = Wblk + (size_t)(c) * WF_U32;                   \
        const uint32_t* xsrc = Xn + (size_t)(c) * 32 * TD;                    \
        _Pragma("unroll")                                                     \
        for (int r = 0; r < 4; r++) {                                         \
            int i = tid + 256 * r;                                            \
            CP16(wb + (uint32_t)i * 16, wsrc + i * 4);                        \
            int k = i >> 5, c4 = i & 31;                                      \
            CP16(xb + (uint32_t)(k * XS_STR + c4 * 4) * 4,                    \
                 xsrc + (size_t)k * TD + c4 * 4);                             \
        }                                                                     \
        CP_COMMIT;                                                            \
    } while (0)

    ISSUE(0);
    if (nchunks > 1) ISSUE(1);

    float acc[4][4][4];
#pragma unroll
    for (int m = 0; m < 4; m++)
#pragma unroll
        for (int nf = 0; nf < 4; nf++)
#pragma unroll
            for (int j = 0; j < 4; j++) acc[m][nf][j] = 0.f;

    int cidx = warp_t * 32 + g;
    for (int c = 0; c < nchunks; c++) {
        if (c + 1 < nchunks) { CP_WAIT(1); } else { CP_WAIT(0); }
        __syncthreads();               // chunk c visible; MMA(c-1) done by all
        if (c + 2 < nchunks) ISSUE(c + 2);   // into buffer vacated by chunk c-1

        const uint32_t* Wb = smem_dyn + (c % 3) * BUFU;
        const uint32_t* Xb = Wb + WF_U32;
#pragma unroll
        for (int kt = 0; kt < 4; kt++) {
            uint32_t a[4][4], b[4][2];
#pragma unroll
            for (int m = 0; m < 4; m++) {
                int f = (warp_o * 4 + m) * 4 + kt;
                *(uint4*)a[m] = *(const uint4*)&Wb[f * 128 + lane * 4];
            }
            const uint32_t* xrow0 = &Xb[(kt * 8 + q) * XS_STR + cidx];
            const uint32_t* xrow1 = xrow0 + 4 * XS_STR;
#pragma unroll
            for (int nf = 0; nf < 4; nf++) {
                b[nf][0] = xrow0[nf * 8];
                b[nf][1] = xrow1[nf * 8];
            }
#pragma unroll
            for (int m = 0; m < 4; m++)
#pragma unroll
                for (int nf = 0; nf < 4; nf++)
                    MMA_TF32(acc[m][nf], a[m], b[nf]);
        }
    }
#undef ISSUE

    // epilogue
#pragma unroll
    for (int m = 0; m < 4; m++) {
        int obase = blockIdx.x * 128 + warp_o * 64 + m * 16 + g;
#pragma unroll
        for (int r = 0; r < 2; r++) {
            int o = obase + r * 8;
            float bs = bias[o];
            size_t rowoff = ((size_t)n * O + o) * TD;
#pragma unroll
            for (int nf = 0; nf < 4; nf++) {
                int t = warp_t * 32 + nf * 8 + q * 2;
                float v0 = acc[m][nf][r * 2 + 0] + bs;
                float v1 = acc[m][nf][r * 2 + 1] + bs;
                if (EPI == 1) {
                    v0 = fmaxf(v0, 0.f); v1 = fmaxf(v1, 0.f);
                    uint32_t* yrow = (uint32_t*)Yout + rowoff;
                    yrow[t] = f2tf32(v0);
                    yrow[t + 1] = f2tf32(v1);
                } else {
                    if (EPI == 2) {
                        float2 rr = *(const float2*)(Res + rowoff + t);
                        v0 += rr.x; v1 += rr.y;
                    }
                    *(float2*)((float*)Yout + rowoff + t) = make_float2(v0, v1);
                }
            }
        }
    }
}

// ---------------------------------------------------------------------------
// Small GEMM over [N, Cin] tokens (relay path, fp32).
// ---------------------------------------------------------------------------
template <int EPI>
__global__ __launch_bounds__(256)
void gemm_nc(const float* __restrict__ W, const float* __restrict__ bias,
             const float* __restrict__ X, float* __restrict__ Y,
             const float* __restrict__ Res, int O, int Cin)
{
    int o0 = blockIdx.x * 64;
    int n0 = blockIdx.y * 32;
    int tid = threadIdx.x;
    int tx = tid & 31, ty = tid >> 5;

    __shared__ float Ws[32][64];
    __shared__ float Xs[32][33];

    float acc[8];
#pragma unroll
    for (int i = 0; i < 8; i++) acc[i] = 0.f;

    for (int k0 = 0; k0 < Cin; k0 += 32) {
#pragma unroll
        for (int r = 0; r < 2; r++) {
            int idx = tid + 256 * r;
            int o = idx >> 3, kq = idx & 7;
            float4 w4 = *(const float4*)(W + (size_t)(o0 + o) * Cin + k0 + kq * 4);
            Ws[kq * 4 + 0][o] = w4.x;
            Ws[kq * 4 + 1][o] = w4.y;
            Ws[kq * 4 + 2][o] = w4.z;
            Ws[kq * 4 + 3][o] = w4.w;
        }
        {
            int nn = tid >> 3, kq = tid & 7;
            int n = n0 + nn;
            float4 x4 = make_float4(0.f, 0.f, 0.f, 0.f);
            if (n < NTOK) x4 = *(const float4*)(X + (size_t)n * Cin + k0 + kq * 4);
            Xs[kq * 4 + 0][nn] = x4.x;
            Xs[kq * 4 + 1][nn] = x4.y;
            Xs[kq * 4 + 2][nn] = x4.z;
            Xs[kq * 4 + 3][nn] = x4.w;
        }
        __syncthreads();
#pragma unroll
        for (int kk = 0; kk < 32; kk++) {
            float bv = Xs[kk][tx];
#pragma unroll
            for (int i = 0; i < 8; i++) acc[i] += Ws[kk][ty * 8 + i] * bv;
        }
        __syncthreads();
    }

    int n = n0 + tx;
    if (n < NTOK) {
#pragma unroll
        for (int i = 0; i < 8; i++) {
            int o = o0 + ty * 8 + i;
            float val = acc[i] + bias[o];
            if (EPI == 1) val = fmaxf(val, 0.f);
            if (EPI == 2) val += Res[(size_t)n * O + o];
            Y[(size_t)n * O + o] = val;
        }
    }
}

// ---------------------------------------------------------------------------
// tju attention (window-3 + emb token + relay token), fused residual add.
// ---------------------------------------------------------------------------
__global__ void attn_tju(const float* __restrict__ q, const float* __restrict__ k,
                         const float* __restrict__ v, const float* __restrict__ ke,
                         const float* __restrict__ ve, const float* __restrict__ kr,
                         const float* __restrict__ vr, const float* __restrict__ xln,
                         float* __restrict__ sout)
{
    int nh = blockIdx.x;
    int n = nh >> 3, h = nh & 7;
    int t = threadIdx.x;
    int rbase = n * CD + h * DKK;
    size_t base = (size_t)rbase * TD;

    float l0 = 0.f, l1 = 0.f, l2 = 0.f, l3 = 0.f, l4 = 0.f;
#pragma unroll 8
    for (int d = 0; d < DKK; d++) {
        size_t off = base + (size_t)d * TD + t;
        float qd = q[off];
        float kc = k[off];
        float km = (t > 0) ? k[off - 1] : 0.f;
        float kp = (t < TD - 1) ? k[off + 1] : 0.f;
        l0 += qd * km;
        l1 += qd * kc;
        l2 += qd * kp;
        l3 += qd * ke[off];
        l4 += qd * kr[rbase + d];
    }
    const float sc = 0.17677669529663687f;
    l0 *= sc; l1 *= sc; l2 *= sc; l3 *= sc; l4 *= sc;
    float m = fmaxf(fmaxf(fmaxf(l0, l1), fmaxf(l2, l3)), l4);
    float e0 = expf(l0 - m), e1 = expf(l1 - m), e2 = expf(l2 - m);
    float e3 = expf(l3 - m), e4 = expf(l4 - m);
    float rs = 1.f / (e0 + e1 + e2 + e3 + e4);
    float a0 = e0 * rs, a1 = e1 * rs, a2 = e2 * rs, a3 = e3 * rs, a4 = e4 * rs;

#pragma unroll 8
    for (int d = 0; d < DKK; d++) {
        size_t off = base + (size_t)d * TD + t;
        float vc = v[off];
        float vm = (t > 0) ? v[off - 1] : 0.f;
        float vp = (t < TD - 1) ? v[off + 1] : 0.f;
        float att = a0 * vm + a1 * vc + a2 * vp + a3 * ve[off] + a4 * vr[rbase + d];
        sout[off] = xln[off] + att;
    }
}

// ---------------------------------------------------------------------------
// tru attention (relay over 129 tokens). block 256, grid 200 / 8 heads per blk
// ---------------------------------------------------------------------------
__global__ void attn_tru(const float* __restrict__ qtr, const float* __restrict__ ktr,
                         const float* __restrict__ vtr, const float* __restrict__ ktrr,
                         const float* __restrict__ vtrr, const float* __restrict__ relay,
                         float* __restrict__ z)
{
    __shared__ float sq[8][DKK];
    __shared__ float slog[8][132];
    int wid = threadIdx.x >> 5, lane = threadIdx.x & 31;
    int nh = blockIdx.x * 8 + wid;
    int n = nh >> 3, h = nh & 7;
    int rbase = n * CD + h * DKK;
    size_t base = (size_t)rbase * TD;
    const float sc = 0.17677669529663687f;

    sq[wid][lane] = qtr[rbase + lane];
    __syncwarp();

    float lg[5];
#pragma unroll
    for (int j = 0; j < 5; j++) {
        int l = lane + 32 * j;
        float acc = -1e30f;
        if (l < 129) {
            acc = 0.f;
            if (l == 0) {
#pragma unroll 8
                for (int d = 0; d < DKK; d++) acc += sq[wid][d] * ktrr[rbase + d];
            } else {
                int t = l - 1;
#pragma unroll 8
                for (int d = 0; d < DKK; d++) acc += sq[wid][d] * ktr[base + (size_t)d * TD + t];
            }
            acc *= sc;
        }
        lg[j] = acc;
    }
    float m = -1e30f;
#pragma unroll
    for (int j = 0; j < 5; j++) m = fmaxf(m, lg[j]);
#pragma unroll
    for (int o = 16; o > 0; o >>= 1) m = fmaxf(m, __shfl_xor_sync(0xffffffffu, m, o));
    float es = 0.f;
#pragma unroll
    for (int j = 0; j < 5; j++) {
        int l = lane + 32 * j;
        if (l < 129) {
            float e = expf(lg[j] - m);
            slog[wid][l] = e;
            es += e;
        }
    }
#pragma unroll
    for (int o = 16; o > 0; o >>= 1) es += __shfl_xor_sync(0xffffffffu, es, o);
    __syncwarp();
    float rinv = 1.f / es;

    int d = lane;
    float att = slog[wid][0] * vtrr[rbase + d];
    const float* vp = vtr + base + (size_t)d * TD;
#pragma unroll 16
    for (int t = 0; t < TD; t++) att += slog[wid][1 + t] * vp[t];
    att *= rinv;
    z[rbase + d] = relay[rbase + d] + att;
}

// ---------------------------------------------------------------------------
// BN stats over (n,t) per channel. grid 256, block 256.
// ---------------------------------------------------------------------------
__global__ void bn_stats_nct(const float* __restrict__ X, float* __restrict__ mean,
                             float* __restrict__ inv, float eps)
{
    int c = blockIdx.x, tid = threadIdx.x;
    float s1 = 0.f, s2 = 0.f;
    for (int i = tid; i < NTOK * TD; i += 256) {
        int n = i >> 7, t = i & 127;
        float x = X[((size_t)n * CD + c) * TD + t];
        s1 += x;
        s2 += x * x;
    }
    __shared__ double d1[256], d2[256];
    d1[tid] = s1; d2[tid] = s2;
    __syncthreads();
    for (int s = 128; s > 0; s >>= 1) {
        if (tid < s) { d1[tid] += d1[tid + s]; d2[tid] += d2[tid + s]; }
        __syncthreads();
    }
    if (tid == 0) {
        double mm = d1[0] / (NTOK * TD);
        double var = d2[0] / (NTOK * TD) - mm * mm;
        mean[c] = (float)mm;
        inv[c] = rsqrtf((float)var + eps);
    }
}

__global__ void bn_stats_nc(const float* __restrict__ X, float* __restrict__ mean,
                            float* __restrict__ inv, float eps)
{
    int c = blockIdx.x, tid = threadIdx.x;
    float s1 = 0.f, s2 = 0.f;
    for (int n = tid; n < NTOK; n += 256) {
        float x = X[(size_t)n * CD + c];
        s1 += x;
        s2 += x * x;
    }
    __shared__ double d1[256], d2[256];
    d1[tid] = s1; d2[tid] = s2;
    __syncthreads();
    for (int s = 128; s > 0; s >>= 1) {
        if (tid < s) { d1[tid] += d1[tid + s]; d2[tid] += d2[tid + s]; }
        __syncthreads();
    }
    if (tid == 0) {
        double mm = d1[0] / NTOK;
        double var = d2[0] / NTOK - mm * mm;
        mean[c] = (float)mm;
        inv[c] = rsqrtf((float)var + eps);
    }
}

// apply BN affine (+ optional leaky relu) on [N,C,T]; optional tf32 shadow
__global__ void affine_nct(const float* __restrict__ X, const float* __restrict__ mean,
                           const float* __restrict__ inv, const float* __restrict__ g,
                           const float* __restrict__ b, float* __restrict__ Y,
                           uint32_t* __restrict__ Yt, int leaky)
{
    int idx = blockIdx.x * 256 + threadIdx.x;
    if (idx >= NCT) return;
    int c = (idx >> 7) & 255;
    float vv = (X[idx] - mean[c]) * inv[c] * g[c] + b[c];
    if (leaky && vv < 0.f) vv *= 0.01f;
    Y[idx] = vv;
    if (Yt) Yt[idx] = f2tf32(vv);
}

__global__ void affine_nc(const float* __restrict__ X, const float* __restrict__ mean,
                          const float* __restrict__ inv, const float* __restrict__ g,
                          const float* __restrict__ b, float* __restrict__ Y, int leaky)
{
    int idx = blockIdx.x * 256 + threadIdx.x;
    if (idx >= NC) return;
    int c = idx & 255;
    float vv = (X[idx] - mean[c]) * inv[c] * g[c] + b[c];
    if (leaky && vv < 0.f) vv *= 0.01f;
    Y[idx] = vv;
}

// ---------------------------------------------------------------------------
extern "C" void kernel_launch(void* const* d_in, const int* in_sizes, int n_in,
                              void* d_out, int out_size)
{
    (void)in_sizes; (void)n_in; (void)out_size;
    const float* data    = (const float*)d_in[0];
    const float* ln_g    = (const float*)d_in[1];
    const float* ln_b    = (const float*)d_in[2];
    const float* tj_wq   = (const float*)d_in[3];
    const float* tj_bq   = (const float*)d_in[4];
    const float* tj_wk   = (const float*)d_in[5];
    const float* tj_bk   = (const float*)d_in[6];
    const float* tj_wv   = (const float*)d_in[7];
    const float* tj_bv   = (const float*)d_in[8];
    const float* tj_bng  = (const float*)d_in[9];
    const float* tj_bnb  = (const float*)d_in[10];
    const float* tj_w1   = (const float*)d_in[11];
    const float* tj_b1   = (const float*)d_in[12];
    const float* tj_w2   = (const float*)d_in[13];
    const float* tj_b2   = (const float*)d_in[14];
    const float* tj_fg   = (const float*)d_in[15];
    const float* tj_fb   = (const float*)d_in[16];
    const float* tr_wq   = (const float*)d_in[17];
    const float* tr_bq   = (const float*)d_in[18];
    const float* tr_wk   = (const float*)d_in[19];
    const float* tr_bk   = (const float*)d_in[20];
    const float* tr_wv   = (const float*)d_in[21];
    const float* tr_bv   = (const float*)d_in[22];
    const float* tr_bng  = (const float*)d_in[23];
    const float* tr_bnb  = (const float*)d_in[24];
    const float* tr_w1   = (const float*)d_in[25];
    const float* tr_b1   = (const float*)d_in[26];
    const float* tr_w2   = (const float*)d_in[27];
    const float* tr_b2   = (const float*)d_in[28];
    const float* tr_fg   = (const float*)d_in[29];
    const float* tr_fb   = (const float*)d_in[30];

    float* buf = nullptr;
    cudaGetSymbolAddress((void**)&buf, g_buf);

    float* embs  = buf + OFF_EMBS;
    float* nodes = buf + OFF_NODES;
    float* xln   = buf + OFF_XLN;
    float* qb    = buf + OFF_Q;
    float* kb    = buf + OFF_K;
    float* vb    = buf + OFF_V;
    float* keb   = buf + OFF_KE;
    float* veb   = buf + OFF_VE;
    float* sb    = buf + OFF_S;
    float* retb  = buf + OFF_RET;
    float* ob    = buf + OFF_O;
    float* ktrb  = buf + OFF_KTR;
    float* vtrb  = buf + OFF_VTR;
    uint32_t* hb = (uint32_t*)(buf + OFF_H);     // tf32
    float* relay = buf + OFF_RELAY;
    float* krb   = buf + OFF_KR;
    float* vrb   = buf + OFF_VR;
    float* qtrb  = buf + OFF_QTR;
    float* ktrr  = buf + OFF_KTRR;
    float* vtrr  = buf + OFF_VTRR;
    float* zb    = buf + OFF_Z;
    float* rettb = buf + OFF_RETT;
    float* otrb  = buf + OFF_OTR;
    float* htrb  = buf + OFF_HTR;
    float* meanb = buf + OFF_MEAN;
    float* invb  = buf + OFF_INV;

    uint32_t* wq_t  = (uint32_t*)(buf + OFF_WQ_T);
    uint32_t* wk_t  = (uint32_t*)(buf + OFF_WK_T);
    uint32_t* wv_t  = (uint32_t*)(buf + OFF_WV_T);
    uint32_t* rwk_t = (uint32_t*)(buf + OFF_RWK_T);
    uint32_t* rwv_t = (uint32_t*)(buf + OFF_RWV_T);
    uint32_t* w1_t  = (uint32_t*)(buf + OFF_W1_T);
    uint32_t* w2_t  = (uint32_t*)(buf + OFF_W2_T);
    uint32_t* xln_t   = (uint32_t*)(buf + OFF_XLN_T);
    uint32_t* embs_t  = (uint32_t*)(buf + OFF_EMBS_T);
    uint32_t* ret_t   = (uint32_t*)(buf + OFF_RET_T);
    uint32_t* nodes_t = (uint32_t*)(buf + OFF_NODES_T);

    cudaFuncSetAttribute(gemm_pre<0>, cudaFuncAttributeMaxDynamicSharedMemorySize, GEMM_SMEM);
    cudaFuncSetAttribute(gemm_pre<1>, cudaFuncAttributeMaxDynamicSharedMemorySize, GEMM_SMEM);
    cudaFuncSetAttribute(gemm_pre<2>, cudaFuncAttributeMaxDynamicSharedMemorySize, GEMM_SMEM);

    // one-time weight conversions (deterministic each call)
    conv_w_frag<<<dim3(CD * CD / 256, ITER), 256>>>(tj_wq, wq_t, CD, CD);
    conv_w_frag<<<dim3(CD * CD / 256, ITER), 256>>>(tj_wk, wk_t, CD, CD);
    conv_w_frag<<<dim3(CD * CD / 256, ITER), 256>>>(tj_wv, wv_t, CD, CD);
    conv_w_frag<<<dim3(CD * CD / 256, ITER), 256>>>(tr_wk, rwk_t, CD, CD);
    conv_w_frag<<<dim3(CD * CD / 256, ITER), 256>>>(tr_wv, rwv_t, CD, CD);
    conv_w_frag<<<dim3(DFFD * CD / 256, ITER), 256>>>(tj_w1, w1_t, DFFD, CD);
    conv_w_frag<<<dim3(DFFD * CD / 256, ITER), 256>>>(tj_w2, w2_t, CD, DFFD);

    prep_kernel<<<dim3(NTOK, 32), dim3(32, 8)>>>(data, embs, embs_t, relay);

    const dim3 g_o2(2, NTOK), g_o8(8, NTOK);
    const dim3 gnc4(4, 7), gnc16(16, 7);

    for (int i = 0; i < ITER; i++) {
        const float* nodes_in = (i == 0) ? embs : nodes;
        ln_kernel<<<dim3(NTOK, 4), dim3(32, 8)>>>(nodes_in, ln_g + i * CD, ln_b + i * CD,
                                                  xln, xln_t);

        const uint32_t* lwq = wq_t + (size_t)i * CD * CD;
        const uint32_t* lwk = wk_t + (size_t)i * CD * CD;
        const uint32_t* lwv = wv_t + (size_t)i * CD * CD;
        const float* bq = tj_bq + i * CD;
        const float* bk = tj_bk + i * CD;
        const float* bv = tj_bv + i * CD;

        gemm_pre<0><<<g_o2, 256, GEMM_SMEM>>>(lwq, bq, xln_t, qb, nullptr, CD, CD);
        gemm_pre<0><<<g_o2, 256, GEMM_SMEM>>>(lwk, bk, xln_t, kb, nullptr, CD, CD);
        gemm_pre<0><<<g_o2, 256, GEMM_SMEM>>>(lwv, bv, xln_t, vb, nullptr, CD, CD);
        gemm_pre<0><<<g_o2, 256, GEMM_SMEM>>>(lwk, bk, embs_t, keb, nullptr, CD, CD);
        gemm_pre<0><<<g_o2, 256, GEMM_SMEM>>>(lwv, bv, embs_t, veb, nullptr, CD, CD);
        gemm_nc<0><<<gnc4, 256>>>(tj_wk + (size_t)i * CD * CD, bk, relay, krb, nullptr, CD, CD);
        gemm_nc<0><<<gnc4, 256>>>(tj_wv + (size_t)i * CD * CD, bv, relay, vrb, nullptr, CD, CD);

        attn_tju<<<NTOK * NHH, 128>>>(qb, kb, vb, keb, veb, krb, vrb, xln, sb);

        bn_stats_nct<<<256, 256>>>(sb, meanb, invb, 1e-5f);
        affine_nct<<<NCT / 256, 256>>>(sb, meanb, invb, tj_bng + i * CD, tj_bnb + i * CD,
                                       retb, ret_t, 0);

        gemm_pre<1><<<g_o8, 256, GEMM_SMEM>>>(w1_t + (size_t)i * DFFD * CD, tj_b1 + i * DFFD,
                                              ret_t, (void*)hb, nullptr, DFFD, CD);
        gemm_pre<2><<<g_o2, 256, GEMM_SMEM>>>(w2_t + (size_t)i * CD * DFFD, tj_b2 + i * CD,
                                              hb, ob, retb, CD, DFFD);

        bn_stats_nct<<<256, 256>>>(ob, meanb, invb, 1e-5f);
        float* nodes_out = (i == ITER - 1) ? (float*)d_out : nodes;
        uint32_t* nodes_out_t = (i == ITER - 1) ? nullptr : nodes_t;
        affine_nct<<<NCT / 256, 256>>>(ob, meanb, invb, tj_fg + i * CD, tj_fb + i * CD,
                                       nodes_out, nodes_out_t, 1);

        if (i < ITER - 1) {
            const float* rwq = tr_wq + (size_t)i * CD * CD;
            const float* rwkf = tr_wk + (size_t)i * CD * CD;
            const float* rwvf = tr_wv + (size_t)i * CD * CD;
            const float* rbq = tr_bq + i * CD;
            const float* rbk = tr_bk + i * CD;
            const float* rbv = tr_bv + i * CD;

            gemm_nc<0><<<gnc4, 256>>>(rwq, rbq, relay, qtrb, nullptr, CD, CD);
            gemm_pre<0><<<g_o2, 256, GEMM_SMEM>>>(rwk_t + (size_t)i * CD * CD, rbk,
                                                  nodes_t, ktrb, nullptr, CD, CD);
            gemm_pre<0><<<g_o2, 256, GEMM_SMEM>>>(rwv_t + (size_t)i * CD * CD, rbv,
                                                  nodes_t, vtrb, nullptr, CD, CD);
            gemm_nc<0><<<gnc4, 256>>>(rwkf, rbk, relay, ktrr, nullptr, CD, CD);
            gemm_nc<0><<<gnc4, 256>>>(rwvf, rbv, relay, vtrr, nullptr, CD, CD);

            attn_tru<<<NTOK, 256>>>(qtrb, ktrb, vtrb, ktrr, vtrr, relay, zb);

            bn_stats_nc<<<256, 256>>>(zb, meanb, invb, 1e-5f);
            affine_nc<<<NC / 256, 256>>>(zb, meanb, invb, tr_bng + i * CD, tr_bnb + i * CD,
                                         rettb, 0);

            gemm_nc<1><<<gnc16, 256>>>(tr_w1 + (size_t)i * DFFD * CD, tr_b1 + i * DFFD,
                                       rettb, htrb, nullptr, DFFD, CD);
            gemm_nc<2><<<gnc4, 256>>>(tr_w2 + (size_t)i * CD * DFFD, tr_b2 + i * CD,
                                      htrb, otrb, rettb, CD, DFFD);

            bn_stats_nc<<<256, 256>>>(otrb, meanb, invb, 1e-5f);
            affine_nc<<<NC / 256, 256>>>(otrb, meanb, invb, tr_fg + i * CD, tr_fb + i * CD,
                                         relay, 1);
        }
    }
}

// round 11
// speedup vs baseline: 2.6493x; 1.0176x over previous
#include <cuda_runtime.h>
#include <math.h>
#include <stdint.h>

#define NTOK 200
#define CD   256
#define TD   128
#define NHH  8
#define DKK  32
#define DFFD 1024
#define ITER 4
#define NCT  (NTOK*CD*TD)
#define NC   (NTOK*CD)

#define OFF_EMBS   0
#define OFF_NODES  (1*NCT)
#define OFF_XLN    (2*NCT)
#define OFF_QKV    (3*NCT)             /* 3 NCT: [n][768][T] */
#define OFF_S      (6*NCT)
#define OFF_RET    (7*NCT)
#define OFF_O      (8*NCT)
#define OFF_KTRVTR (9*NCT)             /* 2 NCT: [n][512][T] */
#define OFF_H      (11*NCT)            /* 4 NCT tf32 */
#define OFF_KEVE   (15*NCT)            /* 8 NCT: 4 layers x [n][512][T] */
#define OFF_RELAY  (23*NCT)
#define OFF_KR     (OFF_RELAY+NC)
#define OFF_VR     (OFF_KR+NC)
#define OFF_QTR    (OFF_VR+NC)
#define OFF_KTRR   (OFF_QTR+NC)
#define OFF_VTRR   (OFF_KTRR+NC)
#define OFF_Z      (OFF_VTRR+NC)
#define OFF_RETT   (OFF_Z+NC)
#define OFF_OTR    (OFF_RETT+NC)
#define OFF_HTR    (OFF_OTR+NC)
#define OFF_MEAN   (OFF_HTR+NTOK*DFFD)
#define OFF_INV    (OFF_MEAN+256)

/* fragment-major tf32 weights */
#define SEGQ       (128*256)                 /* u32 per o_blk, Cin=256 */
#define LQKV       (6*SEGQ)                  /* per-layer combined qkv  */
#define LRKV       (4*SEGQ)
#define LW1        (DFFD*CD)
#define LW2        (CD*DFFD)
#define OFF_QKVW   (OFF_INV+256)
#define OFF_RWKVW  (OFF_QKVW + LQKV*ITER)
#define OFF_W1T    (OFF_RWKVW + LRKV*ITER)
#define OFF_W2T    (OFF_W1T + LW1*ITER)
#define OFF_XLN_T  (OFF_W2T + LW2*ITER)
#define OFF_EMBS_T (OFF_XLN_T + NCT)
#define OFF_RET_T  (OFF_EMBS_T + NCT)
#define OFF_NODES_T (OFF_RET_T + NCT)
#define BUF_TOTAL  (OFF_NODES_T + NCT)

__device__ __align__(16) float g_buf[BUF_TOTAL];

__device__ __forceinline__ uint32_t f2tf32(float x) {
    uint32_t r;
    asm("cvt.rna.tf32.f32 %0, %1;" : "=r"(r) : "f"(x));
    return r;
}

#define MMA_TF32(C, A, B)                                                     \
    asm volatile("mma.sync.aligned.m16n8k8.row.col.f32.tf32.tf32.f32 "        \
                 "{%0,%1,%2,%3}, {%4,%5,%6,%7}, {%8,%9}, {%0,%1,%2,%3};\n"    \
                 : "+f"((C)[0]), "+f"((C)[1]), "+f"((C)[2]), "+f"((C)[3])     \
                 : "r"((A)[0]), "r"((A)[1]), "r"((A)[2]), "r"((A)[3]),        \
                   "r"((B)[0]), "r"((B)[1]));

#define CP16(daddr, src)                                                      \
    asm volatile("cp.async.cg.shared.global [%0], [%1], 16;"                  \
                 :: "r"(daddr), "l"(src))
#define CP_COMMIT asm volatile("cp.async.commit_group;")
#define CP_WAIT(N) asm volatile("cp.async.wait_group %0;" :: "n"(N))

// ---------------------------------------------------------------------------
// Convert W (fp32 [layer][O][Cin]) to fragment-major tf32 at dst offset:
// dst[l*dl + doff + idx], idx = [ob][chunk][frag][lane][4].
// grid ((O*Cin)/256, ITER)
// ---------------------------------------------------------------------------
__global__ void conv_w_frag(const float* __restrict__ W, uint32_t* __restrict__ Wt,
                            int O, int Cin, size_t dl, size_t doff)
{
    size_t sbase = (size_t)blockIdx.y * O * Cin;
    size_t dbase = (size_t)blockIdx.y * dl + doff;
    int idx = blockIdx.x * 256 + threadIdx.x;
    if (idx >= O * Cin) return;
    int NCH = Cin >> 5;
    int j = idx & 3, sl = (idx >> 2) & 31, f = (idx >> 7) & 31;
    int rest = idx >> 12;
    int c = rest % NCH, ob = rest / NCH;
    int r = ob * 128 + (f >> 2) * 16 + (sl >> 2) + ((j & 1) << 3);
    int col = c * 32 + (f & 3) * 8 + (sl & 3) + ((j >> 1) << 2);
    Wt[dbase + idx] = f2tf32(W[sbase + (size_t)r * Cin + col]);
}

// ---------------------------------------------------------------------------
// prep: embs[n,c,t] = data[b,c,v,t], embs_t = tf32(embs), relay = mean_t
// ---------------------------------------------------------------------------
__global__ void prep_kernel(const float* __restrict__ data,
                            float* __restrict__ embs, uint32_t* __restrict__ embs_t,
                            float* __restrict__ relay)
{
    int n = blockIdx.x;
    int b = n / 25, v = n % 25;
    int c = blockIdx.y * 8 + threadIdx.y;
    int tx = threadIdx.x;
    const float* src = data + (((size_t)b * CD + c) * 25 + v) * TD;
    size_t dof = ((size_t)n * CD + c) * TD;
    float s = 0.f;
#pragma unroll
    for (int j = 0; j < 4; j++) {
        int t = tx + 32 * j;
        float x = src[t];
        embs[dof + t] = x;
        embs_t[dof + t] = f2tf32(x);
        s += x;
    }
#pragma unroll
    for (int o = 16; o > 0; o >>= 1) s += __shfl_xor_sync(0xffffffffu, s, o);
    if (tx == 0) relay[n * CD + c] = s * (1.0f / 128.0f);
}

// ---------------------------------------------------------------------------
// LayerNorm over channel dim; writes fp32 + tf32. grid (NTOK,4), block (32,8)
// ---------------------------------------------------------------------------
__global__ void ln_kernel(const float* __restrict__ X, const float* __restrict__ g,
                          const float* __restrict__ b, float* __restrict__ Y,
                          uint32_t* __restrict__ Yt)
{
    int n = blockIdx.x;
    int t = blockIdx.y * 32 + threadIdx.x;
    int tx = threadIdx.x, ty = threadIdx.y;
    float x[32];
    float s1 = 0.f, s2 = 0.f;
#pragma unroll
    for (int j = 0; j < 32; j++) {
        int c = ty + j * 8;
        x[j] = X[((size_t)n * CD + c) * TD + t];
        s1 += x[j];
        s2 += x[j] * x[j];
    }
    __shared__ float sm1[8][32], sm2[8][32], smean[32], sinv[32];
    sm1[ty][tx] = s1; sm2[ty][tx] = s2;
    __syncthreads();
    if (ty == 0) {
        float a = 0.f, bb = 0.f;
#pragma unroll
        for (int qy = 0; qy < 8; qy++) { a += sm1[qy][tx]; bb += sm2[qy][tx]; }
        float m = a * (1.0f / 256.0f);
        float var = bb * (1.0f / 256.0f) - m * m;
        smean[tx] = m;
        sinv[tx] = rsqrtf(var + 1e-6f);
    }
    __syncthreads();
    float m = smean[tx], inv = sinv[tx];
#pragma unroll
    for (int j = 0; j < 32; j++) {
        int c = ty + j * 8;
        float vv = (x[j] - m) * inv * g[c] + b[c];
        size_t off = ((size_t)n * CD + c) * TD + t;
        Y[off] = vv;
        Yt[off] = f2tf32(vv);
    }
}

// ---------------------------------------------------------------------------
// TF32 GEMM, pre-converted operands + cp.async 3-stage pipeline.
// Layered via blockIdx.z (weight stride wl, Y stride yl; bias z*256 segs).
// NSEG: bias segmentation (1 = single array indexed by o; 2/3 = per-256 segs).
// EPI: 0 bias->f32, 1 relu->tf32, 2 +Res->f32
// ---------------------------------------------------------------------------
#define XS_STR   132
#define WF_U32   (32 * 128)
#define BUFU     (WF_U32 + 32 * XS_STR)
#define GEMM_SMEM (3 * BUFU * 4)

template <int EPI, int NSEG>
__global__ __launch_bounds__(256, 2)
void gemm_pre(const uint32_t* __restrict__ Wt, const float* __restrict__ b0,
              const float* __restrict__ b1, const float* __restrict__ b2,
              const uint32_t* __restrict__ Xt, void* __restrict__ Yout,
              const float* __restrict__ Res, int O, int Cin,
              size_t wl, size_t yl)
{
    extern __shared__ __align__(16) uint32_t smem_dyn[];
    uint32_t smem_base = (uint32_t)__cvta_generic_to_shared(smem_dyn);

    int n = blockIdx.y;
    int z = blockIdx.z;
    int nchunks = Cin >> 5;
    const uint32_t* Wblk = Wt + (size_t)z * wl + (size_t)blockIdx.x * nchunks * WF_U32;
    const uint32_t* Xn = Xt + (size_t)n * Cin * TD;
    int tid = threadIdx.x;
    int lane = tid & 31, wid = tid >> 5;
    int warp_o = wid >> 2, warp_t = wid & 3;
    int g = lane >> 2, q = lane & 3;

#define ISSUE(c)                                                              \
    do {                                                                      \
        int bsel = (c) % 3;                                                   \
        uint32_t wb = smem_base + bsel * (BUFU * 4);                          \
        uint32_t xb = wb + WF_U32 * 4;                                        \
        const uint32_t* wsrc = Wblk + (size_t)(c) * WF_U32;                   \
        const uint32_t* xsrc = Xn + (size_t)(c) * 32 * TD;                    \
        _Pragma("unroll")                                                     \
        for (int r = 0; r < 4; r++) {                                         \
            int i = tid + 256 * r;                                            \
            CP16(wb + (uint32_t)i * 16, wsrc + i * 4);                        \
            int k = i >> 5, c4 = i & 31;                                      \
            CP16(xb + (uint32_t)(k * XS_STR + c4 * 4) * 4,                    \
                 xsrc + (size_t)k * TD + c4 * 4);                             \
        }                                                                     \
        CP_COMMIT;                                                            \
    } while (0)

    ISSUE(0);
    if (nchunks > 1) ISSUE(1);

    float acc[4][4][4];
#pragma unroll
    for (int m = 0; m < 4; m++)
#pragma unroll
        for (int nf = 0; nf < 4; nf++)
#pragma unroll
            for (int j = 0; j < 4; j++) acc[m][nf][j] = 0.f;

    int cidx = warp_t * 32 + g;
    for (int c = 0; c < nchunks; c++) {
        if (c + 1 < nchunks) { CP_WAIT(1); } else { CP_WAIT(0); }
        __syncthreads();
        if (c + 2 < nchunks) ISSUE(c + 2);

        const uint32_t* Wb = smem_dyn + (c % 3) * BUFU;
        const uint32_t* Xb = Wb + WF_U32;
#pragma unroll
        for (int kt = 0; kt < 4; kt++) {
            uint32_t a[4][4], b[4][2];
#pragma unroll
            for (int m = 0; m < 4; m++) {
                int f = (warp_o * 4 + m) * 4 + kt;
                *(uint4*)a[m] = *(const uint4*)&Wb[f * 128 + lane * 4];
            }
            const uint32_t* xrow0 = &Xb[(kt * 8 + q) * XS_STR + cidx];
            const uint32_t* xrow1 = xrow0 + 4 * XS_STR;
#pragma unroll
            for (int nf = 0; nf < 4; nf++) {
                b[nf][0] = xrow0[nf * 8];
                b[nf][1] = xrow1[nf * 8];
            }
#pragma unroll
            for (int m = 0; m < 4; m++)
#pragma unroll
                for (int nf = 0; nf < 4; nf++)
                    MMA_TF32(acc[m][nf], a[m], b[nf]);
        }
    }
#undef ISSUE

#pragma unroll
    for (int m = 0; m < 4; m++) {
        int obase = blockIdx.x * 128 + warp_o * 64 + m * 16 + g;
#pragma unroll
        for (int r = 0; r < 2; r++) {
            int o = obase + r * 8;
            float bs;
            if (NSEG == 1) {
                bs = b0[o];
            } else {
                int seg = o >> 8;
                const float* bp = (seg == 0) ? b0 : (seg == 1 ? b1 : b2);
                bs = bp[z * 256 + (o & 255)];
            }
            size_t rowoff = (size_t)z * yl + ((size_t)n * O + o) * TD;
#pragma unroll
            for (int nf = 0; nf < 4; nf++) {
                int t = warp_t * 32 + nf * 8 + q * 2;
                float v0 = acc[m][nf][r * 2 + 0] + bs;
                float v1 = acc[m][nf][r * 2 + 1] + bs;
                if (EPI == 1) {
                    v0 = fmaxf(v0, 0.f); v1 = fmaxf(v1, 0.f);
                    uint32_t* yrow = (uint32_t*)Yout + rowoff;
                    yrow[t] = f2tf32(v0);
                    yrow[t + 1] = f2tf32(v1);
                } else {
                    if (EPI == 2) {
                        float2 rr = *(const float2*)(Res + rowoff + t);
                        v0 += rr.x; v1 += rr.y;
                    }
                    *(float2*)((float*)Yout + rowoff + t) = make_float2(v0, v1);
                }
            }
        }
    }
}

// ---------------------------------------------------------------------------
// Small GEMM over [N, Cin] tokens (relay path, fp32).
// ---------------------------------------------------------------------------
template <int EPI>
__global__ __launch_bounds__(256)
void gemm_nc(const float* __restrict__ W, const float* __restrict__ bias,
             const float* __restrict__ X, float* __restrict__ Y,
             const float* __restrict__ Res, int O, int Cin)
{
    int o0 = blockIdx.x * 64;
    int n0 = blockIdx.y * 32;
    int tid = threadIdx.x;
    int tx = tid & 31, ty = tid >> 5;

    __shared__ float Ws[32][64];
    __shared__ float Xs[32][33];

    float acc[8];
#pragma unroll
    for (int i = 0; i < 8; i++) acc[i] = 0.f;

    for (int k0 = 0; k0 < Cin; k0 += 32) {
#pragma unroll
        for (int r = 0; r < 2; r++) {
            int idx = tid + 256 * r;
            int o = idx >> 3, kq = idx & 7;
            float4 w4 = *(const float4*)(W + (size_t)(o0 + o) * Cin + k0 + kq * 4);
            Ws[kq * 4 + 0][o] = w4.x;
            Ws[kq * 4 + 1][o] = w4.y;
            Ws[kq * 4 + 2][o] = w4.z;
            Ws[kq * 4 + 3][o] = w4.w;
        }
        {
            int nn = tid >> 3, kq = tid & 7;
            int n = n0 + nn;
            float4 x4 = make_float4(0.f, 0.f, 0.f, 0.f);
            if (n < NTOK) x4 = *(const float4*)(X + (size_t)n * Cin + k0 + kq * 4);
            Xs[kq * 4 + 0][nn] = x4.x;
            Xs[kq * 4 + 1][nn] = x4.y;
            Xs[kq * 4 + 2][nn] = x4.z;
            Xs[kq * 4 + 3][nn] = x4.w;
        }
        __syncthreads();
#pragma unroll
        for (int kk = 0; kk < 32; kk++) {
            float bv = Xs[kk][tx];
#pragma unroll
            for (int i = 0; i < 8; i++) acc[i] += Ws[kk][ty * 8 + i] * bv;
        }
        __syncthreads();
    }

    int n = n0 + tx;
    if (n < NTOK) {
#pragma unroll
        for (int i = 0; i < 8; i++) {
            int o = o0 + ty * 8 + i;
            float val = acc[i] + bias[o];
            if (EPI == 1) val = fmaxf(val, 0.f);
            if (EPI == 2) val += Res[(size_t)n * O + o];
            Y[(size_t)n * O + o] = val;
        }
    }
}

// ---------------------------------------------------------------------------
// tju attention. qkv: [n][768][T] (q 0-255, k 256-511, v 512-767);
// keve: [n][512][T] (ke 0-255, ve 256-511). grid NTOK*NHH, block 128.
// ---------------------------------------------------------------------------
__global__ void attn_tju(const float* __restrict__ qkv, const float* __restrict__ keve,
                         const float* __restrict__ kr, const float* __restrict__ vr,
                         const float* __restrict__ xln, float* __restrict__ sout)
{
    int nh = blockIdx.x;
    int n = nh >> 3, h = nh & 7;
    int t = threadIdx.x;
    int rbase = n * CD + h * DKK;
    size_t base = (size_t)rbase * TD;                        // xln/sout
    size_t bq = ((size_t)n * 768 + h * DKK) * TD;            // q rows
    size_t bke = ((size_t)n * 512 + h * DKK) * TD;           // ke rows
    const size_t KOFF = (size_t)256 * TD, VOFF = (size_t)512 * TD;

    float l0 = 0.f, l1 = 0.f, l2 = 0.f, l3 = 0.f, l4 = 0.f;
#pragma unroll 8
    for (int d = 0; d < DKK; d++) {
        size_t oq = bq + (size_t)d * TD + t;
        float qd = qkv[oq];
        float kc = qkv[oq + KOFF];
        float km = (t > 0) ? qkv[oq + KOFF - 1] : 0.f;
        float kp = (t < TD - 1) ? qkv[oq + KOFF + 1] : 0.f;
        l0 += qd * km;
        l1 += qd * kc;
        l2 += qd * kp;
        l3 += qd * keve[bke + (size_t)d * TD + t];
        l4 += qd * kr[rbase + d];
    }
    const float sc = 0.17677669529663687f;
    l0 *= sc; l1 *= sc; l2 *= sc; l3 *= sc; l4 *= sc;
    float m = fmaxf(fmaxf(fmaxf(l0, l1), fmaxf(l2, l3)), l4);
    float e0 = expf(l0 - m), e1 = expf(l1 - m), e2 = expf(l2 - m);
    float e3 = expf(l3 - m), e4 = expf(l4 - m);
    float rs = 1.f / (e0 + e1 + e2 + e3 + e4);
    float a0 = e0 * rs, a1 = e1 * rs, a2 = e2 * rs, a3 = e3 * rs, a4 = e4 * rs;

#pragma unroll 8
    for (int d = 0; d < DKK; d++) {
        size_t oq = bq + (size_t)d * TD + t;
        float vc = qkv[oq + VOFF];
        float vm = (t > 0) ? qkv[oq + VOFF - 1] : 0.f;
        float vp = (t < TD - 1) ? qkv[oq + VOFF + 1] : 0.f;
        float att = a0 * vm + a1 * vc + a2 * vp
                  + a3 * keve[bke + KOFF + (size_t)d * TD + t] + a4 * vr[rbase + d];
        sout[base + (size_t)d * TD + t] = xln[base + (size_t)d * TD + t] + att;
    }
}

// ---------------------------------------------------------------------------
// tru attention; ktrvtr: [n][512][T] (k 0-255, v 256-511). block 256 = 8 heads
// per block -> grid NTOK (200 blocks for 1600 heads).
// ---------------------------------------------------------------------------
__global__ void attn_tru(const float* __restrict__ qtr, const float* __restrict__ ktrvtr,
                         const float* __restrict__ ktrr, const float* __restrict__ vtrr,
                         const float* __restrict__ relay, float* __restrict__ z)
{
    __shared__ float sq[8][DKK];
    __shared__ float slog[8][132];
    int wid = threadIdx.x >> 5, lane = threadIdx.x & 31;
    int nh = blockIdx.x * 8 + wid;
    int n = nh >> 3, h = nh & 7;
    int rbase = n * CD + h * DKK;
    size_t bk = ((size_t)n * 512 + h * DKK) * TD;
    const size_t VOFF = (size_t)256 * TD;
    const float sc = 0.17677669529663687f;

    sq[wid][lane] = qtr[rbase + lane];
    __syncwarp();

    float lg[5];
#pragma unroll
    for (int j = 0; j < 5; j++) {
        int l = lane + 32 * j;
        float acc = -1e30f;
        if (l < 129) {
            acc = 0.f;
            if (l == 0) {
#pragma unroll 8
                for (int d = 0; d < DKK; d++) acc += sq[wid][d] * ktrr[rbase + d];
            } else {
                int t = l - 1;
#pragma unroll 8
                for (int d = 0; d < DKK; d++) acc += sq[wid][d] * ktrvtr[bk + (size_t)d * TD + t];
            }
            acc *= sc;
        }
        lg[j] = acc;
    }
    float m = -1e30f;
#pragma unroll
    for (int j = 0; j < 5; j++) m = fmaxf(m, lg[j]);
#pragma unroll
    for (int o = 16; o > 0; o >>= 1) m = fmaxf(m, __shfl_xor_sync(0xffffffffu, m, o));
    float es = 0.f;
#pragma unroll
    for (int j = 0; j < 5; j++) {
        int l = lane + 32 * j;
        if (l < 129) {
            float e = expf(lg[j] - m);
            slog[wid][l] = e;
            es += e;
        }
    }
#pragma unroll
    for (int o = 16; o > 0; o >>= 1) es += __shfl_xor_sync(0xffffffffu, es, o);
    __syncwarp();
    float rinv = 1.f / es;

    int d = lane;
    float att = slog[wid][0] * vtrr[rbase + d];
    const float* vp = ktrvtr + bk + VOFF + (size_t)d * TD;
#pragma unroll 16
    for (int t = 0; t < TD; t++) att += slog[wid][1 + t] * vp[t];
    att *= rinv;
    z[rbase + d] = relay[rbase + d] + att;
}

// ---------------------------------------------------------------------------
// BN stats + affine helpers (unchanged numerics)
// ---------------------------------------------------------------------------
__global__ void bn_stats_nct(const float* __restrict__ X, float* __restrict__ mean,
                             float* __restrict__ inv, float eps)
{
    int c = blockIdx.x, tid = threadIdx.x;
    float s1 = 0.f, s2 = 0.f;
    for (int i = tid; i < NTOK * TD; i += 256) {
        int n = i >> 7, t = i & 127;
        float x = X[((size_t)n * CD + c) * TD + t];
        s1 += x;
        s2 += x * x;
    }
    __shared__ double d1[256], d2[256];
    d1[tid] = s1; d2[tid] = s2;
    __syncthreads();
    for (int s = 128; s > 0; s >>= 1) {
        if (tid < s) { d1[tid] += d1[tid + s]; d2[tid] += d2[tid + s]; }
        __syncthreads();
    }
    if (tid == 0) {
        double mm = d1[0] / (NTOK * TD);
        double var = d2[0] / (NTOK * TD) - mm * mm;
        mean[c] = (float)mm;
        inv[c] = rsqrtf((float)var + eps);
    }
}

__global__ void bn_stats_nc(const float* __restrict__ X, float* __restrict__ mean,
                            float* __restrict__ inv, float eps)
{
    int c = blockIdx.x, tid = threadIdx.x;
    float s1 = 0.f, s2 = 0.f;
    for (int n = tid; n < NTOK; n += 256) {
        float x = X[(size_t)n * CD + c];
        s1 += x;
        s2 += x * x;
    }
    __shared__ double d1[256], d2[256];
    d1[tid] = s1; d2[tid] = s2;
    __syncthreads();
    for (int s = 128; s > 0; s >>= 1) {
        if (tid < s) { d1[tid] += d1[tid + s]; d2[tid] += d2[tid + s]; }
        __syncthreads();
    }
    if (tid == 0) {
        double mm = d1[0] / NTOK;
        double var = d2[0] / NTOK - mm * mm;
        mean[c] = (float)mm;
        inv[c] = rsqrtf((float)var + eps);
    }
}

__global__ void affine_nct(const float* __restrict__ X, const float* __restrict__ mean,
                           const float* __restrict__ inv, const float* __restrict__ g,
                           const float* __restrict__ b, float* __restrict__ Y,
                           uint32_t* __restrict__ Yt, int leaky)
{
    int idx = blockIdx.x * 256 + threadIdx.x;
    if (idx >= NCT) return;
    int c = (idx >> 7) & 255;
    float vv = (X[idx] - mean[c]) * inv[c] * g[c] + b[c];
    if (leaky && vv < 0.f) vv *= 0.01f;
    Y[idx] = vv;
    if (Yt) Yt[idx] = f2tf32(vv);
}

__global__ void affine_nc(const float* __restrict__ X, const float* __restrict__ mean,
                          const float* __restrict__ inv, const float* __restrict__ g,
                          const float* __restrict__ b, float* __restrict__ Y, int leaky)
{
    int idx = blockIdx.x * 256 + threadIdx.x;
    if (idx >= NC) return;
    int c = idx & 255;
    float vv = (X[idx] - mean[c]) * inv[c] * g[c] + b[c];
    if (leaky && vv < 0.f) vv *= 0.01f;
    Y[idx] = vv;
}

// ---------------------------------------------------------------------------
extern "C" void kernel_launch(void* const* d_in, const int* in_sizes, int n_in,
                              void* d_out, int out_size)
{
    (void)in_sizes; (void)n_in; (void)out_size;
    const float* data    = (const float*)d_in[0];
    const float* ln_g    = (const float*)d_in[1];
    const float* ln_b    = (const float*)d_in[2];
    const float* tj_wq   = (const float*)d_in[3];
    const float* tj_bq   = (const float*)d_in[4];
    const float* tj_wk   = (const float*)d_in[5];
    const float* tj_bk   = (const float*)d_in[6];
    const float* tj_wv   = (const float*)d_in[7];
    const float* tj_bv   = (const float*)d_in[8];
    const float* tj_bng  = (const float*)d_in[9];
    const float* tj_bnb  = (const float*)d_in[10];
    const float* tj_w1   = (const float*)d_in[11];
    const float* tj_b1   = (const float*)d_in[12];
    const float* tj_w2   = (const float*)d_in[13];
    const float* tj_b2   = (const float*)d_in[14];
    const float* tj_fg   = (const float*)d_in[15];
    const float* tj_fb   = (const float*)d_in[16];
    const float* tr_wq   = (const float*)d_in[17];
    const float* tr_bq   = (const float*)d_in[18];
    const float* tr_wk   = (const float*)d_in[19];
    const float* tr_bk   = (const float*)d_in[20];
    const float* tr_wv   = (const float*)d_in[21];
    const float* tr_bv   = (const float*)d_in[22];
    const float* tr_bng  = (const float*)d_in[23];
    const float* tr_bnb  = (const float*)d_in[24];
    const float* tr_w1   = (const float*)d_in[25];
    const float* tr_b1   = (const float*)d_in[26];
    const float* tr_w2   = (const float*)d_in[27];
    const float* tr_b2   = (const float*)d_in[28];
    const float* tr_fg   = (const float*)d_in[29];
    const float* tr_fb   = (const float*)d_in[30];

    float* buf = nullptr;
    cudaGetSymbolAddress((void**)&buf, g_buf);

    float* embs   = buf + OFF_EMBS;
    float* nodes  = buf + OFF_NODES;
    float* xln    = buf + OFF_XLN;
    float* qkvb   = buf + OFF_QKV;
    float* sb     = buf + OFF_S;
    float* retb   = buf + OFF_RET;
    float* ob     = buf + OFF_O;
    float* ktrvtrb = buf + OFF_KTRVTR;
    uint32_t* hb  = (uint32_t*)(buf + OFF_H);
    float* keveb  = buf + OFF_KEVE;
    float* relay  = buf + OFF_RELAY;
    float* krb    = buf + OFF_KR;
    float* vrb    = buf + OFF_VR;
    float* qtrb   = buf + OFF_QTR;
    float* ktrr   = buf + OFF_KTRR;
    float* vtrr   = buf + OFF_VTRR;
    float* zb     = buf + OFF_Z;
    float* rettb  = buf + OFF_RETT;
    float* otrb   = buf + OFF_OTR;
    float* htrb   = buf + OFF_HTR;
    float* meanb  = buf + OFF_MEAN;
    float* invb   = buf + OFF_INV;

    uint32_t* qkvw  = (uint32_t*)(buf + OFF_QKVW);
    uint32_t* rwkvw = (uint32_t*)(buf + OFF_RWKVW);
    uint32_t* w1_t  = (uint32_t*)(buf + OFF_W1T);
    uint32_t* w2_t  = (uint32_t*)(buf + OFF_W2T);
    uint32_t* xln_t   = (uint32_t*)(buf + OFF_XLN_T);
    uint32_t* embs_t  = (uint32_t*)(buf + OFF_EMBS_T);
    uint32_t* ret_t   = (uint32_t*)(buf + OFF_RET_T);
    uint32_t* nodes_t = (uint32_t*)(buf + OFF_NODES_T);

    cudaFuncSetAttribute(gemm_pre<0,3>, cudaFuncAttributeMaxDynamicSharedMemorySize, GEMM_SMEM);
    cudaFuncSetAttribute(gemm_pre<0,2>, cudaFuncAttributeMaxDynamicSharedMemorySize, GEMM_SMEM);
    cudaFuncSetAttribute(gemm_pre<1,1>, cudaFuncAttributeMaxDynamicSharedMemorySize, GEMM_SMEM);
    cudaFuncSetAttribute(gemm_pre<2,1>, cudaFuncAttributeMaxDynamicSharedMemorySize, GEMM_SMEM);

    // weight conversion into combined fragment-major layouts
    conv_w_frag<<<dim3(CD * CD / 256, ITER), 256>>>(tj_wq, qkvw, CD, CD, LQKV, 0);
    conv_w_frag<<<dim3(CD * CD / 256, ITER), 256>>>(tj_wk, qkvw, CD, CD, LQKV, 2 * SEGQ);
    conv_w_frag<<<dim3(CD * CD / 256, ITER), 256>>>(tj_wv, qkvw, CD, CD, LQKV, 4 * SEGQ);
    conv_w_frag<<<dim3(CD * CD / 256, ITER), 256>>>(tr_wk, rwkvw, CD, CD, LRKV, 0);
    conv_w_frag<<<dim3(CD * CD / 256, ITER), 256>>>(tr_wv, rwkvw, CD, CD, LRKV, 2 * SEGQ);
    conv_w_frag<<<dim3(DFFD * CD / 256, ITER), 256>>>(tj_w1, w1_t, DFFD, CD, LW1, 0);
    conv_w_frag<<<dim3(DFFD * CD / 256, ITER), 256>>>(tj_w2, w2_t, CD, DFFD, LW2, 0);

    prep_kernel<<<dim3(NTOK, 32), dim3(32, 8)>>>(data, embs, embs_t, relay);

    // all 4 layers' ke/ve from embs (layer-batched, weights = [wk,wv] slice of qkvw)
    gemm_pre<0,2><<<dim3(4, NTOK, ITER), 256, GEMM_SMEM>>>(
        qkvw + 2 * SEGQ, tj_bk, tj_bv, nullptr, embs_t, keveb, nullptr,
        512, CD, (size_t)LQKV, (size_t)NTOK * 512 * TD);

    const dim3 gnc4(4, 7), gnc16(16, 7);

    for (int i = 0; i < ITER; i++) {
        const float* nodes_in = (i == 0) ? embs : nodes;
        ln_kernel<<<dim3(NTOK, 4), dim3(32, 8)>>>(nodes_in, ln_g + i * CD, ln_b + i * CD,
                                                  xln, xln_t);

        // fused QKV (O=768)
        gemm_pre<0,3><<<dim3(6, NTOK, 1), 256, GEMM_SMEM>>>(
            qkvw + (size_t)i * LQKV, tj_bq + i * CD, tj_bk + i * CD, tj_bv + i * CD,
            xln_t, qkvb, nullptr, 768, CD, 0, 0);
        gemm_nc<0><<<gnc4, 256>>>(tj_wk + (size_t)i * CD * CD, tj_bk + i * CD,
                                  relay, krb, nullptr, CD, CD);
        gemm_nc<0><<<gnc4, 256>>>(tj_wv + (size_t)i * CD * CD, tj_bv + i * CD,
                                  relay, vrb, nullptr, CD, CD);

        attn_tju<<<NTOK * NHH, 128>>>(qkvb, keveb + (size_t)i * NTOK * 512 * TD,
                                      krb, vrb, xln, sb);

        bn_stats_nct<<<256, 256>>>(sb, meanb, invb, 1e-5f);
        affine_nct<<<NCT / 256, 256>>>(sb, meanb, invb, tj_bng + i * CD, tj_bnb + i * CD,
                                       retb, ret_t, 0);

        gemm_pre<1,1><<<dim3(8, NTOK, 1), 256, GEMM_SMEM>>>(
            w1_t + (size_t)i * LW1, tj_b1 + i * DFFD, nullptr, nullptr,
            ret_t, (void*)hb, nullptr, DFFD, CD, 0, 0);
        gemm_pre<2,1><<<dim3(2, NTOK, 1), 256, GEMM_SMEM>>>(
            w2_t + (size_t)i * LW2, tj_b2 + i * CD, nullptr, nullptr,
            hb, ob, retb, CD, DFFD, 0, 0);

        bn_stats_nct<<<256, 256>>>(ob, meanb, invb, 1e-5f);
        float* nodes_out = (i == ITER - 1) ? (float*)d_out : nodes;
        uint32_t* nodes_out_t = (i == ITER - 1) ? nullptr : nodes_t;
        affine_nct<<<NCT / 256, 256>>>(ob, meanb, invb, tj_fg + i * CD, tj_fb + i * CD,
                                       nodes_out, nodes_out_t, 1);

        if (i < ITER - 1) {
            gemm_nc<0><<<gnc4, 256>>>(tr_wq + (size_t)i * CD * CD, tr_bq + i * CD,
                                      relay, qtrb, nullptr, CD, CD);
            // fused ktr/vtr (O=512)
            gemm_pre<0,2><<<dim3(4, NTOK, 1), 256, GEMM_SMEM>>>(
                rwkvw + (size_t)i * LRKV, tr_bk + i * CD, tr_bv + i * CD, nullptr,
                nodes_t, ktrvtrb, nullptr, 512, CD, 0, 0);
            gemm_nc<0><<<gnc4, 256>>>(tr_wk + (size_t)i * CD * CD, tr_bk + i * CD,
                                      relay, ktrr, nullptr, CD, CD);
            gemm_nc<0><<<gnc4, 256>>>(tr_wv + (size_t)i * CD * CD, tr_bv + i * CD,
                                      relay, vtrr, nullptr, CD, CD);

            attn_tru<<<NTOK, 256>>>(qtrb, ktrvtrb, ktrr, vtrr, relay, zb);

            bn_stats_nc<<<256, 256>>>(zb, meanb, invb, 1e-5f);
            affine_nc<<<NC / 256, 256>>>(zb, meanb, invb, tr_bng + i * CD, tr_bnb + i * CD,
                                         rettb, 0);

            gemm_nc<1><<<gnc16, 256>>>(tr_w1 + (size_t)i * DFFD * CD, tr_b1 + i * DFFD,
                                       rettb, htrb, nullptr, DFFD, CD);
            gemm_nc<2><<<gnc4, 256>>>(tr_w2 + (size_t)i * CD * DFFD, tr_b2 + i * CD,
                                      htrb, otrb, rettb, CD, DFFD);

            bn_stats_nc<<<256, 256>>>(otrb, meanb, invb, 1e-5f);
            affine_nc<<<NC / 256, 256>>>(otrb, meanb, invb, tr_fg + i * CD, tr_fb + i * CD,
                                         relay, 1);
        }
    }
}

// round 14
// speedup vs baseline: 2.9016x; 1.0952x over previous
#include <cuda_runtime.h>
#include <math.h>
#include <stdint.h>

#define NTOK 200
#define CD   256
#define TD   128
#define NHH  8
#define DKK  32
#define DFFD 1024
#define ITER 4
#define NCT  (NTOK*CD*TD)
#define NC   (NTOK*CD)

#define OFF_EMBS   0
#define OFF_NODES  (1*NCT)
#define OFF_XLN    (2*NCT)
#define OFF_QKV    (3*NCT)             /* 3 NCT: [n][768][T] */
#define OFF_S      (6*NCT)
#define OFF_RET    (7*NCT)
#define OFF_O      (8*NCT)
#define OFF_KTRVTR (9*NCT)             /* 2 NCT: [n][512][T] */
#define OFF_H      (11*NCT)            /* 4 NCT tf32 */
#define OFF_KEVE   (15*NCT)            /* 8 NCT: 4 layers x [n][512][T] */
#define OFF_RELAY  (23*NCT)
#define OFF_KR     (OFF_RELAY+NC)
#define OFF_VR     (OFF_KR+NC)
#define OFF_QTR    (OFF_VR+NC)
#define OFF_KTRR   (OFF_QTR+NC)
#define OFF_VTRR   (OFF_KTRR+NC)
#define OFF_Z      (OFF_VTRR+NC)
#define OFF_RETT   (OFF_Z+NC)
#define OFF_OTR    (OFF_RETT+NC)
#define OFF_HTR    (OFF_OTR+NC)
#define OFF_MEAN   (OFF_HTR+NTOK*DFFD)
#define OFF_INV    (OFF_MEAN+256)

/* fragment-major tf32 weights */
#define SEGQ       (128*256)                 /* u32 per o_blk, Cin=256 */
#define LQKV       (6*SEGQ)                  /* per-layer combined qkv  */
#define LRKV       (4*SEGQ)
#define LW1        (DFFD*CD)
#define LW2        (CD*DFFD)
#define OFF_QKVW   (OFF_INV+256)
#define OFF_RWKVW  (OFF_QKVW + LQKV*ITER)
#define OFF_W1T    (OFF_RWKVW + LRKV*ITER)
#define OFF_W2T    (OFF_W1T + LW1*ITER)
#define OFF_XLN_T  (OFF_W2T + LW2*ITER)
#define OFF_EMBS_T (OFF_XLN_T + NCT)
#define OFF_RET_T  (OFF_EMBS_T + NCT)
#define OFF_NODES_T (OFF_RET_T + NCT)
#define BUF_TOTAL  (OFF_NODES_T + NCT)

__device__ __align__(16) float g_buf[BUF_TOTAL];

__device__ __forceinline__ uint32_t f2tf32(float x) {
    uint32_t r;
    asm("cvt.rna.tf32.f32 %0, %1;" : "=r"(r) : "f"(x));
    return r;
}

#define MMA_TF32(C, A, B)                                                     \
    asm volatile("mma.sync.aligned.m16n8k8.row.col.f32.tf32.tf32.f32 "        \
                 "{%0,%1,%2,%3}, {%4,%5,%6,%7}, {%8,%9}, {%0,%1,%2,%3};\n"    \
                 : "+f"((C)[0]), "+f"((C)[1]), "+f"((C)[2]), "+f"((C)[3])     \
                 : "r"((A)[0]), "r"((A)[1]), "r"((A)[2]), "r"((A)[3]),        \
                   "r"((B)[0]), "r"((B)[1]));

#define CP16(daddr, src)                                                      \
    asm volatile("cp.async.cg.shared.global [%0], [%1], 16;"                  \
                 :: "r"(daddr), "l"(src))
#define CP_COMMIT asm volatile("cp.async.commit_group;")
#define CP_WAIT(N) asm volatile("cp.async.wait_group %0;" :: "n"(N))

// ---------------------------------------------------------------------------
// Convert W (fp32 [layer][O][Cin]) to fragment-major tf32 at dst offset.
// ---------------------------------------------------------------------------
__global__ void conv_w_frag(const float* __restrict__ W, uint32_t* __restrict__ Wt,
                            int O, int Cin, size_t dl, size_t doff)
{
    size_t sbase = (size_t)blockIdx.y * O * Cin;
    size_t dbase = (size_t)blockIdx.y * dl + doff;
    int idx = blockIdx.x * 256 + threadIdx.x;
    if (idx >= O * Cin) return;
    int NCH = Cin >> 5;
    int j = idx & 3, sl = (idx >> 2) & 31, f = (idx >> 7) & 31;
    int rest = idx >> 12;
    int c = rest % NCH, ob = rest / NCH;
    int r = ob * 128 + (f >> 2) * 16 + (sl >> 2) + ((j & 1) << 3);
    int col = c * 32 + (f & 3) * 8 + (sl & 3) + ((j >> 1) << 2);
    Wt[dbase + idx] = f2tf32(W[sbase + (size_t)r * Cin + col]);
}

// ---------------------------------------------------------------------------
// prep: embs[n,c,t] = data[b,c,v,t], embs_t = tf32(embs), relay = mean_t
// ---------------------------------------------------------------------------
__global__ void prep_kernel(const float* __restrict__ data,
                            float* __restrict__ embs, uint32_t* __restrict__ embs_t,
                            float* __restrict__ relay)
{
    int n = blockIdx.x;
    int b = n / 25, v = n % 25;
    int c = blockIdx.y * 8 + threadIdx.y;
    int tx = threadIdx.x;
    const float* src = data + (((size_t)b * CD + c) * 25 + v) * TD;
    size_t dof = ((size_t)n * CD + c) * TD;
    float s = 0.f;
#pragma unroll
    for (int j = 0; j < 4; j++) {
        int t = tx + 32 * j;
        float x = src[t];
        embs[dof + t] = x;
        embs_t[dof + t] = f2tf32(x);
        s += x;
    }
#pragma unroll
    for (int o = 16; o > 0; o >>= 1) s += __shfl_xor_sync(0xffffffffu, s, o);
    if (tx == 0) relay[n * CD + c] = s * (1.0f / 128.0f);
}

// ---------------------------------------------------------------------------
// LayerNorm over channel dim; writes fp32 + tf32. grid (NTOK,4), block (32,8)
// ---------------------------------------------------------------------------
__global__ void ln_kernel(const float* __restrict__ X, const float* __restrict__ g,
                          const float* __restrict__ b, float* __restrict__ Y,
                          uint32_t* __restrict__ Yt)
{
    int n = blockIdx.x;
    int t = blockIdx.y * 32 + threadIdx.x;
    int tx = threadIdx.x, ty = threadIdx.y;
    float x[32];
    float s1 = 0.f, s2 = 0.f;
#pragma unroll
    for (int j = 0; j < 32; j++) {
        int c = ty + j * 8;
        x[j] = X[((size_t)n * CD + c) * TD + t];
        s1 += x[j];
        s2 += x[j] * x[j];
    }
    __shared__ float sm1[8][32], sm2[8][32], smean[32], sinv[32];
    sm1[ty][tx] = s1; sm2[ty][tx] = s2;
    __syncthreads();
    if (ty == 0) {
        float a = 0.f, bb = 0.f;
#pragma unroll
        for (int qy = 0; qy < 8; qy++) { a += sm1[qy][tx]; bb += sm2[qy][tx]; }
        float m = a * (1.0f / 256.0f);
        float var = bb * (1.0f / 256.0f) - m * m;
        smean[tx] = m;
        sinv[tx] = rsqrtf(var + 1e-6f);
    }
    __syncthreads();
    float m = smean[tx], inv = sinv[tx];
#pragma unroll
    for (int j = 0; j < 32; j++) {
        int c = ty + j * 8;
        float vv = (x[j] - m) * inv * g[c] + b[c];
        size_t off = ((size_t)n * CD + c) * TD + t;
        Y[off] = vv;
        Yt[off] = f2tf32(vv);
    }
}

// ---------------------------------------------------------------------------
// TF32 GEMM, pre-converted operands + cp.async 3-stage pipeline.
// ---------------------------------------------------------------------------
#define XS_STR   132
#define WF_U32   (32 * 128)
#define BUFU     (WF_U32 + 32 * XS_STR)
#define GEMM_SMEM (3 * BUFU * 4)

template <int EPI, int NSEG>
__global__ __launch_bounds__(256, 2)
void gemm_pre(const uint32_t* __restrict__ Wt, const float* __restrict__ b0,
              const float* __restrict__ b1, const float* __restrict__ b2,
              const uint32_t* __restrict__ Xt, void* __restrict__ Yout,
              const float* __restrict__ Res, int O, int Cin,
              size_t wl, size_t yl)
{
    extern __shared__ __align__(16) uint32_t smem_dyn[];
    uint32_t smem_base = (uint32_t)__cvta_generic_to_shared(smem_dyn);

    int n = blockIdx.y;
    int z = blockIdx.z;
    int nchunks = Cin >> 5;
    const uint32_t* Wblk = Wt + (size_t)z * wl + (size_t)blockIdx.x * nchunks * WF_U32;
    const uint32_t* Xn = Xt + (size_t)n * Cin * TD;
    int tid = threadIdx.x;
    int lane = tid & 31, wid = tid >> 5;
    int warp_o = wid >> 2, warp_t = wid & 3;
    int g = lane >> 2, q = lane & 3;

#define ISSUE(c)                                                              \
    do {                                                                      \
        int bsel = (c) % 3;                                                   \
        uint32_t wb = smem_base + bsel * (BUFU * 4);                          \
        uint32_t xb = wb + WF_U32 * 4;                                        \
        const uint32_t* wsrc = Wblk + (size_t)(c) * WF_U32;                   \
        const uint32_t* xsrc = Xn + (size_t)(c) * 32 * TD;                    \
        _Pragma("unroll")                                                     \
        for (int r = 0; r < 4; r++) {                                         \
            int i = tid + 256 * r;                                            \
            CP16(wb + (uint32_t)i * 16, wsrc + i * 4);                        \
            int k = i >> 5, c4 = i & 31;                                      \
            CP16(xb + (uint32_t)(k * XS_STR + c4 * 4) * 4,                    \
                 xsrc + (size_t)k * TD + c4 * 4);                             \
        }                                                                     \
        CP_COMMIT;                                                            \
    } while (0)

    ISSUE(0);
    if (nchunks > 1) ISSUE(1);

    float acc[4][4][4];
#pragma unroll
    for (int m = 0; m < 4; m++)
#pragma unroll
        for (int nf = 0; nf < 4; nf++)
#pragma unroll
            for (int j = 0; j < 4; j++) acc[m][nf][j] = 0.f;

    int cidx = warp_t * 32 + g;
    for (int c = 0; c < nchunks; c++) {
        if (c + 1 < nchunks) { CP_WAIT(1); } else { CP_WAIT(0); }
        __syncthreads();
        if (c + 2 < nchunks) ISSUE(c + 2);

        const uint32_t* Wb = smem_dyn + (c % 3) * BUFU;
        const uint32_t* Xb = Wb + WF_U32;
#pragma unroll
        for (int kt = 0; kt < 4; kt++) {
            uint32_t a[4][4], b[4][2];
#pragma unroll
            for (int m = 0; m < 4; m++) {
                int f = (warp_o * 4 + m) * 4 + kt;
                *(uint4*)a[m] = *(const uint4*)&Wb[f * 128 + lane * 4];
            }
            const uint32_t* xrow0 = &Xb[(kt * 8 + q) * XS_STR + cidx];
            const uint32_t* xrow1 = xrow0 + 4 * XS_STR;
#pragma unroll
            for (int nf = 0; nf < 4; nf++) {
                b[nf][0] = xrow0[nf * 8];
                b[nf][1] = xrow1[nf * 8];
            }
#pragma unroll
            for (int m = 0; m < 4; m++)
#pragma unroll
                for (int nf = 0; nf < 4; nf++)
                    MMA_TF32(acc[m][nf], a[m], b[nf]);
        }
    }
#undef ISSUE

#pragma unroll
    for (int m = 0; m < 4; m++) {
        int obase = blockIdx.x * 128 + warp_o * 64 + m * 16 + g;
#pragma unroll
        for (int r = 0; r < 2; r++) {
            int o = obase + r * 8;
            float bs;
            if (NSEG == 1) {
                bs = b0[o];
            } else {
                int seg = o >> 8;
                const float* bp = (seg == 0) ? b0 : (seg == 1 ? b1 : b2);
                bs = bp[z * 256 + (o & 255)];
            }
            size_t rowoff = (size_t)z * yl + ((size_t)n * O + o) * TD;
#pragma unroll
            for (int nf = 0; nf < 4; nf++) {
                int t = warp_t * 32 + nf * 8 + q * 2;
                float v0 = acc[m][nf][r * 2 + 0] + bs;
                float v1 = acc[m][nf][r * 2 + 1] + bs;
                if (EPI == 1) {
                    v0 = fmaxf(v0, 0.f); v1 = fmaxf(v1, 0.f);
                    uint32_t* yrow = (uint32_t*)Yout + rowoff;
                    yrow[t] = f2tf32(v0);
                    yrow[t + 1] = f2tf32(v1);
                } else {
                    if (EPI == 2) {
                        float2 rr = *(const float2*)(Res + rowoff + t);
                        v0 += rr.x; v1 += rr.y;
                    }
                    *(float2*)((float*)Yout + rowoff + t) = make_float2(v0, v1);
                }
            }
        }
    }
}

// ---------------------------------------------------------------------------
// Small GEMM over [N, Cin] tokens (relay path, fp32). Single weight/out.
// ---------------------------------------------------------------------------
template <int EPI>
__global__ __launch_bounds__(256)
void gemm_nc(const float* __restrict__ W, const float* __restrict__ bias,
             const float* __restrict__ X, float* __restrict__ Y,
             const float* __restrict__ Res, int O, int Cin)
{
    int o0 = blockIdx.x * 64;
    int n0 = blockIdx.y * 32;
    int tid = threadIdx.x;
    int tx = tid & 31, ty = tid >> 5;

    __shared__ float Ws[32][64];
    __shared__ float Xs[32][33];

    float acc[8];
#pragma unroll
    for (int i = 0; i < 8; i++) acc[i] = 0.f;

    for (int k0 = 0; k0 < Cin; k0 += 32) {
#pragma unroll
        for (int r = 0; r < 2; r++) {
            int idx = tid + 256 * r;
            int o = idx >> 3, kq = idx & 7;
            float4 w4 = *(const float4*)(W + (size_t)(o0 + o) * Cin + k0 + kq * 4);
            Ws[kq * 4 + 0][o] = w4.x;
            Ws[kq * 4 + 1][o] = w4.y;
            Ws[kq * 4 + 2][o] = w4.z;
            Ws[kq * 4 + 3][o] = w4.w;
        }
        {
            int nn = tid >> 3, kq = tid & 7;
            int n = n0 + nn;
            float4 x4 = make_float4(0.f, 0.f, 0.f, 0.f);
            if (n < NTOK) x4 = *(const float4*)(X + (size_t)n * Cin + k0 + kq * 4);
            Xs[kq * 4 + 0][nn] = x4.x;
            Xs[kq * 4 + 1][nn] = x4.y;
            Xs[kq * 4 + 2][nn] = x4.z;
            Xs[kq * 4 + 3][nn] = x4.w;
        }
        __syncthreads();
#pragma unroll
        for (int kk = 0; kk < 32; kk++) {
            float bv = Xs[kk][tx];
#pragma unroll
            for (int i = 0; i < 8; i++) acc[i] += Ws[kk][ty * 8 + i] * bv;
        }
        __syncthreads();
    }

    int n = n0 + tx;
    if (n < NTOK) {
#pragma unroll
        for (int i = 0; i < 8; i++) {
            int o = o0 + ty * 8 + i;
            float val = acc[i] + bias[o];
            if (EPI == 1) val = fmaxf(val, 0.f);
            if (EPI == 2) val += Res[(size_t)n * O + o];
            Y[(size_t)n * O + o] = val;
        }
    }
}

// ---------------------------------------------------------------------------
// Segmented small GEMM: up to 3 weight sets of [256][Cin], each with its own
// bias and [N][256] output. Block bx covers global o0 = bx*64 -> seg = o0>>8.
// Per-64-o block arithmetic identical to gemm_nc. grid (nseg*4, 7).
// ---------------------------------------------------------------------------
__global__ __launch_bounds__(256)
void gemm_nc_seg(const float* __restrict__ w0, const float* __restrict__ w1,
                 const float* __restrict__ w2,
                 const float* __restrict__ b0, const float* __restrict__ b1,
                 const float* __restrict__ b2,
                 const float* __restrict__ X,
                 float* __restrict__ y0, float* __restrict__ y1,
                 float* __restrict__ y2, int Cin)
{
    int o0g = blockIdx.x * 64;
    int seg = o0g >> 8;
    const float* W = (seg == 0) ? w0 : (seg == 1 ? w1 : w2);
    const float* bias = (seg == 0) ? b0 : (seg == 1 ? b1 : b2);
    float* Y = (seg == 0) ? y0 : (seg == 1 ? y1 : y2);
    int o0 = o0g & 255;
    int n0 = blockIdx.y * 32;
    int tid = threadIdx.x;
    int tx = tid & 31, ty = tid >> 5;

    __shared__ float Ws[32][64];
    __shared__ float Xs[32][33];

    float acc[8];
#pragma unroll
    for (int i = 0; i < 8; i++) acc[i] = 0.f;

    for (int k0 = 0; k0 < Cin; k0 += 32) {
#pragma unroll
        for (int r = 0; r < 2; r++) {
            int idx = tid + 256 * r;
            int o = idx >> 3, kq = idx & 7;
            float4 w4 = *(const float4*)(W + (size_t)(o0 + o) * Cin + k0 + kq * 4);
            Ws[kq * 4 + 0][o] = w4.x;
            Ws[kq * 4 + 1][o] = w4.y;
            Ws[kq * 4 + 2][o] = w4.z;
            Ws[kq * 4 + 3][o] = w4.w;
        }
        {
            int nn = tid >> 3, kq = tid & 7;
            int n = n0 + nn;
            float4 x4 = make_float4(0.f, 0.f, 0.f, 0.f);
            if (n < NTOK) x4 = *(const float4*)(X + (size_t)n * Cin + k0 + kq * 4);
            Xs[kq * 4 + 0][nn] = x4.x;
            Xs[kq * 4 + 1][nn] = x4.y;
            Xs[kq * 4 + 2][nn] = x4.z;
            Xs[kq * 4 + 3][nn] = x4.w;
        }
        __syncthreads();
#pragma unroll
        for (int kk = 0; kk < 32; kk++) {
            float bv = Xs[kk][tx];
#pragma unroll
            for (int i = 0; i < 8; i++) acc[i] += Ws[kk][ty * 8 + i] * bv;
        }
        __syncthreads();
    }

    int n = n0 + tx;
    if (n < NTOK) {
#pragma unroll
        for (int i = 0; i < 8; i++) {
            int o = o0 + ty * 8 + i;
            Y[(size_t)n * 256 + o] = acc[i] + bias[o];
        }
    }
}

// ---------------------------------------------------------------------------
// tju attention. qkv: [n][768][T]; keve: [n][512][T]. grid NTOK*NHH, block 128.
// ---------------------------------------------------------------------------
__global__ void attn_tju(const float* __restrict__ qkv, const float* __restrict__ keve,
                         const float* __restrict__ kr, const float* __restrict__ vr,
                         const float* __restrict__ xln, float* __restrict__ sout)
{
    int nh = blockIdx.x;
    int n = nh >> 3, h = nh & 7;
    int t = threadIdx.x;
    int rbase = n * CD + h * DKK;
    size_t base = (size_t)rbase * TD;
    size_t bq = ((size_t)n * 768 + h * DKK) * TD;
    size_t bke = ((size_t)n * 512 + h * DKK) * TD;
    const size_t KOFF = (size_t)256 * TD, VOFF = (size_t)512 * TD;

    float l0 = 0.f, l1 = 0.f, l2 = 0.f, l3 = 0.f, l4 = 0.f;
#pragma unroll 8
    for (int d = 0; d < DKK; d++) {
        size_t oq = bq + (size_t)d * TD + t;
        float qd = qkv[oq];
        float kc = qkv[oq + KOFF];
        float km = (t > 0) ? qkv[oq + KOFF - 1] : 0.f;
        float kp = (t < TD - 1) ? qkv[oq + KOFF + 1] : 0.f;
        l0 += qd * km;
        l1 += qd * kc;
        l2 += qd * kp;
        l3 += qd * keve[bke + (size_t)d * TD + t];
        l4 += qd * kr[rbase + d];
    }
    const float sc = 0.17677669529663687f;
    l0 *= sc; l1 *= sc; l2 *= sc; l3 *= sc; l4 *= sc;
    float m = fmaxf(fmaxf(fmaxf(l0, l1), fmaxf(l2, l3)), l4);
    float e0 = expf(l0 - m), e1 = expf(l1 - m), e2 = expf(l2 - m);
    float e3 = expf(l3 - m), e4 = expf(l4 - m);
    float rs = 1.f / (e0 + e1 + e2 + e3 + e4);
    float a0 = e0 * rs, a1 = e1 * rs, a2 = e2 * rs, a3 = e3 * rs, a4 = e4 * rs;

#pragma unroll 8
    for (int d = 0; d < DKK; d++) {
        size_t oq = bq + (size_t)d * TD + t;
        float vc = qkv[oq + VOFF];
        float vm = (t > 0) ? qkv[oq + VOFF - 1] : 0.f;
        float vp = (t < TD - 1) ? qkv[oq + VOFF + 1] : 0.f;
        float att = a0 * vm + a1 * vc + a2 * vp
                  + a3 * keve[bke + KOFF + (size_t)d * TD + t] + a4 * vr[rbase + d];
        sout[base + (size_t)d * TD + t] = xln[base + (size_t)d * TD + t] + att;
    }
}

// ---------------------------------------------------------------------------
// tru attention; ktrvtr: [n][512][T]. grid NTOK (8 heads/block), block 256.
// ---------------------------------------------------------------------------
__global__ void attn_tru(const float* __restrict__ qtr, const float* __restrict__ ktrvtr,
                         const float* __restrict__ ktrr, const float* __restrict__ vtrr,
                         const float* __restrict__ relay, float* __restrict__ z)
{
    __shared__ float sq[8][DKK];
    __shared__ float slog[8][132];
    int wid = threadIdx.x >> 5, lane = threadIdx.x & 31;
    int nh = blockIdx.x * 8 + wid;
    int n = nh >> 3, h = nh & 7;
    int rbase = n * CD + h * DKK;
    size_t bk = ((size_t)n * 512 + h * DKK) * TD;
    const size_t VOFF = (size_t)256 * TD;
    const float sc = 0.17677669529663687f;

    sq[wid][lane] = qtr[rbase + lane];
    __syncwarp();

    float lg[5];
#pragma unroll
    for (int j = 0; j < 5; j++) {
        int l = lane + 32 * j;
        float acc = -1e30f;
        if (l < 129) {
            acc = 0.f;
            if (l == 0) {
#pragma unroll 8
                for (int d = 0; d < DKK; d++) acc += sq[wid][d] * ktrr[rbase + d];
            } else {
                int t = l - 1;
#pragma unroll 8
                for (int d = 0; d < DKK; d++) acc += sq[wid][d] * ktrvtr[bk + (size_t)d * TD + t];
            }
            acc *= sc;
        }
        lg[j] = acc;
    }
    float m = -1e30f;
#pragma unroll
    for (int j = 0; j < 5; j++) m = fmaxf(m, lg[j]);
#pragma unroll
    for (int o = 16; o > 0; o >>= 1) m = fmaxf(m, __shfl_xor_sync(0xffffffffu, m, o));
    float es = 0.f;
#pragma unroll
    for (int j = 0; j < 5; j++) {
        int l = lane + 32 * j;
        if (l < 129) {
            float e = expf(lg[j] - m);
            slog[wid][l] = e;
            es += e;
        }
    }
#pragma unroll
    for (int o = 16; o > 0; o >>= 1) es += __shfl_xor_sync(0xffffffffu, es, o);
    __syncwarp();
    float rinv = 1.f / es;

    int d = lane;
    float att = slog[wid][0] * vtrr[rbase + d];
    const float* vp = ktrvtr + bk + VOFF + (size_t)d * TD;
#pragma unroll 16
    for (int t = 0; t < TD; t++) att += slog[wid][1 + t] * vp[t];
    att *= rinv;
    z[rbase + d] = relay[rbase + d] + att;
}

// ---------------------------------------------------------------------------
// FUSED BatchNorm (stats + affine) over (n,t) per channel.
// One block per channel; stats accumulation identical to the previous
// bn_stats_nct (bit-identical mean/inv), then affine applied in-kernel
// (float4, elementwise math identical). grid 256, block 256.
// ---------------------------------------------------------------------------
__global__ void bn_fused_nct(const float* __restrict__ X, const float* __restrict__ g,
                             const float* __restrict__ b, float* __restrict__ Y,
                             uint32_t* __restrict__ Yt, int leaky, float eps)
{
    int c = blockIdx.x, tid = threadIdx.x;
    float s1 = 0.f, s2 = 0.f;
    for (int i = tid; i < NTOK * TD; i += 256) {
        int n = i >> 7, t = i & 127;
        float x = X[((size_t)n * CD + c) * TD + t];
        s1 += x;
        s2 += x * x;
    }
    __shared__ double d1[256], d2[256];
    d1[tid] = s1; d2[tid] = s2;
    __syncthreads();
    for (int s = 128; s > 0; s >>= 1) {
        if (tid < s) { d1[tid] += d1[tid + s]; d2[tid] += d2[tid + s]; }
        __syncthreads();
    }
    __shared__ float smean, sinv;
    if (tid == 0) {
        double mm = d1[0] / (NTOK * TD);
        double var = d2[0] / (NTOK * TD) - mm * mm;
        smean = (float)mm;
        sinv = rsqrtf((float)var + eps);
    }
    __syncthreads();
    float mean = smean, inv = sinv, gg = g[c], bb = b[c];

    for (int i = tid * 4; i < NTOK * TD; i += 1024) {
        int n = i >> 7, t = i & 127;
        size_t off = ((size_t)n * CD + c) * TD + t;
        float4 x4 = *(const float4*)(X + off);
        float v0 = (x4.x - mean) * inv * gg + bb;
        float v1 = (x4.y - mean) * inv * gg + bb;
        float v2 = (x4.z - mean) * inv * gg + bb;
        float v3 = (x4.w - mean) * inv * gg + bb;
        if (leaky) {
            if (v0 < 0.f) v0 *= 0.01f;
            if (v1 < 0.f) v1 *= 0.01f;
            if (v2 < 0.f) v2 *= 0.01f;
            if (v3 < 0.f) v3 *= 0.01f;
        }
        *(float4*)(Y + off) = make_float4(v0, v1, v2, v3);
        if (Yt) {
            uint4 u;
            u.x = f2tf32(v0); u.y = f2tf32(v1);
            u.z = f2tf32(v2); u.w = f2tf32(v3);
            *(uint4*)(Yt + off) = u;
        }
    }
}

// Fused BN over n per channel ([N,C]). grid 256, block 256.
__global__ void bn_fused_nc(const float* __restrict__ X, const float* __restrict__ g,
                            const float* __restrict__ b, float* __restrict__ Y,
                            int leaky, float eps)
{
    int c = blockIdx.x, tid = threadIdx.x;
    float s1 = 0.f, s2 = 0.f;
    for (int n = tid; n < NTOK; n += 256) {
        float x = X[(size_t)n * CD + c];
        s1 += x;
        s2 += x * x;
    }
    __shared__ double d1[256], d2[256];
    d1[tid] = s1; d2[tid] = s2;
    __syncthreads();
    for (int s = 128; s > 0; s >>= 1) {
        if (tid < s) { d1[tid] += d1[tid + s]; d2[tid] += d2[tid + s]; }
        __syncthreads();
    }
    __shared__ float smean, sinv;
    if (tid == 0) {
        double mm = d1[0] / NTOK;
        double var = d2[0] / NTOK - mm * mm;
        smean = (float)mm;
        sinv = rsqrtf((float)var + eps);
    }
    __syncthreads();
    float mean = smean, inv = sinv, gg = g[c], bb = b[c];
    for (int n = tid; n < NTOK; n += 256) {
        float vv = (X[(size_t)n * CD + c] - mean) * inv * gg + bb;
        if (leaky && vv < 0.f) vv *= 0.01f;
        Y[(size_t)n * CD + c] = vv;
    }
}

// ---------------------------------------------------------------------------
extern "C" void kernel_launch(void* const* d_in, const int* in_sizes, int n_in,
                              void* d_out, int out_size)
{
    (void)in_sizes; (void)n_in; (void)out_size;
    const float* data    = (const float*)d_in[0];
    const float* ln_g    = (const float*)d_in[1];
    const float* ln_b    = (const float*)d_in[2];
    const float* tj_wq   = (const float*)d_in[3];
    const float* tj_bq   = (const float*)d_in[4];
    const float* tj_wk   = (const float*)d_in[5];
    const float* tj_bk   = (const float*)d_in[6];
    const float* tj_wv   = (const float*)d_in[7];
    const float* tj_bv   = (const float*)d_in[8];
    const float* tj_bng  = (const float*)d_in[9];
    const float* tj_bnb  = (const float*)d_in[10];
    const float* tj_w1   = (const float*)d_in[11];
    const float* tj_b1   = (const float*)d_in[12];
    const float* tj_w2   = (const float*)d_in[13];
    const float* tj_b2   = (const float*)d_in[14];
    const float* tj_fg   = (const float*)d_in[15];
    const float* tj_fb   = (const float*)d_in[16];
    const float* tr_wq   = (const float*)d_in[17];
    const float* tr_bq   = (const float*)d_in[18];
    const float* tr_wk   = (const float*)d_in[19];
    const float* tr_bk   = (const float*)d_in[20];
    const float* tr_wv   = (const float*)d_in[21];
    const float* tr_bv   = (const float*)d_in[22];
    const float* tr_bng  = (const float*)d_in[23];
    const float* tr_bnb  = (const float*)d_in[24];
    const float* tr_w1   = (const float*)d_in[25];
    const float* tr_b1   = (const float*)d_in[26];
    const float* tr_w2   = (const float*)d_in[27];
    const float* tr_b2   = (const float*)d_in[28];
    const float* tr_fg   = (const float*)d_in[29];
    const float* tr_fb   = (const float*)d_in[30];

    float* buf = nullptr;
    cudaGetSymbolAddress((void**)&buf, g_buf);

    float* embs   = buf + OFF_EMBS;
    float* nodes  = buf + OFF_NODES;
    float* xln    = buf + OFF_XLN;
    float* qkvb   = buf + OFF_QKV;
    float* sb     = buf + OFF_S;
    float* retb   = buf + OFF_RET;
    float* ob     = buf + OFF_O;
    float* ktrvtrb = buf + OFF_KTRVTR;
    uint32_t* hb  = (uint32_t*)(buf + OFF_H);
    float* keveb  = buf + OFF_KEVE;
    float* relay  = buf + OFF_RELAY;
    float* krb    = buf + OFF_KR;
    float* vrb    = buf + OFF_VR;
    float* qtrb   = buf + OFF_QTR;
    float* ktrr   = buf + OFF_KTRR;
    float* vtrr   = buf + OFF_VTRR;
    float* zb     = buf + OFF_Z;
    float* rettb  = buf + OFF_RETT;
    float* otrb   = buf + OFF_OTR;
    float* htrb   = buf + OFF_HTR;

    uint32_t* qkvw  = (uint32_t*)(buf + OFF_QKVW);
    uint32_t* rwkvw = (uint32_t*)(buf + OFF_RWKVW);
    uint32_t* w1_t  = (uint32_t*)(buf + OFF_W1T);
    uint32_t* w2_t  = (uint32_t*)(buf + OFF_W2T);
    uint32_t* xln_t   = (uint32_t*)(buf + OFF_XLN_T);
    uint32_t* embs_t  = (uint32_t*)(buf + OFF_EMBS_T);
    uint32_t* ret_t   = (uint32_t*)(buf + OFF_RET_T);
    uint32_t* nodes_t = (uint32_t*)(buf + OFF_NODES_T);

    cudaFuncSetAttribute(gemm_pre<0,3>, cudaFuncAttributeMaxDynamicSharedMemorySize, GEMM_SMEM);
    cudaFuncSetAttribute(gemm_pre<0,2>, cudaFuncAttributeMaxDynamicSharedMemorySize, GEMM_SMEM);
    cudaFuncSetAttribute(gemm_pre<1,1>, cudaFuncAttributeMaxDynamicSharedMemorySize, GEMM_SMEM);
    cudaFuncSetAttribute(gemm_pre<2,1>, cudaFuncAttributeMaxDynamicSharedMemorySize, GEMM_SMEM);

    // weight conversion into combined fragment-major layouts
    conv_w_frag<<<dim3(CD * CD / 256, ITER), 256>>>(tj_wq, qkvw, CD, CD, LQKV, 0);
    conv_w_frag<<<dim3(CD * CD / 256, ITER), 256>>>(tj_wk, qkvw, CD, CD, LQKV, 2 * SEGQ);
    conv_w_frag<<<dim3(CD * CD / 256, ITER), 256>>>(tj_wv, qkvw, CD, CD, LQKV, 4 * SEGQ);
    conv_w_frag<<<dim3(CD * CD / 256, ITER), 256>>>(tr_wk, rwkvw, CD, CD, LRKV, 0);
    conv_w_frag<<<dim3(CD * CD / 256, ITER), 256>>>(tr_wv, rwkvw, CD, CD, LRKV, 2 * SEGQ);
    conv_w_frag<<<dim3(DFFD * CD / 256, ITER), 256>>>(tj_w1, w1_t, DFFD, CD, LW1, 0);
    conv_w_frag<<<dim3(DFFD * CD / 256, ITER), 256>>>(tj_w2, w2_t, CD, DFFD, LW2, 0);

    prep_kernel<<<dim3(NTOK, 32), dim3(32, 8)>>>(data, embs, embs_t, relay);

    // all 4 layers' ke/ve from embs (layer-batched)
    gemm_pre<0,2><<<dim3(4, NTOK, ITER), 256, GEMM_SMEM>>>(
        qkvw + 2 * SEGQ, tj_bk, tj_bv, nullptr, embs_t, keveb, nullptr,
        512, CD, (size_t)LQKV, (size_t)NTOK * 512 * TD);

    for (int i = 0; i < ITER; i++) {
        const float* nodes_in = (i == 0) ? embs : nodes;
        ln_kernel<<<dim3(NTOK, 4), dim3(32, 8)>>>(nodes_in, ln_g + i * CD, ln_b + i * CD,
                                                  xln, xln_t);

        // fused QKV (O=768)
        gemm_pre<0,3><<<dim3(6, NTOK, 1), 256, GEMM_SMEM>>>(
            qkvw + (size_t)i * LQKV, tj_bq + i * CD, tj_bk + i * CD, tj_bv + i * CD,
            xln_t, qkvb, nullptr, 768, CD, 0, 0);
        // kr + vr in one segmented launch
        gemm_nc_seg<<<dim3(8, 7), 256>>>(
            tj_wk + (size_t)i * CD * CD, tj_wv + (size_t)i * CD * CD, nullptr,
            tj_bk + i * CD, tj_bv + i * CD, nullptr,
            relay, krb, vrb, nullptr, CD);

        attn_tju<<<NTOK * NHH, 128>>>(qkvb, keveb + (size_t)i * NTOK * 512 * TD,
                                      krb, vrb, xln, sb);

        bn_fused_nct<<<256, 256>>>(sb, tj_bng + i * CD, tj_bnb + i * CD,
                                   retb, ret_t, 0, 1e-5f);

        gemm_pre<1,1><<<dim3(8, NTOK, 1), 256, GEMM_SMEM>>>(
            w1_t + (size_t)i * LW1, tj_b1 + i * DFFD, nullptr, nullptr,
            ret_t, (void*)hb, nullptr, DFFD, CD, 0, 0);
        gemm_pre<2,1><<<dim3(2, NTOK, 1), 256, GEMM_SMEM>>>(
            w2_t + (size_t)i * LW2, tj_b2 + i * CD, nullptr, nullptr,
            hb, ob, retb, CD, DFFD, 0, 0);

        float* nodes_out = (i == ITER - 1) ? (float*)d_out : nodes;
        uint32_t* nodes_out_t = (i == ITER - 1) ? nullptr : nodes_t;
        bn_fused_nct<<<256, 256>>>(ob, tj_fg + i * CD, tj_fb + i * CD,
                                   nodes_out, nodes_out_t, 1, 1e-5f);

        if (i < ITER - 1) {
            // qtr + ktrr + vtrr in one segmented launch
            gemm_nc_seg<<<dim3(12, 7), 256>>>(
                tr_wq + (size_t)i * CD * CD, tr_wk + (size_t)i * CD * CD,
                tr_wv + (size_t)i * CD * CD,
                tr_bq + i * CD, tr_bk + i * CD, tr_bv + i * CD,
                relay, qtrb, ktrr, vtrr, CD);
            // fused ktr/vtr (O=512)
            gemm_pre<0,2><<<dim3(4, NTOK, 1), 256, GEMM_SMEM>>>(
                rwkvw + (size_t)i * LRKV, tr_bk + i * CD, tr_bv + i * CD, nullptr,
                nodes_t, ktrvtrb, nullptr, 512, CD, 0, 0);

            attn_tru<<<NTOK, 256>>>(qtrb, ktrvtrb, ktrr, vtrr, relay, zb);

            bn_fused_nc<<<256, 256>>>(zb, tr_bng + i * CD, tr_bnb + i * CD,
                                      rettb, 0, 1e-5f);

            gemm_nc<1><<<dim3(16, 7), 256>>>(tr_w1 + (size_t)i * DFFD * CD, tr_b1 + i * DFFD,
                                             rettb, htrb, nullptr, DFFD, CD);
            gemm_nc<2><<<dim3(4, 7), 256>>>(tr_w2 + (size_t)i * CD * DFFD, tr_b2 + i * CD,
                                            htrb, otrb, rettb, CD, DFFD);

            bn_fused_nc<<<256, 256>>>(otrb, tr_fg + i * CD, tr_fb + i * CD,
                                      relay, 1, 1e-5f);
        }
    }
}

// round 15
// speedup vs baseline: 2.9359x; 1.0118x over previous
#include <cuda_runtime.h>
#include <math.h>
#include <stdint.h>

#define NTOK 200
#define CD   256
#define TD   128
#define NHH  8
#define DKK  32
#define DFFD 1024
#define ITER 4
#define NCT  (NTOK*CD*TD)
#define NC   (NTOK*CD)

#define OFF_EMBS   0
#define OFF_NODES  (1*NCT)
#define OFF_XLN    (2*NCT)
#define OFF_QKV    (3*NCT)             /* 3 NCT: [n][768][T] */
#define OFF_S      (6*NCT)
#define OFF_RET    (7*NCT)
#define OFF_O      (8*NCT)
#define OFF_KTRVTR (9*NCT)             /* 2 NCT: [n][512][T] */
#define OFF_H      (11*NCT)            /* 4 NCT tf32 */
#define OFF_KEVE   (15*NCT)            /* 8 NCT: 4 layers x [n][512][T] */
#define OFF_RELAY  (23*NCT)
#define OFF_KR     (OFF_RELAY+NC)
#define OFF_VR     (OFF_KR+NC)
#define OFF_QTR    (OFF_VR+NC)
#define OFF_KTRR   (OFF_QTR+NC)
#define OFF_VTRR   (OFF_KTRR+NC)
#define OFF_Z      (OFF_VTRR+NC)
#define OFF_RETT   (OFF_Z+NC)
#define OFF_OTR    (OFF_RETT+NC)
#define OFF_HTR    (OFF_OTR+NC)
#define OFF_MEAN   (OFF_HTR+NTOK*DFFD)
#define OFF_INV    (OFF_MEAN+256)

/* fragment-major tf32 weights */
#define SEGQ       (128*256)
#define LQKV       (6*SEGQ)
#define LRKV       (4*SEGQ)
#define LW1        (DFFD*CD)
#define LW2        (CD*DFFD)
#define OFF_QKVW   (OFF_INV+256)
#define OFF_RWKVW  (OFF_QKVW + LQKV*ITER)
#define OFF_W1T    (OFF_RWKVW + LRKV*ITER)
#define OFF_W2T    (OFF_W1T + LW1*ITER)
#define OFF_XLN_T  (OFF_W2T + LW2*ITER)
#define OFF_EMBS_T (OFF_XLN_T + NCT)
#define OFF_RET_T  (OFF_EMBS_T + NCT)
#define OFF_NODES_T (OFF_RET_T + NCT)
#define BUF_TOTAL  (OFF_NODES_T + NCT)

__device__ __align__(16) float g_buf[BUF_TOTAL];
__device__ int g_bar = 0, g_done = 0;

__device__ __forceinline__ uint32_t f2tf32(float x) {
    uint32_t r;
    asm("cvt.rna.tf32.f32 %0, %1;" : "=r"(r) : "f"(x));
    return r;
}

#define MMA_TF32(C, A, B)                                                     \
    asm volatile("mma.sync.aligned.m16n8k8.row.col.f32.tf32.tf32.f32 "        \
                 "{%0,%1,%2,%3}, {%4,%5,%6,%7}, {%8,%9}, {%0,%1,%2,%3};\n"    \
                 : "+f"((C)[0]), "+f"((C)[1]), "+f"((C)[2]), "+f"((C)[3])     \
                 : "r"((A)[0]), "r"((A)[1]), "r"((A)[2]), "r"((A)[3]),        \
                   "r"((B)[0]), "r"((B)[1]));

#define CP16(daddr, src)                                                      \
    asm volatile("cp.async.cg.shared.global [%0], [%1], 16;"                  \
                 :: "r"(daddr), "l"(src))
#define CP_COMMIT asm volatile("cp.async.commit_group;")
#define CP_WAIT(N) asm volatile("cp.async.wait_group %0;" :: "n"(N))

// ---------------------------------------------------------------------------
// Convert W (fp32 [layer][O][Cin]) to fragment-major tf32 at dst offset.
// ---------------------------------------------------------------------------
__global__ void conv_w_frag(const float* __restrict__ W, uint32_t* __restrict__ Wt,
                            int O, int Cin, size_t dl, size_t doff)
{
    size_t sbase = (size_t)blockIdx.y * O * Cin;
    size_t dbase = (size_t)blockIdx.y * dl + doff;
    int idx = blockIdx.x * 256 + threadIdx.x;
    if (idx >= O * Cin) return;
    int NCH = Cin >> 5;
    int j = idx & 3, sl = (idx >> 2) & 31, f = (idx >> 7) & 31;
    int rest = idx >> 12;
    int c = rest % NCH, ob = rest / NCH;
    int r = ob * 128 + (f >> 2) * 16 + (sl >> 2) + ((j & 1) << 3);
    int col = c * 32 + (f & 3) * 8 + (sl & 3) + ((j >> 1) << 2);
    Wt[dbase + idx] = f2tf32(W[sbase + (size_t)r * Cin + col]);
}

// ---------------------------------------------------------------------------
// prep
// ---------------------------------------------------------------------------
__global__ void prep_kernel(const float* __restrict__ data,
                            float* __restrict__ embs, uint32_t* __restrict__ embs_t,
                            float* __restrict__ relay)
{
    int n = blockIdx.x;
    int b = n / 25, v = n % 25;
    int c = blockIdx.y * 8 + threadIdx.y;
    int tx = threadIdx.x;
    const float* src = data + (((size_t)b * CD + c) * 25 + v) * TD;
    size_t dof = ((size_t)n * CD + c) * TD;
    float s = 0.f;
#pragma unroll
    for (int j = 0; j < 4; j++) {
        int t = tx + 32 * j;
        float x = src[t];
        embs[dof + t] = x;
        embs_t[dof + t] = f2tf32(x);
        s += x;
    }
#pragma unroll
    for (int o = 16; o > 0; o >>= 1) s += __shfl_xor_sync(0xffffffffu, s, o);
    if (tx == 0) relay[n * CD + c] = s * (1.0f / 128.0f);
}

// ---------------------------------------------------------------------------
// LayerNorm; writes fp32 + tf32. grid (NTOK,4), block (32,8)
// ---------------------------------------------------------------------------
__global__ void ln_kernel(const float* __restrict__ X, const float* __restrict__ g,
                          const float* __restrict__ b, float* __restrict__ Y,
                          uint32_t* __restrict__ Yt)
{
    int n = blockIdx.x;
    int t = blockIdx.y * 32 + threadIdx.x;
    int tx = threadIdx.x, ty = threadIdx.y;
    float x[32];
    float s1 = 0.f, s2 = 0.f;
#pragma unroll
    for (int j = 0; j < 32; j++) {
        int c = ty + j * 8;
        x[j] = X[((size_t)n * CD + c) * TD + t];
        s1 += x[j];
        s2 += x[j] * x[j];
    }
    __shared__ float sm1[8][32], sm2[8][32], smean[32], sinv[32];
    sm1[ty][tx] = s1; sm2[ty][tx] = s2;
    __syncthreads();
    if (ty == 0) {
        float a = 0.f, bb = 0.f;
#pragma unroll
        for (int qy = 0; qy < 8; qy++) { a += sm1[qy][tx]; bb += sm2[qy][tx]; }
        float m = a * (1.0f / 256.0f);
        float var = bb * (1.0f / 256.0f) - m * m;
        smean[tx] = m;
        sinv[tx] = rsqrtf(var + 1e-6f);
    }
    __syncthreads();
    float m = smean[tx], inv = sinv[tx];
#pragma unroll
    for (int j = 0; j < 32; j++) {
        int c = ty + j * 8;
        float vv = (x[j] - m) * inv * g[c] + b[c];
        size_t off = ((size_t)n * CD + c) * TD + t;
        Y[off] = vv;
        Yt[off] = f2tf32(vv);
    }
}

// ---------------------------------------------------------------------------
// TF32 GEMM, pre-converted operands + cp.async 3-stage pipeline.
// ---------------------------------------------------------------------------
#define XS_STR   132
#define WF_U32   (32 * 128)
#define BUFU     (WF_U32 + 32 * XS_STR)
#define GEMM_SMEM (3 * BUFU * 4)

template <int EPI, int NSEG>
__global__ __launch_bounds__(256, 2)
void gemm_pre(const uint32_t* __restrict__ Wt, const float* __restrict__ b0,
              const float* __restrict__ b1, const float* __restrict__ b2,
              const uint32_t* __restrict__ Xt, void* __restrict__ Yout,
              const float* __restrict__ Res, int O, int Cin,
              size_t wl, size_t yl)
{
    extern __shared__ __align__(16) uint32_t smem_dyn[];
    uint32_t smem_base = (uint32_t)__cvta_generic_to_shared(smem_dyn);

    int n = blockIdx.y;
    int z = blockIdx.z;
    int nchunks = Cin >> 5;
    const uint32_t* Wblk = Wt + (size_t)z * wl + (size_t)blockIdx.x * nchunks * WF_U32;
    const uint32_t* Xn = Xt + (size_t)n * Cin * TD;
    int tid = threadIdx.x;
    int lane = tid & 31, wid = tid >> 5;
    int warp_o = wid >> 2, warp_t = wid & 3;
    int g = lane >> 2, q = lane & 3;

#define ISSUE(c)                                                              \
    do {                                                                      \
        int bsel = (c) % 3;                                                   \
        uint32_t wb = smem_base + bsel * (BUFU * 4);                          \
        uint32_t xb = wb + WF_U32 * 4;                                        \
        const uint32_t* wsrc = Wblk + (size_t)(c) * WF_U32;                   \
        const uint32_t* xsrc = Xn + (size_t)(c) * 32 * TD;                    \
        _Pragma("unroll")                                                     \
        for (int r = 0; r < 4; r++) {                                         \
            int i = tid + 256 * r;                                            \
            CP16(wb + (uint32_t)i * 16, wsrc + i * 4);                        \
            int k = i >> 5, c4 = i & 31;                                      \
            CP16(xb + (uint32_t)(k * XS_STR + c4 * 4) * 4,                    \
                 xsrc + (size_t)k * TD + c4 * 4);                             \
        }                                                                     \
        CP_COMMIT;                                                            \
    } while (0)

    ISSUE(0);
    if (nchunks > 1) ISSUE(1);

    float acc[4][4][4];
#pragma unroll
    for (int m = 0; m < 4; m++)
#pragma unroll
        for (int nf = 0; nf < 4; nf++)
#pragma unroll
            for (int j = 0; j < 4; j++) acc[m][nf][j] = 0.f;

    int cidx = warp_t * 32 + g;
    for (int c = 0; c < nchunks; c++) {
        if (c + 1 < nchunks) { CP_WAIT(1); } else { CP_WAIT(0); }
        __syncthreads();
        if (c + 2 < nchunks) ISSUE(c + 2);

        const uint32_t* Wb = smem_dyn + (c % 3) * BUFU;
        const uint32_t* Xb = Wb + WF_U32;
#pragma unroll
        for (int kt = 0; kt < 4; kt++) {
            uint32_t a[4][4], b[4][2];
#pragma unroll
            for (int m = 0; m < 4; m++) {
                int f = (warp_o * 4 + m) * 4 + kt;
                *(uint4*)a[m] = *(const uint4*)&Wb[f * 128 + lane * 4];
            }
            const uint32_t* xrow0 = &Xb[(kt * 8 + q) * XS_STR + cidx];
            const uint32_t* xrow1 = xrow0 + 4 * XS_STR;
#pragma unroll
            for (int nf = 0; nf < 4; nf++) {
                b[nf][0] = xrow0[nf * 8];
                b[nf][1] = xrow1[nf * 8];
            }
#pragma unroll
            for (int m = 0; m < 4; m++)
#pragma unroll
                for (int nf = 0; nf < 4; nf++)
                    MMA_TF32(acc[m][nf], a[m], b[nf]);
        }
    }
#undef ISSUE

#pragma unroll
    for (int m = 0; m < 4; m++) {
        int obase = blockIdx.x * 128 + warp_o * 64 + m * 16 + g;
#pragma unroll
        for (int r = 0; r < 2; r++) {
            int o = obase + r * 8;
            float bs;
            if (NSEG == 1) {
                bs = b0[o];
            } else {
                int seg = o >> 8;
                const float* bp = (seg == 0) ? b0 : (seg == 1 ? b1 : b2);
                bs = bp[z * 256 + (o & 255)];
            }
            size_t rowoff = (size_t)z * yl + ((size_t)n * O + o) * TD;
#pragma unroll
            for (int nf = 0; nf < 4; nf++) {
                int t = warp_t * 32 + nf * 8 + q * 2;
                float v0 = acc[m][nf][r * 2 + 0] + bs;
                float v1 = acc[m][nf][r * 2 + 1] + bs;
                if (EPI == 1) {
                    v0 = fmaxf(v0, 0.f); v1 = fmaxf(v1, 0.f);
                    uint2 uu;
                    uu.x = f2tf32(v0); uu.y = f2tf32(v1);
                    *(uint2*)((uint32_t*)Yout + rowoff + t) = uu;
                } else {
                    if (EPI == 2) {
                        float2 rr = *(const float2*)(Res + rowoff + t);
                        v0 += rr.x; v1 += rr.y;
                    }
                    *(float2*)((float*)Yout + rowoff + t) = make_float2(v0, v1);
                }
            }
        }
    }
}

// ---------------------------------------------------------------------------
// Device small-GEMM core over [N, Cin] tokens (identical math to gemm_nc).
// smem_raw layout: Ws 32x64 floats (8192 B) then Xs 32x33 floats (4224 B).
// ---------------------------------------------------------------------------
template <int EPI>
__device__ void dev_gemm_nc(char* smem_raw,
                            const float* __restrict__ W, const float* __restrict__ bias,
                            const float* __restrict__ X, float* __restrict__ Y,
                            const float* __restrict__ Res, int O, int Cin,
                            int o0, int n0)
{
    float (*Ws)[64] = (float(*)[64])smem_raw;
    float (*Xs)[33] = (float(*)[33])(smem_raw + 8192);
    int tid = threadIdx.x;
    int tx = tid & 31, ty = tid >> 5;

    float acc[8];
#pragma unroll
    for (int i = 0; i < 8; i++) acc[i] = 0.f;

    for (int k0 = 0; k0 < Cin; k0 += 32) {
#pragma unroll
        for (int r = 0; r < 2; r++) {
            int idx = tid + 256 * r;
            int o = idx >> 3, kq = idx & 7;
            float4 w4 = *(const float4*)(W + (size_t)(o0 + o) * Cin + k0 + kq * 4);
            Ws[kq * 4 + 0][o] = w4.x;
            Ws[kq * 4 + 1][o] = w4.y;
            Ws[kq * 4 + 2][o] = w4.z;
            Ws[kq * 4 + 3][o] = w4.w;
        }
        {
            int nn = tid >> 3, kq = tid & 7;
            int n = n0 + nn;
            float4 x4 = make_float4(0.f, 0.f, 0.f, 0.f);
            if (n < NTOK) x4 = *(const float4*)(X + (size_t)n * Cin + k0 + kq * 4);
            Xs[kq * 4 + 0][nn] = x4.x;
            Xs[kq * 4 + 1][nn] = x4.y;
            Xs[kq * 4 + 2][nn] = x4.z;
            Xs[kq * 4 + 3][nn] = x4.w;
        }
        __syncthreads();
#pragma unroll
        for (int kk = 0; kk < 32; kk++) {
            float bv = Xs[kk][tx];
#pragma unroll
            for (int i = 0; i < 8; i++) acc[i] += Ws[kk][ty * 8 + i] * bv;
        }
        __syncthreads();
    }

    int n = n0 + tx;
    if (n < NTOK) {
#pragma unroll
        for (int i = 0; i < 8; i++) {
            int o = o0 + ty * 8 + i;
            float val = acc[i] + bias[o];
            if (EPI == 1) val = fmaxf(val, 0.f);
            if (EPI == 2) val += Res[(size_t)n * O + o];
            Y[(size_t)n * O + o] = val;
        }
    }
}

// ---------------------------------------------------------------------------
// Standalone segmented small GEMM (kr/vr path, unchanged).
// ---------------------------------------------------------------------------
__global__ __launch_bounds__(256)
void gemm_nc_seg(const float* __restrict__ w0, const float* __restrict__ w1,
                 const float* __restrict__ b0, const float* __restrict__ b1,
                 const float* __restrict__ X,
                 float* __restrict__ y0, float* __restrict__ y1, int Cin)
{
    __shared__ char smem_raw[12416];
    int o0g = blockIdx.x * 64;
    int seg = o0g >> 8;
    const float* W = (seg == 0) ? w0 : w1;
    const float* bias = (seg == 0) ? b0 : b1;
    float* Y = (seg == 0) ? y0 : y1;
    dev_gemm_nc<0>(smem_raw, W, bias, X, Y, nullptr, 256, Cin, o0g & 255,
                   blockIdx.y * 32);
}

// ---------------------------------------------------------------------------
// Device attn_tru (identical math). smem_raw: sq 8x32 (1024B), slog 8x132 (4224B)
// ---------------------------------------------------------------------------
__device__ void dev_attn_tru(char* smem_raw,
                             const float* __restrict__ qtr, const float* __restrict__ ktrvtr,
                             const float* __restrict__ ktrr, const float* __restrict__ vtrr,
                             const float* __restrict__ relay, float* __restrict__ z, int nblk)
{
    float (*sq)[DKK] = (float(*)[DKK])smem_raw;
    float (*slog)[132] = (float(*)[132])(smem_raw + 1024);
    int wid = threadIdx.x >> 5, lane = threadIdx.x & 31;
    int n = nblk, h = wid;
    int rbase = n * CD + h * DKK;
    size_t bk = ((size_t)n * 512 + h * DKK) * TD;
    const size_t VOFF = (size_t)256 * TD;
    const float sc = 0.17677669529663687f;

    sq[wid][lane] = qtr[rbase + lane];
    __syncwarp();

    float lg[5];
#pragma unroll
    for (int j = 0; j < 5; j++) {
        int l = lane + 32 * j;
        float acc = -1e30f;
        if (l < 129) {
            acc = 0.f;
            if (l == 0) {
#pragma unroll 8
                for (int d = 0; d < DKK; d++) acc += sq[wid][d] * ktrr[rbase + d];
            } else {
                int t = l - 1;
#pragma unroll 8
                for (int d = 0; d < DKK; d++) acc += sq[wid][d] * ktrvtr[bk + (size_t)d * TD + t];
            }
            acc *= sc;
        }
        lg[j] = acc;
    }
    float m = -1e30f;
#pragma unroll
    for (int j = 0; j < 5; j++) m = fmaxf(m, lg[j]);
#pragma unroll
    for (int o = 16; o > 0; o >>= 1) m = fmaxf(m, __shfl_xor_sync(0xffffffffu, m, o));
    float es = 0.f;
#pragma unroll
    for (int j = 0; j < 5; j++) {
        int l = lane + 32 * j;
        if (l < 129) {
            float e = expf(lg[j] - m);
            slog[wid][l] = e;
            es += e;
        }
    }
#pragma unroll
    for (int o = 16; o > 0; o >>= 1) es += __shfl_xor_sync(0xffffffffu, es, o);
    __syncwarp();
    float rinv = 1.f / es;

    int d = lane;
    float att = slog[wid][0] * vtrr[rbase + d];
    const float* vp = ktrvtr + bk + VOFF + (size_t)d * TD;
#pragma unroll 16
    for (int t = 0; t < TD; t++) att += slog[wid][1 + t] * vp[t];
    att *= rinv;
    z[rbase + d] = relay[rbase + d] + att;
}

// ---------------------------------------------------------------------------
// Device fused BN over n per channel (identical math to bn_fused_nc).
// smem_raw: d1[256] doubles (2048B), d2[256] doubles (2048B), mean/inv.
// ---------------------------------------------------------------------------
__device__ void dev_bn_nc(char* smem_raw,
                          const float* __restrict__ X, const float* __restrict__ g,
                          const float* __restrict__ b, float* __restrict__ Y,
                          int leaky, float eps, int c)
{
    double* d1 = (double*)smem_raw;
    double* d2 = (double*)(smem_raw + 2048);
    float* sm = (float*)(smem_raw + 4096);
    int tid = threadIdx.x;
    float s1 = 0.f, s2 = 0.f;
    for (int n = tid; n < NTOK; n += 256) {
        float x = X[(size_t)n * CD + c];
        s1 += x;
        s2 += x * x;
    }
    d1[tid] = s1; d2[tid] = s2;
    __syncthreads();
    for (int s = 128; s > 0; s >>= 1) {
        if (tid < s) { d1[tid] += d1[tid + s]; d2[tid] += d2[tid + s]; }
        __syncthreads();
    }
    if (tid == 0) {
        double mm = d1[0] / NTOK;
        double var = d2[0] / NTOK - mm * mm;
        sm[0] = (float)mm;
        sm[1] = rsqrtf((float)var + eps);
    }
    __syncthreads();
    float mean = sm[0], inv = sm[1], gg = g[c], bb = b[c];
    for (int n = tid; n < NTOK; n += 256) {
        float vv = (X[(size_t)n * CD + c] - mean) * inv * gg + bb;
        if (leaky && vv < 0.f) vv *= 0.01f;
        Y[(size_t)n * CD + c] = vv;
    }
}

// ---------------------------------------------------------------------------
// Software grid barrier (all 256 blocks guaranteed co-resident).
// ---------------------------------------------------------------------------
__device__ __forceinline__ void grid_bar(int target)
{
    __syncthreads();
    __threadfence();
    if (threadIdx.x == 0) {
        atomicAdd(&g_bar, 1);
        while (atomicAdd(&g_bar, 0) < target) { }
    }
    __syncthreads();
}

// ---------------------------------------------------------------------------
// FUSED relay chain: seg-GEMM (qtr/ktrr/vtrr) -> attn_tru -> BN -> FFN w1 ->
// FFN w2 -> BN. grid 256 x 256 threads. Phase bodies identical to the
// standalone kernels -> bit-identical numerics.
// ---------------------------------------------------------------------------
__global__ __launch_bounds__(256)
void relay_chain(const float* __restrict__ rwq, const float* __restrict__ rwk,
                 const float* __restrict__ rwv,
                 const float* __restrict__ rbq, const float* __restrict__ rbk,
                 const float* __restrict__ rbv,
                 float* __restrict__ relay, float* __restrict__ qtrb,
                 float* __restrict__ ktrr, float* __restrict__ vtrr,
                 const float* __restrict__ ktrvtrb,
                 float* __restrict__ zb, float* __restrict__ rettb,
                 float* __restrict__ htrb, float* __restrict__ otrb,
                 const float* __restrict__ bng, const float* __restrict__ bnb,
                 const float* __restrict__ w1, const float* __restrict__ b1,
                 const float* __restrict__ w2, const float* __restrict__ b2,
                 const float* __restrict__ fg, const float* __restrict__ fb)
{
    __shared__ char smem_raw[12416];
    int bx = blockIdx.x;

    // P0: segmented GEMM relay -> qtr | ktrr | vtrr (84 units: 12 o-blk x 7 n)
    if (bx < 84) {
        int ox = bx % 12, ny = bx / 12;
        int o0g = ox * 64;
        int seg = o0g >> 8;
        const float* W = (seg == 0) ? rwq : (seg == 1 ? rwk : rwv);
        const float* bias = (seg == 0) ? rbq : (seg == 1 ? rbk : rbv);
        float* Y = (seg == 0) ? qtrb : (seg == 1 ? ktrr : vtrr);
        dev_gemm_nc<0>(smem_raw, W, bias, relay, Y, nullptr, 256, CD,
                       o0g & 255, ny * 32);
    }
    grid_bar(256);

    // P1: attn_tru (200 units)
    if (bx < NTOK)
        dev_attn_tru(smem_raw, qtrb, ktrvtrb, ktrr, vtrr, relay, zb, bx);
    grid_bar(512);

    // P2: BN z -> rett (no leaky)
    dev_bn_nc(smem_raw, zb, bng, bnb, rettb, 0, 1e-5f, bx);
    grid_bar(768);

    // P3: FFN w1 (O=1024, relu): 112 units (16 o-blk x 7 n)
    if (bx < 112) {
        int ox = bx % 16, ny = bx / 16;
        dev_gemm_nc<1>(smem_raw, w1, b1, rettb, htrb, nullptr, DFFD, CD,
                       ox * 64, ny * 32);
    }
    grid_bar(1024);

    // P4: FFN w2 (O=256, +res): 28 units (4 o-blk x 7 n)
    if (bx < 28) {
        int ox = bx % 4, ny = bx / 4;
        dev_gemm_nc<2>(smem_raw, w2, b2, htrb, otrb, rettb, 256, DFFD,
                       ox * 64, ny * 32);
    }
    grid_bar(1280);

    // P5: BN otr -> relay (leaky)
    dev_bn_nc(smem_raw, otrb, fg, fb, relay, 1, 1e-5f, bx);

    // end handshake + reset for next launch
    __syncthreads();
    __threadfence();
    if (threadIdx.x == 0) {
        int d = atomicAdd(&g_done, 1);
        if (d == 255) {
            atomicExch(&g_bar, 0);
            atomicExch(&g_done, 0);
        }
    }
}

// ---------------------------------------------------------------------------
// tju attention. qkv: [n][768][T]; keve: [n][512][T]. grid NTOK*NHH, block 128.
// ---------------------------------------------------------------------------
__global__ void attn_tju(const float* __restrict__ qkv, const float* __restrict__ keve,
                         const float* __restrict__ kr, const float* __restrict__ vr,
                         const float* __restrict__ xln, float* __restrict__ sout)
{
    int nh = blockIdx.x;
    int n = nh >> 3, h = nh & 7;
    int t = threadIdx.x;
    int rbase = n * CD + h * DKK;
    size_t base = (size_t)rbase * TD;
    size_t bq = ((size_t)n * 768 + h * DKK) * TD;
    size_t bke = ((size_t)n * 512 + h * DKK) * TD;
    const size_t KOFF = (size_t)256 * TD, VOFF = (size_t)512 * TD;

    float l0 = 0.f, l1 = 0.f, l2 = 0.f, l3 = 0.f, l4 = 0.f;
#pragma unroll 8
    for (int d = 0; d < DKK; d++) {
        size_t oq = bq + (size_t)d * TD + t;
        float qd = qkv[oq];
        float kc = qkv[oq + KOFF];
        float km = (t > 0) ? qkv[oq + KOFF - 1] : 0.f;
        float kp = (t < TD - 1) ? qkv[oq + KOFF + 1] : 0.f;
        l0 += qd * km;
        l1 += qd * kc;
        l2 += qd * kp;
        l3 += qd * keve[bke + (size_t)d * TD + t];
        l4 += qd * kr[rbase + d];
    }
    const float sc = 0.17677669529663687f;
    l0 *= sc; l1 *= sc; l2 *= sc; l3 *= sc; l4 *= sc;
    float m = fmaxf(fmaxf(fmaxf(l0, l1), fmaxf(l2, l3)), l4);
    float e0 = expf(l0 - m), e1 = expf(l1 - m), e2 = expf(l2 - m);
    float e3 = expf(l3 - m), e4 = expf(l4 - m);
    float rs = 1.f / (e0 + e1 + e2 + e3 + e4);
    float a0 = e0 * rs, a1 = e1 * rs, a2 = e2 * rs, a3 = e3 * rs, a4 = e4 * rs;

#pragma unroll 8
    for (int d = 0; d < DKK; d++) {
        size_t oq = bq + (size_t)d * TD + t;
        float vc = qkv[oq + VOFF];
        float vm = (t > 0) ? qkv[oq + VOFF - 1] : 0.f;
        float vp = (t < TD - 1) ? qkv[oq + VOFF + 1] : 0.f;
        float att = a0 * vm + a1 * vc + a2 * vp
                  + a3 * keve[bke + KOFF + (size_t)d * TD + t] + a4 * vr[rbase + d];
        sout[base + (size_t)d * TD + t] = xln[base + (size_t)d * TD + t] + att;
    }
}

// ---------------------------------------------------------------------------
// FUSED BatchNorm (stats + affine) over (n,t) per channel. grid 256.
// ---------------------------------------------------------------------------
__global__ void bn_fused_nct(const float* __restrict__ X, const float* __restrict__ g,
                             const float* __restrict__ b, float* __restrict__ Y,
                             uint32_t* __restrict__ Yt, int leaky, float eps)
{
    int c = blockIdx.x, tid = threadIdx.x;
    float s1 = 0.f, s2 = 0.f;
    for (int i = tid; i < NTOK * TD; i += 256) {
        int n = i >> 7, t = i & 127;
        float x = X[((size_t)n * CD + c) * TD + t];
        s1 += x;
        s2 += x * x;
    }
    __shared__ double d1[256], d2[256];
    d1[tid] = s1; d2[tid] = s2;
    __syncthreads();
    for (int s = 128; s > 0; s >>= 1) {
        if (tid < s) { d1[tid] += d1[tid + s]; d2[tid] += d2[tid + s]; }
        __syncthreads();
    }
    __shared__ float smean, sinv;
    if (tid == 0) {
        double mm = d1[0] / (NTOK * TD);
        double var = d2[0] / (NTOK * TD) - mm * mm;
        smean = (float)mm;
        sinv = rsqrtf((float)var + eps);
    }
    __syncthreads();
    float mean = smean, inv = sinv, gg = g[c], bb = b[c];

    for (int i = tid * 4; i < NTOK * TD; i += 1024) {
        int n = i >> 7, t = i & 127;
        size_t off = ((size_t)n * CD + c) * TD + t;
        float4 x4 = *(const float4*)(X + off);
        float v0 = (x4.x - mean) * inv * gg + bb;
        float v1 = (x4.y - mean) * inv * gg + bb;
        float v2 = (x4.z - mean) * inv * gg + bb;
        float v3 = (x4.w - mean) * inv * gg + bb;
        if (leaky) {
            if (v0 < 0.f) v0 *= 0.01f;
            if (v1 < 0.f) v1 *= 0.01f;
            if (v2 < 0.f) v2 *= 0.01f;
            if (v3 < 0.f) v3 *= 0.01f;
        }
        *(float4*)(Y + off) = make_float4(v0, v1, v2, v3);
        if (Yt) {
            uint4 u;
            u.x = f2tf32(v0); u.y = f2tf32(v1);
            u.z = f2tf32(v2); u.w = f2tf32(v3);
            *(uint4*)(Yt + off) = u;
        }
    }
}

// ---------------------------------------------------------------------------
extern "C" void kernel_launch(void* const* d_in, const int* in_sizes, int n_in,
                              void* d_out, int out_size)
{
    (void)in_sizes; (void)n_in; (void)out_size;
    const float* data    = (const float*)d_in[0];
    const float* ln_g    = (const float*)d_in[1];
    const float* ln_b    = (const float*)d_in[2];
    const float* tj_wq   = (const float*)d_in[3];
    const float* tj_bq   = (const float*)d_in[4];
    const float* tj_wk   = (const float*)d_in[5];
    const float* tj_bk   = (const float*)d_in[6];
    const float* tj_wv   = (const float*)d_in[7];
    const float* tj_bv   = (const float*)d_in[8];
    const float* tj_bng  = (const float*)d_in[9];
    const float* tj_bnb  = (const float*)d_in[10];
    const float* tj_w1   = (const float*)d_in[11];
    const float* tj_b1   = (const float*)d_in[12];
    const float* tj_w2   = (const float*)d_in[13];
    const float* tj_b2   = (const float*)d_in[14];
    const float* tj_fg   = (const float*)d_in[15];
    const float* tj_fb   = (const float*)d_in[16];
    const float* tr_wq   = (const float*)d_in[17];
    const float* tr_bq   = (const float*)d_in[18];
    const float* tr_wk   = (const float*)d_in[19];
    const float* tr_bk   = (const float*)d_in[20];
    const float* tr_wv   = (const float*)d_in[21];
    const float* tr_bv   = (const float*)d_in[22];
    const float* tr_bng  = (const float*)d_in[23];
    const float* tr_bnb  = (const float*)d_in[24];
    const float* tr_w1   = (const float*)d_in[25];
    const float* tr_b1   = (const float*)d_in[26];
    const float* tr_w2   = (const float*)d_in[27];
    const float* tr_b2   = (const float*)d_in[28];
    const float* tr_fg   = (const float*)d_in[29];
    const float* tr_fb   = (const float*)d_in[30];

    float* buf = nullptr;
    cudaGetSymbolAddress((void**)&buf, g_buf);

    float* embs   = buf + OFF_EMBS;
    float* nodes  = buf + OFF_NODES;
    float* xln    = buf + OFF_XLN;
    float* qkvb   = buf + OFF_QKV;
    float* sb     = buf + OFF_S;
    float* retb   = buf + OFF_RET;
    float* ob     = buf + OFF_O;
    float* ktrvtrb = buf + OFF_KTRVTR;
    uint32_t* hb  = (uint32_t*)(buf + OFF_H);
    float* keveb  = buf + OFF_KEVE;
    float* relay  = buf + OFF_RELAY;
    float* krb    = buf + OFF_KR;
    float* vrb    = buf + OFF_VR;
    float* qtrb   = buf + OFF_QTR;
    float* ktrr   = buf + OFF_KTRR;
    float* vtrr   = buf + OFF_VTRR;
    float* zb     = buf + OFF_Z;
    float* rettb  = buf + OFF_RETT;
    float* otrb   = buf + OFF_OTR;
    float* htrb   = buf + OFF_HTR;

    uint32_t* qkvw  = (uint32_t*)(buf + OFF_QKVW);
    uint32_t* rwkvw = (uint32_t*)(buf + OFF_RWKVW);
    uint32_t* w1_t  = (uint32_t*)(buf + OFF_W1T);
    uint32_t* w2_t  = (uint32_t*)(buf + OFF_W2T);
    uint32_t* xln_t   = (uint32_t*)(buf + OFF_XLN_T);
    uint32_t* embs_t  = (uint32_t*)(buf + OFF_EMBS_T);
    uint32_t* ret_t   = (uint32_t*)(buf + OFF_RET_T);
    uint32_t* nodes_t = (uint32_t*)(buf + OFF_NODES_T);

    cudaFuncSetAttribute(gemm_pre<0,3>, cudaFuncAttributeMaxDynamicSharedMemorySize, GEMM_SMEM);
    cudaFuncSetAttribute(gemm_pre<0,2>, cudaFuncAttributeMaxDynamicSharedMemorySize, GEMM_SMEM);
    cudaFuncSetAttribute(gemm_pre<1,1>, cudaFuncAttributeMaxDynamicSharedMemorySize, GEMM_SMEM);
    cudaFuncSetAttribute(gemm_pre<2,1>, cudaFuncAttributeMaxDynamicSharedMemorySize, GEMM_SMEM);

    // weight conversion into combined fragment-major layouts
    conv_w_frag<<<dim3(CD * CD / 256, ITER), 256>>>(tj_wq, qkvw, CD, CD, LQKV, 0);
    conv_w_frag<<<dim3(CD * CD / 256, ITER), 256>>>(tj_wk, qkvw, CD, CD, LQKV, 2 * SEGQ);
    conv_w_frag<<<dim3(CD * CD / 256, ITER), 256>>>(tj_wv, qkvw, CD, CD, LQKV, 4 * SEGQ);
    conv_w_frag<<<dim3(CD * CD / 256, ITER), 256>>>(tr_wk, rwkvw, CD, CD, LRKV, 0);
    conv_w_frag<<<dim3(CD * CD / 256, ITER), 256>>>(tr_wv, rwkvw, CD, CD, LRKV, 2 * SEGQ);
    conv_w_frag<<<dim3(DFFD * CD / 256, ITER), 256>>>(tj_w1, w1_t, DFFD, CD, LW1, 0);
    conv_w_frag<<<dim3(DFFD * CD / 256, ITER), 256>>>(tj_w2, w2_t, CD, DFFD, LW2, 0);

    prep_kernel<<<dim3(NTOK, 32), dim3(32, 8)>>>(data, embs, embs_t, relay);

    // all 4 layers' ke/ve from embs (layer-batched)
    gemm_pre<0,2><<<dim3(4, NTOK, ITER), 256, GEMM_SMEM>>>(
        qkvw + 2 * SEGQ, tj_bk, tj_bv, nullptr, embs_t, keveb, nullptr,
        512, CD, (size_t)LQKV, (size_t)NTOK * 512 * TD);

    for (int i = 0; i < ITER; i++) {
        const float* nodes_in = (i == 0) ? embs : nodes;
        ln_kernel<<<dim3(NTOK, 4), dim3(32, 8)>>>(nodes_in, ln_g + i * CD, ln_b + i * CD,
                                                  xln, xln_t);

        // fused QKV (O=768)
        gemm_pre<0,3><<<dim3(6, NTOK, 1), 256, GEMM_SMEM>>>(
            qkvw + (size_t)i * LQKV, tj_bq + i * CD, tj_bk + i * CD, tj_bv + i * CD,
            xln_t, qkvb, nullptr, 768, CD, 0, 0);
        // kr + vr in one segmented launch
        gemm_nc_seg<<<dim3(8, 7), 256>>>(
            tj_wk + (size_t)i * CD * CD, tj_wv + (size_t)i * CD * CD,
            tj_bk + i * CD, tj_bv + i * CD,
            relay, krb, vrb, CD);

        attn_tju<<<NTOK * NHH, 128>>>(qkvb, keveb + (size_t)i * NTOK * 512 * TD,
                                      krb, vrb, xln, sb);

        bn_fused_nct<<<256, 256>>>(sb, tj_bng + i * CD, tj_bnb + i * CD,
                                   retb, ret_t, 0, 1e-5f);

        gemm_pre<1,1><<<dim3(8, NTOK, 1), 256, GEMM_SMEM>>>(
            w1_t + (size_t)i * LW1, tj_b1 + i * DFFD, nullptr, nullptr,
            ret_t, (void*)hb, nullptr, DFFD, CD, 0, 0);
        gemm_pre<2,1><<<dim3(2, NTOK, 1), 256, GEMM_SMEM>>>(
            w2_t + (size_t)i * LW2, tj_b2 + i * CD, nullptr, nullptr,
            hb, ob, retb, CD, DFFD, 0, 0);

        float* nodes_out = (i == ITER - 1) ? (float*)d_out : nodes;
        uint32_t* nodes_out_t = (i == ITER - 1) ? nullptr : nodes_t;
        bn_fused_nct<<<256, 256>>>(ob, tj_fg + i * CD, tj_fb + i * CD,
                                   nodes_out, nodes_out_t, 1, 1e-5f);

        if (i < ITER - 1) {
            // big GEMM: ktr/vtr from nodes (O=512)
            gemm_pre<0,2><<<dim3(4, NTOK, 1), 256, GEMM_SMEM>>>(
                rwkvw + (size_t)i * LRKV, tr_bk + i * CD, tr_bv + i * CD, nullptr,
                nodes_t, ktrvtrb, nullptr, 512, CD, 0, 0);

            // fused relay chain (seg-GEMM + attn_tru + BN + FFN + BN)
            relay_chain<<<256, 256>>>(
                tr_wq + (size_t)i * CD * CD, tr_wk + (size_t)i * CD * CD,
                tr_wv + (size_t)i * CD * CD,
                tr_bq + i * CD, tr_bk + i * CD, tr_bv + i * CD,
                relay, qtrb, ktrr, vtrr, ktrvtrb,
                zb, rettb, htrb, otrb,
                tr_bng + i * CD, tr_bnb + i * CD,
                tr_w1 + (size_t)i * DFFD * CD, tr_b1 + i * DFFD,
                tr_w2 + (size_t)i * CD * DFFD, tr_b2 + i * CD,
                tr_fg + i * CD, tr_fb + i * CD);
        }
    }
}